// round 1
// baseline (speedup 1.0000x reference)
#include <cuda_runtime.h>

#define BB 8
#define CC 256
#define NN 4096
#define DD 32
#define MQKV 320
#define EPSV 1e-5f

// ---------------- scratch (device globals; no allocations allowed) ----------
__device__ float g_WeffT[CC * MQKV];              // [c][o]  (transposed folded weights)
__device__ float g_Beff[MQKV];                    // folded bias
__device__ float g_QKV[(size_t)BB * MQKV * NN];   // [b][o][n]  o: 0-31 Q, 32-63 K, 64-319 V
__device__ float g_E[(size_t)BB * NN * NN];       // [b][i][j]  energy / attention (in-place)

// ---------------- 1) fold BN into conv ----------------
__global__ void fold_kernel(
    const float* __restrict__ wq, const float* __restrict__ bq,
    const float* __restrict__ gq, const float* __restrict__ betaq,
    const float* __restrict__ mq, const float* __restrict__ vq,
    const float* __restrict__ wk, const float* __restrict__ bk,
    const float* __restrict__ gk, const float* __restrict__ betak,
    const float* __restrict__ mk, const float* __restrict__ vk,
    const float* __restrict__ wv, const float* __restrict__ bv,
    const float* __restrict__ gv, const float* __restrict__ betav,
    const float* __restrict__ mv, const float* __restrict__ vv)
{
    int o = blockIdx.x;      // 0..319
    int c = threadIdx.x;     // 0..255
    const float *w, *bb, *g, *beta, *mean, *var;
    int oo;
    if (o < 32)      { w = wq; bb = bq; g = gq; beta = betaq; mean = mq; var = vq; oo = o; }
    else if (o < 64) { w = wk; bb = bk; g = gk; beta = betak; mean = mk; var = vk; oo = o - 32; }
    else             { w = wv; bb = bv; g = gv; beta = betav; mean = mv; var = vv; oo = o - 64; }

    float scale = g[oo] * rsqrtf(var[oo] + EPSV);
    g_WeffT[c * MQKV + o] = w[oo * CC + c] * scale;
    if (c == 0)
        g_Beff[o] = (bb[oo] - mean[oo]) * scale + beta[oo];
}

// ---------------- 2) fused QKV conv:  QKV[b][o][n] = relu(Weff[o][:]·x[b][:][n] + Beff[o]) ----
// grid (NN/64, MQKV/64=5, BB), block 256
__global__ void qkv_kernel(const float* __restrict__ x)
{
    const int n0 = blockIdx.x * 64;
    const int o0 = blockIdx.y * 64;
    const int b  = blockIdx.z;

    __shared__ float As[32][64];   // [k][o]
    __shared__ float Bs[32][64];   // [k][n]

    const int tid = threadIdx.x;
    const int mo = (tid >> 4) * 4;   // o within tile
    const int nn = (tid & 15) * 4;   // n within tile

    float acc[4][4] = {};
    const float* xb = x + (size_t)b * CC * NN;

    for (int k0 = 0; k0 < CC; k0 += 32) {
        #pragma unroll
        for (int l = 0; l < 8; l++) {
            int idx = tid + l * 256;
            int oo = idx & 63, kk = idx >> 6;
            As[kk][oo] = g_WeffT[(size_t)(k0 + kk) * MQKV + o0 + oo];
        }
        #pragma unroll
        for (int l = 0; l < 8; l++) {
            int idx = tid + l * 256;
            int nn2 = idx & 63, kk = idx >> 6;
            Bs[kk][nn2] = xb[(size_t)(k0 + kk) * NN + n0 + nn2];
        }
        __syncthreads();
        #pragma unroll
        for (int kk = 0; kk < 32; kk++) {
            float4 av = *(const float4*)&As[kk][mo];
            float4 bv = *(const float4*)&Bs[kk][nn];
            acc[0][0] += av.x * bv.x; acc[0][1] += av.x * bv.y; acc[0][2] += av.x * bv.z; acc[0][3] += av.x * bv.w;
            acc[1][0] += av.y * bv.x; acc[1][1] += av.y * bv.y; acc[1][2] += av.y * bv.z; acc[1][3] += av.y * bv.w;
            acc[2][0] += av.z * bv.x; acc[2][1] += av.z * bv.y; acc[2][2] += av.z * bv.z; acc[2][3] += av.z * bv.w;
            acc[3][0] += av.w * bv.x; acc[3][1] += av.w * bv.y; acc[3][2] += av.w * bv.z; acc[3][3] += av.w * bv.w;
        }
        __syncthreads();
    }

    #pragma unroll
    for (int a = 0; a < 4; a++) {
        int o = o0 + mo + a;
        float bias = g_Beff[o];
        float4 r;
        r.x = fmaxf(acc[a][0] + bias, 0.f);
        r.y = fmaxf(acc[a][1] + bias, 0.f);
        r.z = fmaxf(acc[a][2] + bias, 0.f);
        r.w = fmaxf(acc[a][3] + bias, 0.f);
        *(float4*)&g_QKV[((size_t)b * MQKV + o) * NN + n0 + nn] = r;
    }
}

// ---------------- 3) energy GEMM:  E[b][i][j] = sum_d Q[d][i] * K[d][j] ----
// grid (NN/64 (j), NN/64 (i), BB), block 256
__global__ void qk_kernel()
{
    const int j0 = blockIdx.x * 64;
    const int i0 = blockIdx.y * 64;
    const int b  = blockIdx.z;

    __shared__ float Qs[32][64];   // [d][i]
    __shared__ float Ks[32][64];   // [d][j]

    const int tid = threadIdx.x;
    const int il = (tid >> 4) * 4;
    const int jl = (tid & 15) * 4;

    const float* qb = g_QKV + (size_t)b * MQKV * NN;          // rows 0..31
    const float* kb = qb + (size_t)32 * NN;                   // rows 32..63

    #pragma unroll
    for (int l = 0; l < 8; l++) {
        int idx = tid + l * 256;
        int ii = idx & 63, kk = idx >> 6;
        Qs[kk][ii] = qb[(size_t)kk * NN + i0 + ii];
        Ks[kk][ii] = kb[(size_t)kk * NN + j0 + ii];
    }
    __syncthreads();

    float acc[4][4] = {};
    #pragma unroll
    for (int kk = 0; kk < 32; kk++) {
        float4 qv = *(const float4*)&Qs[kk][il];
        float4 kv = *(const float4*)&Ks[kk][jl];
        acc[0][0] += qv.x * kv.x; acc[0][1] += qv.x * kv.y; acc[0][2] += qv.x * kv.z; acc[0][3] += qv.x * kv.w;
        acc[1][0] += qv.y * kv.x; acc[1][1] += qv.y * kv.y; acc[1][2] += qv.y * kv.z; acc[1][3] += qv.y * kv.w;
        acc[2][0] += qv.z * kv.x; acc[2][1] += qv.z * kv.y; acc[2][2] += qv.z * kv.z; acc[2][3] += qv.z * kv.w;
        acc[3][0] += qv.w * kv.x; acc[3][1] += qv.w * kv.y; acc[3][2] += qv.w * kv.z; acc[3][3] += qv.w * kv.w;
    }

    float* eb = g_E + (size_t)b * NN * NN;
    #pragma unroll
    for (int a = 0; a < 4; a++) {
        float4 r;
        r.x = acc[a][0]; r.y = acc[a][1]; r.z = acc[a][2]; r.w = acc[a][3];
        *(float4*)&eb[(size_t)(i0 + il + a) * NN + j0 + jl] = r;
    }
}

// ---------------- 4) row softmax over j (in place), row kept in registers ----
// grid BB*NN blocks, block 256 (16 floats per thread)
__global__ void softmax_kernel()
{
    const size_t row = blockIdx.x;
    float4* e4 = (float4*)(g_E + row * NN);
    const int tid = threadIdx.x;

    float4 r[4];
    #pragma unroll
    for (int l = 0; l < 4; l++) r[l] = e4[tid + l * 256];

    float m = -3.4e38f;
    #pragma unroll
    for (int l = 0; l < 4; l++) {
        m = fmaxf(m, fmaxf(fmaxf(r[l].x, r[l].y), fmaxf(r[l].z, r[l].w)));
    }
    #pragma unroll
    for (int off = 16; off > 0; off >>= 1)
        m = fmaxf(m, __shfl_xor_sync(0xffffffffu, m, off));

    __shared__ float redm[8];
    __shared__ float reds[8];
    const int wid = tid >> 5, lane = tid & 31;
    if (lane == 0) redm[wid] = m;
    __syncthreads();
    float bm = redm[0];
    #pragma unroll
    for (int w = 1; w < 8; w++) bm = fmaxf(bm, redm[w]);

    float s = 0.f;
    #pragma unroll
    for (int l = 0; l < 4; l++) {
        r[l].x = __expf(r[l].x - bm); s += r[l].x;
        r[l].y = __expf(r[l].y - bm); s += r[l].y;
        r[l].z = __expf(r[l].z - bm); s += r[l].z;
        r[l].w = __expf(r[l].w - bm); s += r[l].w;
    }
    #pragma unroll
    for (int off = 16; off > 0; off >>= 1)
        s += __shfl_xor_sync(0xffffffffu, s, off);
    if (lane == 0) reds[wid] = s;
    __syncthreads();
    float tot = 0.f;
    #pragma unroll
    for (int w = 0; w < 8; w++) tot += reds[w];
    float inv = 1.0f / tot;

    #pragma unroll
    for (int l = 0; l < 4; l++) {
        r[l].x *= inv; r[l].y *= inv; r[l].z *= inv; r[l].w *= inv;
        e4[tid + l * 256] = r[l];
    }
}

// ---------------- 5) PV GEMM + residual epilogue ----
// out[b][c][i] = gamma * sum_j V[b][c][j] * A[b][i][j] + x[b][c][i]
// grid (NN/64 (i), CC/128 (c), BB), block 256
__global__ void pv_kernel(const float* __restrict__ x,
                          const float* __restrict__ gamma,
                          float* __restrict__ out)
{
    const int i0 = blockIdx.x * 64;
    const int c0 = blockIdx.y * 128;
    const int b  = blockIdx.z;

    __shared__ float Vs[128][36];  // [c][j] (pitch 36 keeps float4 alignment, no conflicts)
    __shared__ float As[64][36];   // [i][j]

    const int tid = threadIdx.x;
    const int cl = (tid >> 4) * 8;   // 16 groups of 8 c's
    const int il = (tid & 15) * 4;   // 16 groups of 4 i's

    const float* vb = g_QKV + ((size_t)b * MQKV + 64) * NN;   // V rows
    const float* eb = g_E + (size_t)b * NN * NN;

    float acc[8][4] = {};

    for (int j0 = 0; j0 < NN; j0 += 32) {
        #pragma unroll
        for (int l = 0; l < 16; l++) {
            int idx = tid + l * 256;
            int jj = idx & 31, ccr = idx >> 5;
            Vs[ccr][jj] = vb[(size_t)(c0 + ccr) * NN + j0 + jj];
        }
        #pragma unroll
        for (int l = 0; l < 8; l++) {
            int idx = tid + l * 256;
            int jj = idx & 31, ii = idx >> 5;
            As[ii][jj] = eb[(size_t)(i0 + ii) * NN + j0 + jj];
        }
        __syncthreads();

        #pragma unroll
        for (int q = 0; q < 8; q++) {
            float4 aa[4];
            #pragma unroll
            for (int t = 0; t < 4; t++) aa[t] = *(const float4*)&As[il + t][q * 4];
            #pragma unroll
            for (int a = 0; a < 8; a++) {
                float4 vv4 = *(const float4*)&Vs[cl + a][q * 4];
                #pragma unroll
                for (int t = 0; t < 4; t++) {
                    acc[a][t] += vv4.x * aa[t].x + vv4.y * aa[t].y
                               + vv4.z * aa[t].z + vv4.w * aa[t].w;
                }
            }
        }
        __syncthreads();
    }

    const float g = gamma[0];
    #pragma unroll
    for (int a = 0; a < 8; a++) {
        int c = c0 + cl + a;
        size_t base = ((size_t)b * CC + c) * NN + i0 + il;
        float4 xv = *(const float4*)&x[base];
        float4 r;
        r.x = g * acc[a][0] + xv.x;
        r.y = g * acc[a][1] + xv.y;
        r.z = g * acc[a][2] + xv.z;
        r.w = g * acc[a][3] + xv.w;
        *(float4*)&out[base] = r;
    }
}

// ---------------- launch ----------------
extern "C" void kernel_launch(void* const* d_in, const int* in_sizes, int n_in,
                              void* d_out, int out_size)
{
    const float* x     = (const float*)d_in[0];
    const float* wq    = (const float*)d_in[1];
    const float* bq    = (const float*)d_in[2];
    const float* gq    = (const float*)d_in[3];
    const float* betaq = (const float*)d_in[4];
    const float* mq    = (const float*)d_in[5];
    const float* vq    = (const float*)d_in[6];
    const float* wk    = (const float*)d_in[7];
    const float* bk    = (const float*)d_in[8];
    const float* gk    = (const float*)d_in[9];
    const float* betak = (const float*)d_in[10];
    const float* mk    = (const float*)d_in[11];
    const float* vk    = (const float*)d_in[12];
    const float* wv    = (const float*)d_in[13];
    const float* bv    = (const float*)d_in[14];
    const float* gv    = (const float*)d_in[15];
    const float* betav = (const float*)d_in[16];
    const float* mv    = (const float*)d_in[17];
    const float* vv    = (const float*)d_in[18];
    const float* gamma = (const float*)d_in[19];
    float* out = (float*)d_out;

    fold_kernel<<<MQKV, CC>>>(wq, bq, gq, betaq, mq, vq,
                              wk, bk, gk, betak, mk, vk,
                              wv, bv, gv, betav, mv, vv);

    qkv_kernel<<<dim3(NN / 64, MQKV / 64, BB), 256>>>(x);

    qk_kernel<<<dim3(NN / 64, NN / 64, BB), 256>>>();

    softmax_kernel<<<BB * NN, 256>>>();

    pv_kernel<<<dim3(NN / 64, CC / 128, BB), 256>>>(x, gamma, out);
}

// round 2
// speedup vs baseline: 1.0023x; 1.0023x over previous
#include <cuda_runtime.h>

#define BB 8
#define CC 256
#define NN 4096
#define DD 32
#define MQKV 320
#define EPSV 1e-5f

// ---------------- scratch (device globals; no allocations allowed) ----------
__device__ float g_WeffT[CC * MQKV];              // [c][o]  (transposed folded weights)
__device__ float g_Beff[MQKV];                    // folded bias
__device__ float g_QKV[(size_t)BB * MQKV * NN];   // [b][o][n]  o: 0-31 Q, 32-63 K, 64-319 V
__device__ float g_E[(size_t)BB * NN * NN];       // [b][i][j]  energy / attention (in-place)

// ---------------- 1) fold BN into conv ----------------
__global__ void fold_kernel(
    const float* __restrict__ wq, const float* __restrict__ bq,
    const float* __restrict__ gq, const float* __restrict__ betaq,
    const float* __restrict__ mq, const float* __restrict__ vq,
    const float* __restrict__ wk, const float* __restrict__ bk,
    const float* __restrict__ gk, const float* __restrict__ betak,
    const float* __restrict__ mk, const float* __restrict__ vk,
    const float* __restrict__ wv, const float* __restrict__ bv,
    const float* __restrict__ gv, const float* __restrict__ betav,
    const float* __restrict__ mv, const float* __restrict__ vv)
{
    int o = blockIdx.x;      // 0..319
    int c = threadIdx.x;     // 0..255
    const float *w, *bb, *g, *beta, *mean, *var;
    int oo;
    if (o < 32)      { w = wq; bb = bq; g = gq; beta = betaq; mean = mq; var = vq; oo = o; }
    else if (o < 64) { w = wk; bb = bk; g = gk; beta = betak; mean = mk; var = vk; oo = o - 32; }
    else             { w = wv; bb = bv; g = gv; beta = betav; mean = mv; var = vv; oo = o - 64; }

    float scale = g[oo] * rsqrtf(var[oo] + EPSV);
    g_WeffT[c * MQKV + o] = w[oo * CC + c] * scale;
    if (c == 0)
        g_Beff[o] = (bb[oo] - mean[oo]) * scale + beta[oo];
}

// ---------------- 2) fused QKV conv:  QKV[b][o][n] = relu(Weff[o][:]·x[b][:][n] + Beff[o]) ----
// grid (NN/64, MQKV/64=5, BB), block 256
__global__ void qkv_kernel(const float* __restrict__ x)
{
    const int n0 = blockIdx.x * 64;
    const int o0 = blockIdx.y * 64;
    const int b  = blockIdx.z;

    __shared__ float As[32][64];   // [k][o]
    __shared__ float Bs[32][64];   // [k][n]

    const int tid = threadIdx.x;
    const int mo = (tid >> 4) * 4;   // o within tile
    const int nn = (tid & 15) * 4;   // n within tile

    float acc[4][4] = {};
    const float* xb = x + (size_t)b * CC * NN;

    for (int k0 = 0; k0 < CC; k0 += 32) {
        #pragma unroll
        for (int l = 0; l < 8; l++) {
            int idx = tid + l * 256;
            int oo = idx & 63, kk = idx >> 6;
            As[kk][oo] = g_WeffT[(size_t)(k0 + kk) * MQKV + o0 + oo];
        }
        #pragma unroll
        for (int l = 0; l < 8; l++) {
            int idx = tid + l * 256;
            int nn2 = idx & 63, kk = idx >> 6;
            Bs[kk][nn2] = xb[(size_t)(k0 + kk) * NN + n0 + nn2];
        }
        __syncthreads();
        #pragma unroll
        for (int kk = 0; kk < 32; kk++) {
            float4 av = *(const float4*)&As[kk][mo];
            float4 bv = *(const float4*)&Bs[kk][nn];
            acc[0][0] += av.x * bv.x; acc[0][1] += av.x * bv.y; acc[0][2] += av.x * bv.z; acc[0][3] += av.x * bv.w;
            acc[1][0] += av.y * bv.x; acc[1][1] += av.y * bv.y; acc[1][2] += av.y * bv.z; acc[1][3] += av.y * bv.w;
            acc[2][0] += av.z * bv.x; acc[2][1] += av.z * bv.y; acc[2][2] += av.z * bv.z; acc[2][3] += av.z * bv.w;
            acc[3][0] += av.w * bv.x; acc[3][1] += av.w * bv.y; acc[3][2] += av.w * bv.z; acc[3][3] += av.w * bv.w;
        }
        __syncthreads();
    }

    #pragma unroll
    for (int a = 0; a < 4; a++) {
        int o = o0 + mo + a;
        float bias = g_Beff[o];
        float4 r;
        r.x = fmaxf(acc[a][0] + bias, 0.f);
        r.y = fmaxf(acc[a][1] + bias, 0.f);
        r.z = fmaxf(acc[a][2] + bias, 0.f);
        r.w = fmaxf(acc[a][3] + bias, 0.f);
        *(float4*)&g_QKV[((size_t)b * MQKV + o) * NN + n0 + nn] = r;
    }
}

// ---------------- 3) energy GEMM:  E[b][i][j] = sum_d Q[d][i] * K[d][j] ----
// grid (NN/64 (j), NN/64 (i), BB), block 256
__global__ void qk_kernel()
{
    const int j0 = blockIdx.x * 64;
    const int i0 = blockIdx.y * 64;
    const int b  = blockIdx.z;

    __shared__ float Qs[32][64];   // [d][i]
    __shared__ float Ks[32][64];   // [d][j]

    const int tid = threadIdx.x;
    const int il = (tid >> 4) * 4;
    const int jl = (tid & 15) * 4;

    const float* qb = g_QKV + (size_t)b * MQKV * NN;          // rows 0..31
    const float* kb = qb + (size_t)32 * NN;                   // rows 32..63

    #pragma unroll
    for (int l = 0; l < 8; l++) {
        int idx = tid + l * 256;
        int ii = idx & 63, kk = idx >> 6;
        Qs[kk][ii] = qb[(size_t)kk * NN + i0 + ii];
        Ks[kk][ii] = kb[(size_t)kk * NN + j0 + ii];
    }
    __syncthreads();

    float acc[4][4] = {};
    #pragma unroll
    for (int kk = 0; kk < 32; kk++) {
        float4 qv = *(const float4*)&Qs[kk][il];
        float4 kv = *(const float4*)&Ks[kk][jl];
        acc[0][0] += qv.x * kv.x; acc[0][1] += qv.x * kv.y; acc[0][2] += qv.x * kv.z; acc[0][3] += qv.x * kv.w;
        acc[1][0] += qv.y * kv.x; acc[1][1] += qv.y * kv.y; acc[1][2] += qv.y * kv.z; acc[1][3] += qv.y * kv.w;
        acc[2][0] += qv.z * kv.x; acc[2][1] += qv.z * kv.y; acc[2][2] += qv.z * kv.z; acc[2][3] += qv.z * kv.w;
        acc[3][0] += qv.w * kv.x; acc[3][1] += qv.w * kv.y; acc[3][2] += qv.w * kv.z; acc[3][3] += qv.w * kv.w;
    }

    float* eb = g_E + (size_t)b * NN * NN;
    #pragma unroll
    for (int a = 0; a < 4; a++) {
        float4 r;
        r.x = acc[a][0]; r.y = acc[a][1]; r.z = acc[a][2]; r.w = acc[a][3];
        *(float4*)&eb[(size_t)(i0 + il + a) * NN + j0 + jl] = r;
    }
}

// ---------------- 4) row softmax over j (in place), row kept in registers ----
// grid BB*NN blocks, block 256 (16 floats per thread)
__global__ void softmax_kernel()
{
    const size_t row = blockIdx.x;
    float4* e4 = (float4*)(g_E + row * NN);
    const int tid = threadIdx.x;

    float4 r[4];
    #pragma unroll
    for (int l = 0; l < 4; l++) r[l] = e4[tid + l * 256];

    float m = -3.4e38f;
    #pragma unroll
    for (int l = 0; l < 4; l++) {
        m = fmaxf(m, fmaxf(fmaxf(r[l].x, r[l].y), fmaxf(r[l].z, r[l].w)));
    }
    #pragma unroll
    for (int off = 16; off > 0; off >>= 1)
        m = fmaxf(m, __shfl_xor_sync(0xffffffffu, m, off));

    __shared__ float redm[8];
    __shared__ float reds[8];
    const int wid = tid >> 5, lane = tid & 31;
    if (lane == 0) redm[wid] = m;
    __syncthreads();
    float bm = redm[0];
    #pragma unroll
    for (int w = 1; w < 8; w++) bm = fmaxf(bm, redm[w]);

    float s = 0.f;
    #pragma unroll
    for (int l = 0; l < 4; l++) {
        r[l].x = __expf(r[l].x - bm); s += r[l].x;
        r[l].y = __expf(r[l].y - bm); s += r[l].y;
        r[l].z = __expf(r[l].z - bm); s += r[l].z;
        r[l].w = __expf(r[l].w - bm); s += r[l].w;
    }
    #pragma unroll
    for (int off = 16; off > 0; off >>= 1)
        s += __shfl_xor_sync(0xffffffffu, s, off);
    if (lane == 0) reds[wid] = s;
    __syncthreads();
    float tot = 0.f;
    #pragma unroll
    for (int w = 0; w < 8; w++) tot += reds[w];
    float inv = 1.0f / tot;

    #pragma unroll
    for (int l = 0; l < 4; l++) {
        r[l].x *= inv; r[l].y *= inv; r[l].z *= inv; r[l].w *= inv;
        e4[tid + l * 256] = r[l];
    }
}

// ---------------- 5) PV GEMM + residual epilogue ----
// out[b][c][i] = gamma * sum_j V[b][c][j] * A[b][i][j] + x[b][c][i]
// grid (NN/64 (i), CC/128 (c), BB), block 256
__global__ void pv_kernel(const float* __restrict__ x,
                          const float* __restrict__ gamma,
                          float* __restrict__ out)
{
    const int i0 = blockIdx.x * 64;
    const int c0 = blockIdx.y * 128;
    const int b  = blockIdx.z;

    __shared__ float Vs[128][36];  // [c][j] (pitch 36 keeps float4 alignment, no conflicts)
    __shared__ float As[64][36];   // [i][j]

    const int tid = threadIdx.x;
    const int cl = (tid >> 4) * 8;   // 16 groups of 8 c's
    const int il = (tid & 15) * 4;   // 16 groups of 4 i's

    const float* vb = g_QKV + ((size_t)b * MQKV + 64) * NN;   // V rows
    const float* eb = g_E + (size_t)b * NN * NN;

    float acc[8][4] = {};

    for (int j0 = 0; j0 < NN; j0 += 32) {
        #pragma unroll
        for (int l = 0; l < 16; l++) {
            int idx = tid + l * 256;
            int jj = idx & 31, ccr = idx >> 5;
            Vs[ccr][jj] = vb[(size_t)(c0 + ccr) * NN + j0 + jj];
        }
        #pragma unroll
        for (int l = 0; l < 8; l++) {
            int idx = tid + l * 256;
            int jj = idx & 31, ii = idx >> 5;
            As[ii][jj] = eb[(size_t)(i0 + ii) * NN + j0 + jj];
        }
        __syncthreads();

        #pragma unroll
        for (int q = 0; q < 8; q++) {
            float4 aa[4];
            #pragma unroll
            for (int t = 0; t < 4; t++) aa[t] = *(const float4*)&As[il + t][q * 4];
            #pragma unroll
            for (int a = 0; a < 8; a++) {
                float4 vv4 = *(const float4*)&Vs[cl + a][q * 4];
                #pragma unroll
                for (int t = 0; t < 4; t++) {
                    acc[a][t] += vv4.x * aa[t].x + vv4.y * aa[t].y
                               + vv4.z * aa[t].z + vv4.w * aa[t].w;
                }
            }
        }
        __syncthreads();
    }

    const float g = gamma[0];
    #pragma unroll
    for (int a = 0; a < 8; a++) {
        int c = c0 + cl + a;
        size_t base = ((size_t)b * CC + c) * NN + i0 + il;
        float4 xv = *(const float4*)&x[base];
        float4 r;
        r.x = g * acc[a][0] + xv.x;
        r.y = g * acc[a][1] + xv.y;
        r.z = g * acc[a][2] + xv.z;
        r.w = g * acc[a][3] + xv.w;
        *(float4*)&out[base] = r;
    }
}

// ---------------- launch ----------------
extern "C" void kernel_launch(void* const* d_in, const int* in_sizes, int n_in,
                              void* d_out, int out_size)
{
    const float* x     = (const float*)d_in[0];
    const float* wq    = (const float*)d_in[1];
    const float* bq    = (const float*)d_in[2];
    const float* gq    = (const float*)d_in[3];
    const float* betaq = (const float*)d_in[4];
    const float* mq    = (const float*)d_in[5];
    const float* vq    = (const float*)d_in[6];
    const float* wk    = (const float*)d_in[7];
    const float* bk    = (const float*)d_in[8];
    const float* gk    = (const float*)d_in[9];
    const float* betak = (const float*)d_in[10];
    const float* mk    = (const float*)d_in[11];
    const float* vk    = (const float*)d_in[12];
    const float* wv    = (const float*)d_in[13];
    const float* bv    = (const float*)d_in[14];
    const float* gv    = (const float*)d_in[15];
    const float* betav = (const float*)d_in[16];
    const float* mv    = (const float*)d_in[17];
    const float* vv    = (const float*)d_in[18];
    const float* gamma = (const float*)d_in[19];
    float* out = (float*)d_out;

    fold_kernel<<<MQKV, CC>>>(wq, bq, gq, betaq, mq, vq,
                              wk, bk, gk, betak, mk, vk,
                              wv, bv, gv, betav, mv, vv);

    qkv_kernel<<<dim3(NN / 64, MQKV / 64, BB), 256>>>(x);

    qk_kernel<<<dim3(NN / 64, NN / 64, BB), 256>>>();

    softmax_kernel<<<BB * NN, 256>>>();

    pv_kernel<<<dim3(NN / 64, CC / 128, BB), 256>>>(x, gamma, out);
}

// round 4
// speedup vs baseline: 7.5289x; 7.5116x over previous
#include <cuda_runtime.h>
#include <cuda_fp16.h>
#include <cstdint>

#define BB 8
#define CC 256
#define NN 4096
#define EPSV 1e-5f

// ---------------- device-global scratch ----------------
__device__ float  g_WqkT[CC * 64];                 // [c][o] fp32 (QK conv weights)
__device__ __half g_Wv[CC * CC];                   // [c_out][c_in] fp16
__device__ float  g_Beff[320];
__device__ __half g_xT[(size_t)BB * NN * CC];      // [b][n][c] fp16
__device__ __half g_Qt[(size_t)BB * NN * 64];      // [b][n][hi32|lo32]
__device__ __half g_Kt[(size_t)BB * NN * 64];
__device__ __half g_V [(size_t)BB * CC * NN];      // [b][c][n] fp16
__device__ float  g_E [(size_t)BB * NN * NN];      // energy fp32
__device__ __half g_A [(size_t)BB * NN * NN];      // attn fp16

// ---------------- helpers ----------------
__device__ __forceinline__ uint32_t sm_u32(const void* p) {
    uint32_t a;
    asm("{ .reg .u64 t; cvta.to.shared.u64 t, %1; cvt.u32.u64 %0, t; }" : "=r"(a) : "l"(p));
    return a;
}
__device__ __forceinline__ void mma16816(float* d, const uint32_t* a, const uint32_t* b) {
    asm volatile(
        "mma.sync.aligned.m16n8k16.row.col.f32.f16.f16.f32 "
        "{%0,%1,%2,%3}, {%4,%5,%6,%7}, {%8,%9}, {%0,%1,%2,%3};"
        : "+f"(d[0]), "+f"(d[1]), "+f"(d[2]), "+f"(d[3])
        : "r"(a[0]), "r"(a[1]), "r"(a[2]), "r"(a[3]), "r"(b[0]), "r"(b[1]));
}
__device__ __forceinline__ void ldsm_x4(uint32_t* r, uint32_t addr) {
    asm volatile("ldmatrix.sync.aligned.m8n8.x4.shared.b16 {%0,%1,%2,%3}, [%4];"
        : "=r"(r[0]), "=r"(r[1]), "=r"(r[2]), "=r"(r[3]) : "r"(addr));
}
__device__ __forceinline__ void ldsm_x2(uint32_t* r, uint32_t addr) {
    asm volatile("ldmatrix.sync.aligned.m8n8.x2.shared.b16 {%0,%1}, [%2];"
        : "=r"(r[0]), "=r"(r[1]) : "r"(addr));
}
// swizzled tile address: tile rows of 64 halves (128B = 8 chunks of 16B), chunk ^= row&7
__device__ __forceinline__ uint32_t tile_addr(uint32_t base, int row, int ch) {
    return base + row * 128 + (((ch) ^ (row & 7)) << 4);
}
__device__ __forceinline__ void cpasync16(uint32_t dst, const void* src) {
    asm volatile("cp.async.cg.shared.global [%0], [%1], 16;" :: "r"(dst), "l"(src) : "memory");
}

// ---------------- 1) fold BN into conv ----------------
__global__ void fold_kernel(
    const float* __restrict__ wq, const float* __restrict__ bq,
    const float* __restrict__ gq, const float* __restrict__ betaq,
    const float* __restrict__ mq, const float* __restrict__ vq,
    const float* __restrict__ wk, const float* __restrict__ bk,
    const float* __restrict__ gk, const float* __restrict__ betak,
    const float* __restrict__ mk, const float* __restrict__ vk,
    const float* __restrict__ wv, const float* __restrict__ bv,
    const float* __restrict__ gv, const float* __restrict__ betav,
    const float* __restrict__ mv, const float* __restrict__ vv)
{
    int o = blockIdx.x, c = threadIdx.x;
    const float *w, *bb, *g, *beta, *mean, *var;
    int oo;
    if (o < 32)      { w = wq; bb = bq; g = gq; beta = betaq; mean = mq; var = vq; oo = o; }
    else if (o < 64) { w = wk; bb = bk; g = gk; beta = betak; mean = mk; var = vk; oo = o - 32; }
    else             { w = wv; bb = bv; g = gv; beta = betav; mean = mv; var = vv; oo = o - 64; }
    float scale = g[oo] * rsqrtf(var[oo] + EPSV);
    float val = w[oo * CC + c] * scale;
    if (o < 64) g_WqkT[c * 64 + o] = val;
    else        g_Wv[(o - 64) * CC + c] = __float2half(val);
    if (c == 0) g_Beff[o] = (bb[oo] - mean[oo]) * scale + beta[oo];
}

// ---------------- 2) pack x -> x^T fp16  [b][n][c] ----------------
__global__ void packx_kernel(const float* __restrict__ x)
{
    __shared__ float s[64][65];
    const int n0 = blockIdx.x * 64, c0 = blockIdx.y * 64, b = blockIdx.z;
    const int tid = threadIdx.x;
    const float* xb = x + ((size_t)b * CC + c0) * NN + n0;
    #pragma unroll
    for (int l = 0; l < 16; l++) {
        int idx = tid + l * 256, c = idx >> 6, n = idx & 63;
        s[c][n] = xb[(size_t)c * NN + n];
    }
    __syncthreads();
    __half* dst = g_xT + ((size_t)b * NN + n0) * CC + c0;
    #pragma unroll
    for (int l = 0; l < 16; l++) {
        int idx = tid + l * 256, n = idx >> 6, c = idx & 63;
        dst[(size_t)n * CC + c] = __float2half(s[c][n]);
    }
}

// ---------------- 3) QK conv (fp32 SIMT) + hi/lo transposed epilogue ----------------
__global__ void qkconv_kernel(const float* __restrict__ x)
{
    __shared__ float As[32][64];   // [k][o]
    __shared__ float Bs[32][64];   // [k][n]
    __shared__ float st[64][65];   // [n][o]

    const int n0 = blockIdx.x * 64;
    const int b  = blockIdx.y;
    const int tid = threadIdx.x;
    const int mo = (tid >> 4) * 4;
    const int nn = (tid & 15) * 4;

    float acc[4][4] = {};
    const float* xb = x + (size_t)b * CC * NN;

    for (int k0 = 0; k0 < CC; k0 += 32) {
        #pragma unroll
        for (int l = 0; l < 8; l++) {
            int idx = tid + l * 256;
            int oo = idx & 63, kk = idx >> 6;
            As[kk][oo] = g_WqkT[(size_t)(k0 + kk) * 64 + oo];
            Bs[kk][oo] = xb[(size_t)(k0 + kk) * NN + n0 + oo];
        }
        __syncthreads();
        #pragma unroll
        for (int kk = 0; kk < 32; kk++) {
            float4 av = *(const float4*)&As[kk][mo];
            float4 bv = *(const float4*)&Bs[kk][nn];
            acc[0][0] += av.x * bv.x; acc[0][1] += av.x * bv.y; acc[0][2] += av.x * bv.z; acc[0][3] += av.x * bv.w;
            acc[1][0] += av.y * bv.x; acc[1][1] += av.y * bv.y; acc[1][2] += av.y * bv.z; acc[1][3] += av.y * bv.w;
            acc[2][0] += av.z * bv.x; acc[2][1] += av.z * bv.y; acc[2][2] += av.z * bv.z; acc[2][3] += av.z * bv.w;
            acc[3][0] += av.w * bv.x; acc[3][1] += av.w * bv.y; acc[3][2] += av.w * bv.z; acc[3][3] += av.w * bv.w;
        }
        __syncthreads();
    }

    #pragma unroll
    for (int a = 0; a < 4; a++) {
        float bias = g_Beff[mo + a];
        #pragma unroll
        for (int t = 0; t < 4; t++)
            st[nn + t][mo + a] = fmaxf(acc[a][t] + bias, 0.f);
    }
    __syncthreads();

    const int n = tid >> 2, q = tid & 3;
    __align__(16) __half h8[8], l8[8];
    size_t rowb = ((size_t)b * NN + n0 + n) * 64;
    #pragma unroll
    for (int e = 0; e < 8; e++) {
        float v = st[n][q * 8 + e];
        __half h = __float2half(v);
        h8[e] = h; l8[e] = __float2half(v - __half2float(h));
    }
    *(uint4*)&g_Qt[rowb + q * 8]      = *(uint4*)h8;
    *(uint4*)&g_Qt[rowb + 32 + q * 8] = *(uint4*)l8;
    #pragma unroll
    for (int e = 0; e < 8; e++) {
        float v = st[n][32 + q * 8 + e];
        __half h = __float2half(v);
        h8[e] = h; l8[e] = __float2half(v - __half2float(h));
    }
    *(uint4*)&g_Kt[rowb + q * 8]      = *(uint4*)h8;
    *(uint4*)&g_Kt[rowb + 32 + q * 8] = *(uint4*)l8;
}

// ---------------- 4) V conv MMA: V[c][n] = relu(sum_k Wv[c,k]*xT[n,k] + bias) ----------------
// M=c (128/block), N=n (128/block), K=256 in 4 chunks of 64. 256 thr = 8 warps (2m x 4n).
__global__ void __launch_bounds__(256) vconv_kernel()
{
    __shared__ __align__(128) __half sW[128 * 64];
    __shared__ __align__(128) __half sX[128 * 64];

    const int tid = threadIdx.x, wid = tid >> 5, lane = tid & 31;
    const int wm = wid >> 2, wn = wid & 3;
    const int n0 = blockIdx.x * 128, c0 = blockIdx.y * 128, b = blockIdx.z;

    const uint32_t sw = sm_u32(sW), sx = sm_u32(sX);
    float acc[4][4][4] = {};

    for (int kc = 0; kc < 4; kc++) {
        __syncthreads();
        #pragma unroll
        for (int l = 0; l < 4; l++) {
            int idx = tid + l * 256;      // 0..1023
            int row = idx >> 3, ch = idx & 7;
            int soff = row * 64 + ((ch ^ (row & 7)) << 3);
            *(uint4*)&sW[soff] = *(const uint4*)&g_Wv[(size_t)(c0 + row) * CC + kc * 64 + ch * 8];
            *(uint4*)&sX[soff] = *(const uint4*)&g_xT[((size_t)b * NN + n0 + row) * CC + kc * 64 + ch * 8];
        }
        __syncthreads();

        #pragma unroll
        for (int ks = 0; ks < 4; ks++) {
            uint32_t af[4][4], bf[4][2];
            #pragma unroll
            for (int fm = 0; fm < 4; fm++)
                ldsm_x4(af[fm], tile_addr(sw, wm * 64 + fm * 16 + (lane & 15), ks * 2 + (lane >> 4)));
            #pragma unroll
            for (int fn = 0; fn < 4; fn++) {
                int t = lane & 15;
                ldsm_x2(bf[fn], tile_addr(sx, wn * 32 + fn * 8 + (t & 7), ks * 2 + (t >> 3)));
            }
            #pragma unroll
            for (int fm = 0; fm < 4; fm++)
                #pragma unroll
                for (int fn = 0; fn < 4; fn++)
                    mma16816(acc[fm][fn], af[fm], bf[fn]);
        }
    }

    const int r = lane >> 2, cq = (lane & 3) * 2;
    #pragma unroll
    for (int fm = 0; fm < 4; fm++) {
        #pragma unroll
        for (int fn = 0; fn < 4; fn++) {
            int c = c0 + wm * 64 + fm * 16 + r;
            int n = n0 + wn * 32 + fn * 8 + cq;
            float b0 = g_Beff[64 + c], b1 = g_Beff[64 + c + 8];
            __half2 h0 = __floats2half2_rn(fmaxf(acc[fm][fn][0] + b0, 0.f),
                                           fmaxf(acc[fm][fn][1] + b0, 0.f));
            __half2 h1 = __floats2half2_rn(fmaxf(acc[fm][fn][2] + b1, 0.f),
                                           fmaxf(acc[fm][fn][3] + b1, 0.f));
            *(__half2*)&g_V[((size_t)b * CC + c) * NN + n]     = h0;
            *(__half2*)&g_V[((size_t)b * CC + c + 8) * NN + n] = h1;
        }
    }
}

// ---------------- 5) energy MMA (hi/lo): E[i][j] fp32 ----------------
// M=i 128, N=j 128, K=32 with 3 hi/lo products. 256 thr (2m x 4n warps).
__global__ void __launch_bounds__(256) energy_kernel()
{
    __shared__ __align__(128) __half sQ[128 * 64];
    __shared__ __align__(128) __half sK[128 * 64];

    const int tid = threadIdx.x, wid = tid >> 5, lane = tid & 31;
    const int wm = wid >> 2, wn = wid & 3;
    const int j0 = blockIdx.x * 128, i0 = blockIdx.y * 128, b = blockIdx.z;

    const uint4* qs = (const uint4*)(g_Qt + ((size_t)b * NN + i0) * 64);
    const uint4* ks = (const uint4*)(g_Kt + ((size_t)b * NN + j0) * 64);
    #pragma unroll
    for (int l = 0; l < 4; l++) {
        int idx = tid + l * 256;
        int row = idx >> 3, ch = idx & 7;
        int soff = row * 64 + ((ch ^ (row & 7)) << 3);
        *(uint4*)&sQ[soff] = qs[idx];
        *(uint4*)&sK[soff] = ks[idx];
    }
    __syncthreads();

    const uint32_t sq = sm_u32(sQ), sk = sm_u32(sK);
    float acc[4][4][4] = {};

    #pragma unroll
    for (int prod = 0; prod < 3; prod++) {
        const int acb = (prod == 2) ? 4 : 0;   // ql for product 2
        const int bcb = (prod == 1) ? 4 : 0;   // kl for product 1
        #pragma unroll
        for (int kstep = 0; kstep < 2; kstep++) {
            uint32_t af[4][4], bf[4][2];
            #pragma unroll
            for (int fm = 0; fm < 4; fm++)
                ldsm_x4(af[fm], tile_addr(sq, wm * 64 + fm * 16 + (lane & 15), acb + kstep * 2 + (lane >> 4)));
            #pragma unroll
            for (int fn = 0; fn < 4; fn++) {
                int t = lane & 15;
                ldsm_x2(bf[fn], tile_addr(sk, wn * 32 + fn * 8 + (t & 7), bcb + kstep * 2 + (t >> 3)));
            }
            #pragma unroll
            for (int fm = 0; fm < 4; fm++)
                #pragma unroll
                for (int fn = 0; fn < 4; fn++)
                    mma16816(acc[fm][fn], af[fm], bf[fn]);
        }
    }

    float* eb = g_E + ((size_t)b * NN + i0) * NN + j0;
    const int r = lane >> 2, cq = (lane & 3) * 2;
    #pragma unroll
    for (int fm = 0; fm < 4; fm++) {
        #pragma unroll
        for (int fn = 0; fn < 4; fn++) {
            int i = wm * 64 + fm * 16 + r;
            int j = wn * 32 + fn * 8 + cq;
            float2 v0 = { acc[fm][fn][0], acc[fm][fn][1] };
            float2 v1 = { acc[fm][fn][2], acc[fm][fn][3] };
            *(float2*)&eb[(size_t)i * NN + j]       = v0;
            *(float2*)&eb[(size_t)(i + 8) * NN + j] = v1;
        }
    }
}

// ---------------- 6) softmax (fp32 in, fp16 out) ----------------
__global__ void softmax_kernel()
{
    const size_t row = blockIdx.x;
    const float4* e4 = (const float4*)(g_E + row * NN);
    const int tid = threadIdx.x;

    float4 r[4];
    #pragma unroll
    for (int l = 0; l < 4; l++) r[l] = e4[tid + l * 256];

    float m = -3.4e38f;
    #pragma unroll
    for (int l = 0; l < 4; l++)
        m = fmaxf(m, fmaxf(fmaxf(r[l].x, r[l].y), fmaxf(r[l].z, r[l].w)));
    #pragma unroll
    for (int off = 16; off > 0; off >>= 1)
        m = fmaxf(m, __shfl_xor_sync(0xffffffffu, m, off));

    __shared__ float redm[8], reds[8];
    const int wid = tid >> 5, lane = tid & 31;
    if (lane == 0) redm[wid] = m;
    __syncthreads();
    float bm = redm[0];
    #pragma unroll
    for (int w = 1; w < 8; w++) bm = fmaxf(bm, redm[w]);

    float s = 0.f;
    #pragma unroll
    for (int l = 0; l < 4; l++) {
        r[l].x = __expf(r[l].x - bm); s += r[l].x;
        r[l].y = __expf(r[l].y - bm); s += r[l].y;
        r[l].z = __expf(r[l].z - bm); s += r[l].z;
        r[l].w = __expf(r[l].w - bm); s += r[l].w;
    }
    #pragma unroll
    for (int off = 16; off > 0; off >>= 1)
        s += __shfl_xor_sync(0xffffffffu, s, off);
    if (lane == 0) reds[wid] = s;
    __syncthreads();
    float tot = 0.f;
    #pragma unroll
    for (int w = 0; w < 8; w++) tot += reds[w];
    const float inv = 1.0f / tot;

    __half* arow = g_A + row * NN;
    #pragma unroll
    for (int l = 0; l < 4; l++) {
        int idx4 = tid + l * 256;
        __half2 h0 = __floats2half2_rn(r[l].x * inv, r[l].y * inv);
        __half2 h1 = __floats2half2_rn(r[l].z * inv, r[l].w * inv);
        uint2 pk;
        pk.x = *(uint32_t*)&h0; pk.y = *(uint32_t*)&h1;
        *(uint2*)(arow + (size_t)idx4 * 4) = pk;
    }
}

// ---------------- 7) PV MMA: out[c][i] = gamma*sum_j V[c,j]A[i,j] + x ----------------
// M=c 128, N=i 128, K=j 4096 in 64 chunks, cp.async double buffer (2 x 32KB dyn smem).
__global__ void __launch_bounds__(256) pv_kernel(const float* __restrict__ x,
                                                 const float* __restrict__ gamma,
                                                 float* __restrict__ out)
{
    extern __shared__ __align__(128) __half dynsm[];
    const uint32_t sb = sm_u32(dynsm);

    const int tid = threadIdx.x, wid = tid >> 5, lane = tid & 31;
    const int wm = wid >> 2, wn = wid & 3;
    const int i0 = blockIdx.x * 128, c0 = blockIdx.y * 128, b = blockIdx.z;

    const char* vsrc = (const char*)(g_V + ((size_t)b * CC + c0) * NN);
    const char* asrc = (const char*)(g_A + ((size_t)b * NN + i0) * NN);

    float acc[4][4][4] = {};

    auto issue = [&](int k) {
        const int s = k & 1;
        const uint32_t svb = sb + s * 32768, sab = svb + 16384;
        const size_t kb = (size_t)k * 128;
        #pragma unroll
        for (int l = 0; l < 8; l++) {
            int idx = tid + l * 256;
            if (idx < 1024) {
                int row = idx >> 3, ch = idx & 7;
                cpasync16(svb + row * 128 + ((ch ^ (row & 7)) << 4),
                          vsrc + (size_t)row * (NN * 2) + kb + ch * 16);
            } else {
                int id2 = idx - 1024;
                int row = id2 >> 3, ch = id2 & 7;
                cpasync16(sab + row * 128 + ((ch ^ (row & 7)) << 4),
                          asrc + (size_t)row * (NN * 2) + kb + ch * 16);
            }
        }
        asm volatile("cp.async.commit_group;" ::: "memory");
    };

    issue(0);
    for (int k = 0; k < 64; k++) {
        if (k + 1 < 64) {
            issue(k + 1);
            asm volatile("cp.async.wait_group 1;" ::: "memory");
        } else {
            asm volatile("cp.async.wait_group 0;" ::: "memory");
        }
        __syncthreads();

        const int s = k & 1;
        const uint32_t svb = sb + s * 32768, sab = svb + 16384;
        #pragma unroll
        for (int ks = 0; ks < 4; ks++) {
            uint32_t af[4][4], bf[4][2];
            #pragma unroll
            for (int fm = 0; fm < 4; fm++)
                ldsm_x4(af[fm], tile_addr(svb, wm * 64 + fm * 16 + (lane & 15), ks * 2 + (lane >> 4)));
            #pragma unroll
            for (int fn = 0; fn < 4; fn++) {
                int t = lane & 15;
                ldsm_x2(bf[fn], tile_addr(sab, wn * 32 + fn * 8 + (t & 7), ks * 2 + (t >> 3)));
            }
            #pragma unroll
            for (int fm = 0; fm < 4; fm++)
                #pragma unroll
                for (int fn = 0; fn < 4; fn++)
                    mma16816(acc[fm][fn], af[fm], bf[fn]);
        }
        __syncthreads();
    }

    const float g = gamma[0];
    const int r = lane >> 2, cq = (lane & 3) * 2;
    #pragma unroll
    for (int fm = 0; fm < 4; fm++) {
        #pragma unroll
        for (int fn = 0; fn < 4; fn++) {
            int c = c0 + wm * 64 + fm * 16 + r;
            int i = i0 + wn * 32 + fn * 8 + cq;
            size_t o0 = ((size_t)b * CC + c) * NN + i;
            size_t o1 = ((size_t)b * CC + c + 8) * NN + i;
            float2 x0 = *(const float2*)&x[o0];
            float2 x1 = *(const float2*)&x[o1];
            float2 r0 = { g * acc[fm][fn][0] + x0.x, g * acc[fm][fn][1] + x0.y };
            float2 r1 = { g * acc[fm][fn][2] + x1.x, g * acc[fm][fn][3] + x1.y };
            *(float2*)&out[o0] = r0;
            *(float2*)&out[o1] = r1;
        }
    }
}

// ---------------- launch ----------------
extern "C" void kernel_launch(void* const* d_in, const int* in_sizes, int n_in,
                              void* d_out, int out_size)
{
    const float* x     = (const float*)d_in[0];
    const float* wq    = (const float*)d_in[1];
    const float* bq    = (const float*)d_in[2];
    const float* gq    = (const float*)d_in[3];
    const float* betaq = (const float*)d_in[4];
    const float* mq    = (const float*)d_in[5];
    const float* vq    = (const float*)d_in[6];
    const float* wk    = (const float*)d_in[7];
    const float* bk    = (const float*)d_in[8];
    const float* gk    = (const float*)d_in[9];
    const float* betak = (const float*)d_in[10];
    const float* mk    = (const float*)d_in[11];
    const float* vk    = (const float*)d_in[12];
    const float* wv    = (const float*)d_in[13];
    const float* bv    = (const float*)d_in[14];
    const float* gv    = (const float*)d_in[15];
    const float* betav = (const float*)d_in[16];
    const float* mv    = (const float*)d_in[17];
    const float* vv    = (const float*)d_in[18];
    const float* gamma = (const float*)d_in[19];
    float* out = (float*)d_out;

    cudaFuncSetAttribute(pv_kernel, cudaFuncAttributeMaxDynamicSharedMemorySize, 65536);

    fold_kernel<<<320, 256>>>(wq, bq, gq, betaq, mq, vq,
                              wk, bk, gk, betak, mk, vk,
                              wv, bv, gv, betav, mv, vv);

    packx_kernel<<<dim3(NN / 64, CC / 64, BB), 256>>>(x);

    qkconv_kernel<<<dim3(NN / 64, BB), 256>>>(x);

    vconv_kernel<<<dim3(NN / 128, CC / 128, BB), 256>>>();

    energy_kernel<<<dim3(NN / 128, NN / 128, BB), 256>>>();

    softmax_kernel<<<BB * NN, 256>>>();

    pv_kernel<<<dim3(NN / 128, CC / 128, BB), 256, 65536>>>(x, gamma, out);
}

// round 5
// speedup vs baseline: 8.4853x; 1.1270x over previous
#include <cuda_runtime.h>
#include <cuda_fp16.h>
#include <cstdint>

#define BB 8
#define CC 256
#define NN 4096
#define EPSV 1e-5f
#define L2E 1.4426950408889634f

// ---------------- device-global scratch ----------------
__device__ float  g_WqkT[CC * 64];                 // [c][o] fp32 (QK conv weights)
__device__ __half g_Wv[CC * CC];                   // [c_out][c_in] fp16
__device__ float  g_Beff[320];
__device__ __half g_xT[(size_t)BB * NN * CC];      // [b][n][c] fp16
__device__ __half g_Qt[(size_t)BB * NN * 64];      // [b][n][hi32|lo32]
__device__ __half g_Kt[(size_t)BB * NN * 64];
__device__ __half g_V [(size_t)BB * CC * NN];      // [b][c][n] fp16

// ---------------- helpers ----------------
__device__ __forceinline__ uint32_t sm_u32(const void* p) {
    uint32_t a;
    asm("{ .reg .u64 t; cvta.to.shared.u64 t, %1; cvt.u32.u64 %0, t; }" : "=r"(a) : "l"(p));
    return a;
}
__device__ __forceinline__ void mma16816(float* d, const uint32_t* a, const uint32_t* b) {
    asm volatile(
        "mma.sync.aligned.m16n8k16.row.col.f32.f16.f16.f32 "
        "{%0,%1,%2,%3}, {%4,%5,%6,%7}, {%8,%9}, {%0,%1,%2,%3};"
        : "+f"(d[0]), "+f"(d[1]), "+f"(d[2]), "+f"(d[3])
        : "r"(a[0]), "r"(a[1]), "r"(a[2]), "r"(a[3]), "r"(b[0]), "r"(b[1]));
}
__device__ __forceinline__ void mma16816z(float* d, const uint32_t* a, const uint32_t* b) {
    asm volatile(
        "mma.sync.aligned.m16n8k16.row.col.f32.f16.f16.f32 "
        "{%0,%1,%2,%3}, {%4,%5,%6,%7}, {%8,%9}, {%10,%11,%12,%13};"
        : "=f"(d[0]), "=f"(d[1]), "=f"(d[2]), "=f"(d[3])
        : "r"(a[0]), "r"(a[1]), "r"(a[2]), "r"(a[3]), "r"(b[0]), "r"(b[1]),
          "f"(0.f), "f"(0.f), "f"(0.f), "f"(0.f));
}
__device__ __forceinline__ void ldsm_x4(uint32_t* r, uint32_t addr) {
    asm volatile("ldmatrix.sync.aligned.m8n8.x4.shared.b16 {%0,%1,%2,%3}, [%4];"
        : "=r"(r[0]), "=r"(r[1]), "=r"(r[2]), "=r"(r[3]) : "r"(addr));
}
__device__ __forceinline__ void ldsm_x2(uint32_t* r, uint32_t addr) {
    asm volatile("ldmatrix.sync.aligned.m8n8.x2.shared.b16 {%0,%1}, [%2];"
        : "=r"(r[0]), "=r"(r[1]) : "r"(addr));
}
__device__ __forceinline__ uint32_t tile_addr(uint32_t base, int row, int ch) {
    return base + row * 128 + (((ch) ^ (row & 7)) << 4);
}
__device__ __forceinline__ uint32_t tile_addr256(uint32_t base, int row, int ch) {
    return base + row * 256 + (((((ch) & 7) ^ (row & 7)) | ((ch) & 8)) << 4);
}
__device__ __forceinline__ void cpasync16(uint32_t dst, const void* src) {
    asm volatile("cp.async.cg.shared.global [%0], [%1], 16;" :: "r"(dst), "l"(src) : "memory");
}
__device__ __forceinline__ float ex2(float v) {
    float y; asm("ex2.approx.f32 %0, %1;" : "=f"(y) : "f"(v)); return y;
}
__device__ __forceinline__ uint32_t packh2(float lo, float hi) {
    uint32_t r; asm("cvt.rn.f16x2.f32 %0, %1, %2;" : "=r"(r) : "f"(hi), "f"(lo)); return r;
}

// ---------------- 1) fold BN into conv ----------------
__global__ void fold_kernel(
    const float* __restrict__ wq, const float* __restrict__ bq,
    const float* __restrict__ gq, const float* __restrict__ betaq,
    const float* __restrict__ mq, const float* __restrict__ vq,
    const float* __restrict__ wk, const float* __restrict__ bk,
    const float* __restrict__ gk, const float* __restrict__ betak,
    const float* __restrict__ mk, const float* __restrict__ vk,
    const float* __restrict__ wv, const float* __restrict__ bv,
    const float* __restrict__ gv, const float* __restrict__ betav,
    const float* __restrict__ mv, const float* __restrict__ vv)
{
    int o = blockIdx.x, c = threadIdx.x;
    const float *w, *bb, *g, *beta, *mean, *var;
    int oo;
    if (o < 32)      { w = wq; bb = bq; g = gq; beta = betaq; mean = mq; var = vq; oo = o; }
    else if (o < 64) { w = wk; bb = bk; g = gk; beta = betak; mean = mk; var = vk; oo = o - 32; }
    else             { w = wv; bb = bv; g = gv; beta = betav; mean = mv; var = vv; oo = o - 64; }
    float scale = g[oo] * rsqrtf(var[oo] + EPSV);
    float val = w[oo * CC + c] * scale;
    if (o < 64) g_WqkT[c * 64 + o] = val;
    else        g_Wv[(o - 64) * CC + c] = __float2half(val);
    if (c == 0) g_Beff[o] = (bb[oo] - mean[oo]) * scale + beta[oo];
}

// ---------------- 2) pack x -> x^T fp16  [b][n][c] ----------------
__global__ void packx_kernel(const float* __restrict__ x)
{
    __shared__ float s[64][65];
    const int n0 = blockIdx.x * 64, c0 = blockIdx.y * 64, b = blockIdx.z;
    const int tid = threadIdx.x;
    const float* xb = x + ((size_t)b * CC + c0) * NN + n0;
    #pragma unroll
    for (int l = 0; l < 16; l++) {
        int idx = tid + l * 256, c = idx >> 6, n = idx & 63;
        s[c][n] = xb[(size_t)c * NN + n];
    }
    __syncthreads();
    __half* dst = g_xT + ((size_t)b * NN + n0) * CC + c0;
    #pragma unroll
    for (int l = 0; l < 16; l++) {
        int idx = tid + l * 256, n = idx >> 6, c = idx & 63;
        dst[(size_t)n * CC + c] = __float2half(s[c][n]);
    }
}

// ---------------- 3) QK conv (fp32 SIMT) + hi/lo transposed epilogue ----------------
__global__ void qkconv_kernel(const float* __restrict__ x)
{
    __shared__ float As[32][64];
    __shared__ float Bs[32][64];
    __shared__ float st[64][65];

    const int n0 = blockIdx.x * 64;
    const int b  = blockIdx.y;
    const int tid = threadIdx.x;
    const int mo = (tid >> 4) * 4;
    const int nn = (tid & 15) * 4;

    float acc[4][4] = {};
    const float* xb = x + (size_t)b * CC * NN;

    for (int k0 = 0; k0 < CC; k0 += 32) {
        #pragma unroll
        for (int l = 0; l < 8; l++) {
            int idx = tid + l * 256;
            int oo = idx & 63, kk = idx >> 6;
            As[kk][oo] = g_WqkT[(size_t)(k0 + kk) * 64 + oo];
            Bs[kk][oo] = xb[(size_t)(k0 + kk) * NN + n0 + oo];
        }
        __syncthreads();
        #pragma unroll
        for (int kk = 0; kk < 32; kk++) {
            float4 av = *(const float4*)&As[kk][mo];
            float4 bv = *(const float4*)&Bs[kk][nn];
            acc[0][0] += av.x * bv.x; acc[0][1] += av.x * bv.y; acc[0][2] += av.x * bv.z; acc[0][3] += av.x * bv.w;
            acc[1][0] += av.y * bv.x; acc[1][1] += av.y * bv.y; acc[1][2] += av.y * bv.z; acc[1][3] += av.y * bv.w;
            acc[2][0] += av.z * bv.x; acc[2][1] += av.z * bv.y; acc[2][2] += av.z * bv.z; acc[2][3] += av.z * bv.w;
            acc[3][0] += av.w * bv.x; acc[3][1] += av.w * bv.y; acc[3][2] += av.w * bv.z; acc[3][3] += av.w * bv.w;
        }
        __syncthreads();
    }

    #pragma unroll
    for (int a = 0; a < 4; a++) {
        float bias = g_Beff[mo + a];
        #pragma unroll
        for (int t = 0; t < 4; t++)
            st[nn + t][mo + a] = fmaxf(acc[a][t] + bias, 0.f);
    }
    __syncthreads();

    const int n = tid >> 2, q = tid & 3;
    __align__(16) __half h8[8], l8[8];
    size_t rowb = ((size_t)b * NN + n0 + n) * 64;
    #pragma unroll
    for (int e = 0; e < 8; e++) {
        float v = st[n][q * 8 + e];
        __half h = __float2half(v);
        h8[e] = h; l8[e] = __float2half(v - __half2float(h));
    }
    *(uint4*)&g_Qt[rowb + q * 8]      = *(uint4*)h8;
    *(uint4*)&g_Qt[rowb + 32 + q * 8] = *(uint4*)l8;
    #pragma unroll
    for (int e = 0; e < 8; e++) {
        float v = st[n][32 + q * 8 + e];
        __half h = __float2half(v);
        h8[e] = h; l8[e] = __float2half(v - __half2float(h));
    }
    *(uint4*)&g_Kt[rowb + q * 8]      = *(uint4*)h8;
    *(uint4*)&g_Kt[rowb + 32 + q * 8] = *(uint4*)l8;
}

// ---------------- 4) V conv MMA ----------------
__global__ void __launch_bounds__(256) vconv_kernel()
{
    __shared__ __align__(128) __half sW[128 * 64];
    __shared__ __align__(128) __half sX[128 * 64];

    const int tid = threadIdx.x, wid = tid >> 5, lane = tid & 31;
    const int wm = wid >> 2, wn = wid & 3;
    const int n0 = blockIdx.x * 128, c0 = blockIdx.y * 128, b = blockIdx.z;

    const uint32_t sw = sm_u32(sW), sx = sm_u32(sX);
    float acc[4][4][4] = {};

    for (int kc = 0; kc < 4; kc++) {
        __syncthreads();
        #pragma unroll
        for (int l = 0; l < 4; l++) {
            int idx = tid + l * 256;
            int row = idx >> 3, ch = idx & 7;
            int soff = row * 64 + ((ch ^ (row & 7)) << 3);
            *(uint4*)&sW[soff] = *(const uint4*)&g_Wv[(size_t)(c0 + row) * CC + kc * 64 + ch * 8];
            *(uint4*)&sX[soff] = *(const uint4*)&g_xT[((size_t)b * NN + n0 + row) * CC + kc * 64 + ch * 8];
        }
        __syncthreads();

        #pragma unroll
        for (int ks = 0; ks < 4; ks++) {
            uint32_t af[4][4], bf[4][2];
            #pragma unroll
            for (int fm = 0; fm < 4; fm++)
                ldsm_x4(af[fm], tile_addr(sw, wm * 64 + fm * 16 + (lane & 15), ks * 2 + (lane >> 4)) - (tile_addr(sw,0,0)-sw) + sw - sw + tile_addr(sw, wm * 64 + fm * 16 + (lane & 15), ks * 2 + (lane >> 4)) - tile_addr(sw, wm * 64 + fm * 16 + (lane & 15), ks * 2 + (lane >> 4)));
            #pragma unroll
            for (int fn = 0; fn < 4; fn++) {
                int t = lane & 15;
                ldsm_x2(bf[fn], sx + (wn * 32 + fn * 8 + (t & 7)) * 64 * 2 + ((((ks * 2 + (t >> 3)) ^ ((wn * 32 + fn * 8 + (t & 7)) & 7))) << 4));
            }
            #pragma unroll
            for (int fm = 0; fm < 4; fm++)
                #pragma unroll
                for (int fn = 0; fn < 4; fn++)
                    mma16816(acc[fm][fn], af[fm], bf[fn]);
        }
    }

    const int r = lane >> 2, cq = (lane & 3) * 2;
    #pragma unroll
    for (int fm = 0; fm < 4; fm++) {
        #pragma unroll
        for (int fn = 0; fn < 4; fn++) {
            int c = c0 + wm * 64 + fm * 16 + r;
            int n = n0 + wn * 32 + fn * 8 + cq;
            float b0 = g_Beff[64 + c], b1 = g_Beff[64 + c + 8];
            __half2 h0 = __floats2half2_rn(fmaxf(acc[fm][fn][0] + b0, 0.f),
                                           fmaxf(acc[fm][fn][1] + b0, 0.f));
            __half2 h1 = __floats2half2_rn(fmaxf(acc[fm][fn][2] + b1, 0.f),
                                           fmaxf(acc[fm][fn][3] + b1, 0.f));
            *(__half2*)&g_V[((size_t)b * CC + c) * NN + n]     = h0;
            *(__half2*)&g_V[((size_t)b * CC + c + 8) * NN + n] = h1;
        }
    }
}

// ---------------- 5) fused flash attention: S=QK^T (hi/lo), online softmax, O=P.V^T ----
// grid (32 i-tiles, 2 c-halves, 8 b), 256 thr. Each warp owns 16 full i-rows.
// dyn smem: Q 16KB | stage0 {K 16KB, V 32KB} | stage1 {K 16KB, V 32KB} = 114688 B
__global__ void __launch_bounds__(256, 1) flash_kernel(const float* __restrict__ x,
                                                       const float* __restrict__ gamma,
                                                       float* __restrict__ out)
{
    extern __shared__ __align__(128) unsigned char dsm[];
    const uint32_t sb = sm_u32(dsm);
    const uint32_t sQ = sb;

    const int tid = threadIdx.x, wid = tid >> 5, lane = tid & 31;
    const int i0 = blockIdx.x * 128, c0 = blockIdx.y * 128, b = blockIdx.z;

    const char* qsrc = (const char*)(g_Qt + ((size_t)b * NN + i0) * 64);
    const char* ksrc = (const char*)(g_Kt + (size_t)b * NN * 64);
    const char* vsrc = (const char*)(g_V + ((size_t)b * CC + c0) * NN);

    // Q tile (16 KB, contiguous)
    #pragma unroll
    for (int l = 0; l < 4; l++) {
        int idx = tid + l * 256;
        int row = idx >> 3, ch = idx & 7;
        cpasync16(tile_addr(sQ, row, ch), qsrc + (size_t)idx * 16);
    }
    asm volatile("cp.async.commit_group;" ::: "memory");

    auto issueKV = [&](int it) {
        const uint32_t kb = sb + 16384 + (it & 1) * 49152;
        const uint32_t vb = kb + 16384;
        const char* ks = ksrc + (size_t)it * 128 * 128;   // 128 rows * 128 B
        #pragma unroll
        for (int l = 0; l < 4; l++) {
            int idx = tid + l * 256;
            int row = idx >> 3, ch = idx & 7;
            cpasync16(tile_addr(kb, row, ch), ks + (size_t)idx * 16);
        }
        const size_t jb = (size_t)it * 256;               // 128 j * 2 B
        #pragma unroll
        for (int l = 0; l < 8; l++) {
            int idx = tid + l * 256;
            int row = idx >> 4, ch = idx & 15;
            cpasync16(tile_addr256(vb, row, ch), vsrc + (size_t)row * (NN * 2) + jb + ch * 16);
        }
        asm volatile("cp.async.commit_group;" ::: "memory");
    };

    issueKV(0);
    asm volatile("cp.async.wait_group 1;" ::: "memory");
    __syncthreads();

    // Q A-frags (held in registers for all 32 iterations)
    uint32_t qA[4][4];
    #pragma unroll
    for (int ck = 0; ck < 4; ck++)
        ldsm_x4(qA[ck], tile_addr(sQ, wid * 16 + (lane & 15), ck * 2 + (lane >> 4)));

    float oacc[16][4] = {};
    float m0 = -1e30f, m1 = -1e30f, l0 = 0.f, l1 = 0.f;

    for (int it = 0; it < 32; it++) {
        __syncthreads();   // everyone done with buffer (it+1)&1 from iteration it-1
        if (it + 1 < 32) {
            issueKV(it + 1);
            asm volatile("cp.async.wait_group 1;" ::: "memory");
        } else {
            asm volatile("cp.async.wait_group 0;" ::: "memory");
        }
        __syncthreads();   // buffer (it&1) fully loaded by all threads

        const uint32_t kb = sb + 16384 + (it & 1) * 49152;
        const uint32_t vb = kb + 16384;

        // ---- S = Q.K^T (hi/lo, 3 products) ----
        float sacc[16][4];
        #pragma unroll
        for (int n = 0; n < 16; n++) {
            uint32_t Bh[4], Bl[4];
            ldsm_x4(Bh, tile_addr(kb, n * 8 + (lane & 7), (lane >> 3) & 3));
            ldsm_x4(Bl, tile_addr(kb, n * 8 + (lane & 7), 4 + ((lane >> 3) & 3)));
            mma16816z(sacc[n], qA[0], Bh);          // qh . kh (k 0-15)
            mma16816 (sacc[n], qA[1], Bh + 2);      // qh . kh (k 16-31)
            mma16816 (sacc[n], qA[0], Bl);          // qh . kl
            mma16816 (sacc[n], qA[1], Bl + 2);
            mma16816 (sacc[n], qA[2], Bh);          // ql . kh
            mma16816 (sacc[n], qA[3], Bh + 2);
        }

        // ---- online softmax (warp-local rows) ----
        float tm0 = -1e30f, tm1 = -1e30f;
        #pragma unroll
        for (int n = 0; n < 16; n++) {
            tm0 = fmaxf(tm0, fmaxf(sacc[n][0], sacc[n][1]));
            tm1 = fmaxf(tm1, fmaxf(sacc[n][2], sacc[n][3]));
        }
        tm0 = fmaxf(tm0, __shfl_xor_sync(0xffffffffu, tm0, 1));
        tm0 = fmaxf(tm0, __shfl_xor_sync(0xffffffffu, tm0, 2));
        tm1 = fmaxf(tm1, __shfl_xor_sync(0xffffffffu, tm1, 1));
        tm1 = fmaxf(tm1, __shfl_xor_sync(0xffffffffu, tm1, 2));

        float nm0 = fmaxf(m0, tm0), nm1 = fmaxf(m1, tm1);
        float sc0 = ex2((m0 - nm0) * L2E);
        float sc1 = ex2((m1 - nm1) * L2E);
        m0 = nm0; m1 = nm1;
        const float cc0 = nm0 * L2E, cc1 = nm1 * L2E;

        float rs0 = 0.f, rs1 = 0.f;
        uint32_t pk[16][2];
        #pragma unroll
        for (int n = 0; n < 16; n++) {
            float p0 = ex2(sacc[n][0] * L2E - cc0);
            float p1 = ex2(sacc[n][1] * L2E - cc0);
            float p2 = ex2(sacc[n][2] * L2E - cc1);
            float p3 = ex2(sacc[n][3] * L2E - cc1);
            rs0 += p0 + p1; rs1 += p2 + p3;
            pk[n][0] = packh2(p0, p1);
            pk[n][1] = packh2(p2, p3);
        }
        rs0 += __shfl_xor_sync(0xffffffffu, rs0, 1);
        rs0 += __shfl_xor_sync(0xffffffffu, rs0, 2);
        rs1 += __shfl_xor_sync(0xffffffffu, rs1, 1);
        rs1 += __shfl_xor_sync(0xffffffffu, rs1, 2);
        l0 = l0 * sc0 + rs0;
        l1 = l1 * sc1 + rs1;

        #pragma unroll
        for (int n = 0; n < 16; n++) {
            oacc[n][0] *= sc0; oacc[n][1] *= sc0;
            oacc[n][2] *= sc1; oacc[n][3] *= sc1;
        }

        // ---- O += P . V^T ----
        #pragma unroll
        for (int ks = 0; ks < 8; ks++) {
            uint32_t A[4] = { pk[2 * ks][0], pk[2 * ks][1], pk[2 * ks + 1][0], pk[2 * ks + 1][1] };
            #pragma unroll
            for (int cp = 0; cp < 8; cp++) {
                uint32_t Bv[4];
                ldsm_x4(Bv, tile_addr256(vb, cp * 16 + (lane & 7) + ((lane >> 4) << 3),
                                         ks * 2 + ((lane >> 3) & 1)));
                mma16816(oacc[2 * cp],     A, Bv);
                mma16816(oacc[2 * cp + 1], A, Bv + 2);
            }
        }
    }

    // ---- epilogue: out = gamma * O / l + x ----
    const float g = gamma[0];
    const float il0 = g / l0, il1 = g / l1;
    const int r = lane >> 2, q = lane & 3;
    #pragma unroll
    for (int n = 0; n < 16; n++) {
        #pragma unroll
        for (int e = 0; e < 4; e++) {
            int c = c0 + n * 8 + q * 2 + (e & 1);
            int i = i0 + wid * 16 + r + (e >> 1) * 8;
            size_t off = ((size_t)b * CC + c) * NN + i;
            out[off] = oacc[n][e] * ((e < 2) ? il0 : il1) + x[off];
        }
    }
}

// ---------------- launch ----------------
extern "C" void kernel_launch(void* const* d_in, const int* in_sizes, int n_in,
                              void* d_out, int out_size)
{
    const float* x     = (const float*)d_in[0];
    const float* wq    = (const float*)d_in[1];
    const float* bq    = (const float*)d_in[2];
    const float* gq    = (const float*)d_in[3];
    const float* betaq = (const float*)d_in[4];
    const float* mq    = (const float*)d_in[5];
    const float* vq    = (const float*)d_in[6];
    const float* wk    = (const float*)d_in[7];
    const float* bk    = (const float*)d_in[8];
    const float* gk    = (const float*)d_in[9];
    const float* betak = (const float*)d_in[10];
    const float* mk    = (const float*)d_in[11];
    const float* vk    = (const float*)d_in[12];
    const float* wv    = (const float*)d_in[13];
    const float* bv    = (const float*)d_in[14];
    const float* gv    = (const float*)d_in[15];
    const float* betav = (const float*)d_in[16];
    const float* mv    = (const float*)d_in[17];
    const float* vv    = (const float*)d_in[18];
    const float* gamma = (const float*)d_in[19];
    float* out = (float*)d_out;

    cudaFuncSetAttribute(flash_kernel, cudaFuncAttributeMaxDynamicSharedMemorySize, 114688);

    fold_kernel<<<320, 256>>>(wq, bq, gq, betaq, mq, vq,
                              wk, bk, gk, betak, mk, vk,
                              wv, bv, gv, betav, mv, vv);

    packx_kernel<<<dim3(NN / 64, CC / 64, BB), 256>>>(x);

    qkconv_kernel<<<dim3(NN / 64, BB), 256>>>(x);

    vconv_kernel<<<dim3(NN / 128, CC / 128, BB), 256>>>();

    flash_kernel<<<dim3(NN / 128, 2, BB), 256, 114688>>>(x, gamma, out);
}

// round 6
// speedup vs baseline: 8.9347x; 1.0530x over previous
#include <cuda_runtime.h>
#include <cuda_fp16.h>
#include <cstdint>

#define BB 8
#define CC 256
#define NN 4096
#define EPSV 1e-5f
#define L2E 1.4426950408889634f

// ---------------- device-global scratch ----------------
__device__ float  g_WqkT[CC * 64];                 // [c][o] fp32 (QK conv weights)
__device__ __half g_Wv[CC * CC];                   // [c_out][c_in] fp16
__device__ float  g_Beff[320];
__device__ __half g_xT[(size_t)BB * NN * CC];      // [b][n][c] fp16
__device__ __half g_Qt[(size_t)BB * NN * 64];      // [b][n][hi32|lo32] (lo unused now)
__device__ __half g_Kt[(size_t)BB * NN * 64];
__device__ __half g_V [(size_t)BB * CC * NN];      // [b][c][n] fp16

// ---------------- helpers ----------------
__device__ __forceinline__ uint32_t sm_u32(const void* p) {
    uint32_t a;
    asm("{ .reg .u64 t; cvta.to.shared.u64 t, %1; cvt.u32.u64 %0, t; }" : "=r"(a) : "l"(p));
    return a;
}
__device__ __forceinline__ void mma16816(float* d, const uint32_t* a, const uint32_t* b) {
    asm volatile(
        "mma.sync.aligned.m16n8k16.row.col.f32.f16.f16.f32 "
        "{%0,%1,%2,%3}, {%4,%5,%6,%7}, {%8,%9}, {%0,%1,%2,%3};"
        : "+f"(d[0]), "+f"(d[1]), "+f"(d[2]), "+f"(d[3])
        : "r"(a[0]), "r"(a[1]), "r"(a[2]), "r"(a[3]), "r"(b[0]), "r"(b[1]));
}
__device__ __forceinline__ void mma16816z(float* d, const uint32_t* a, const uint32_t* b) {
    asm volatile(
        "mma.sync.aligned.m16n8k16.row.col.f32.f16.f16.f32 "
        "{%0,%1,%2,%3}, {%4,%5,%6,%7}, {%8,%9}, {%10,%11,%12,%13};"
        : "=f"(d[0]), "=f"(d[1]), "=f"(d[2]), "=f"(d[3])
        : "r"(a[0]), "r"(a[1]), "r"(a[2]), "r"(a[3]), "r"(b[0]), "r"(b[1]),
          "f"(0.f), "f"(0.f), "f"(0.f), "f"(0.f));
}
__device__ __forceinline__ void ldsm_x4(uint32_t* r, uint32_t addr) {
    asm volatile("ldmatrix.sync.aligned.m8n8.x4.shared.b16 {%0,%1,%2,%3}, [%4];"
        : "=r"(r[0]), "=r"(r[1]), "=r"(r[2]), "=r"(r[3]) : "r"(addr));
}
__device__ __forceinline__ void ldsm_x2(uint32_t* r, uint32_t addr) {
    asm volatile("ldmatrix.sync.aligned.m8n8.x2.shared.b16 {%0,%1}, [%2];"
        : "=r"(r[0]), "=r"(r[1]) : "r"(addr));
}
__device__ __forceinline__ uint32_t tile_addr(uint32_t base, int row, int ch) {
    return base + row * 128 + (((ch) ^ (row & 7)) << 4);
}
__device__ __forceinline__ uint32_t tile_addr256(uint32_t base, int row, int ch) {
    return base + row * 256 + (((((ch) & 7) ^ (row & 7)) | ((ch) & 8)) << 4);
}
__device__ __forceinline__ void cpasync16(uint32_t dst, const void* src) {
    asm volatile("cp.async.cg.shared.global [%0], [%1], 16;" :: "r"(dst), "l"(src) : "memory");
}
__device__ __forceinline__ float ex2(float v) {
    float y; asm("ex2.approx.f32 %0, %1;" : "=f"(y) : "f"(v)); return y;
}
__device__ __forceinline__ uint32_t packh2(float lo, float hi) {
    uint32_t r; asm("cvt.rn.f16x2.f32 %0, %1, %2;" : "=r"(r) : "f"(hi), "f"(lo)); return r;
}

// ---------------- 1) fold BN into conv ----------------
__global__ void fold_kernel(
    const float* __restrict__ wq, const float* __restrict__ bq,
    const float* __restrict__ gq, const float* __restrict__ betaq,
    const float* __restrict__ mq, const float* __restrict__ vq,
    const float* __restrict__ wk, const float* __restrict__ bk,
    const float* __restrict__ gk, const float* __restrict__ betak,
    const float* __restrict__ mk, const float* __restrict__ vk,
    const float* __restrict__ wv, const float* __restrict__ bv,
    const float* __restrict__ gv, const float* __restrict__ betav,
    const float* __restrict__ mv, const float* __restrict__ vv)
{
    int o = blockIdx.x, c = threadIdx.x;
    const float *w, *bb, *g, *beta, *mean, *var;
    int oo;
    if (o < 32)      { w = wq; bb = bq; g = gq; beta = betaq; mean = mq; var = vq; oo = o; }
    else if (o < 64) { w = wk; bb = bk; g = gk; beta = betak; mean = mk; var = vk; oo = o - 32; }
    else             { w = wv; bb = bv; g = gv; beta = betav; mean = mv; var = vv; oo = o - 64; }
    float scale = g[oo] * rsqrtf(var[oo] + EPSV);
    float val = w[oo * CC + c] * scale;
    if (o < 64) g_WqkT[c * 64 + o] = val;
    else        g_Wv[(o - 64) * CC + c] = __float2half(val);
    if (c == 0) g_Beff[o] = (bb[oo] - mean[oo]) * scale + beta[oo];
}

// ---------------- 2) pack x -> x^T fp16  [b][n][c] ----------------
__global__ void packx_kernel(const float* __restrict__ x)
{
    __shared__ float s[64][65];
    const int n0 = blockIdx.x * 64, c0 = blockIdx.y * 64, b = blockIdx.z;
    const int tid = threadIdx.x;
    const float* xb = x + ((size_t)b * CC + c0) * NN + n0;
    #pragma unroll
    for (int l = 0; l < 16; l++) {
        int idx = tid + l * 256, c = idx >> 6, n = idx & 63;
        s[c][n] = xb[(size_t)c * NN + n];
    }
    __syncthreads();
    __half* dst = g_xT + ((size_t)b * NN + n0) * CC + c0;
    #pragma unroll
    for (int l = 0; l < 16; l++) {
        int idx = tid + l * 256, n = idx >> 6, c = idx & 63;
        dst[(size_t)n * CC + c] = __float2half(s[c][n]);
    }
}

// ---------------- 3) QK conv (fp32 SIMT) + transposed epilogue (Q hi only, K hi/lo) ----
__global__ void qkconv_kernel(const float* __restrict__ x)
{
    __shared__ float As[32][64];
    __shared__ float Bs[32][64];
    __shared__ float st[64][65];

    const int n0 = blockIdx.x * 64;
    const int b  = blockIdx.y;
    const int tid = threadIdx.x;
    const int mo = (tid >> 4) * 4;
    const int nn = (tid & 15) * 4;

    float acc[4][4] = {};
    const float* xb = x + (size_t)b * CC * NN;

    for (int k0 = 0; k0 < CC; k0 += 32) {
        #pragma unroll
        for (int l = 0; l < 8; l++) {
            int idx = tid + l * 256;
            int oo = idx & 63, kk = idx >> 6;
            As[kk][oo] = g_WqkT[(size_t)(k0 + kk) * 64 + oo];
            Bs[kk][oo] = xb[(size_t)(k0 + kk) * NN + n0 + oo];
        }
        __syncthreads();
        #pragma unroll
        for (int kk = 0; kk < 32; kk++) {
            float4 av = *(const float4*)&As[kk][mo];
            float4 bv = *(const float4*)&Bs[kk][nn];
            acc[0][0] += av.x * bv.x; acc[0][1] += av.x * bv.y; acc[0][2] += av.x * bv.z; acc[0][3] += av.x * bv.w;
            acc[1][0] += av.y * bv.x; acc[1][1] += av.y * bv.y; acc[1][2] += av.y * bv.z; acc[1][3] += av.y * bv.w;
            acc[2][0] += av.z * bv.x; acc[2][1] += av.z * bv.y; acc[2][2] += av.z * bv.z; acc[2][3] += av.z * bv.w;
            acc[3][0] += av.w * bv.x; acc[3][1] += av.w * bv.y; acc[3][2] += av.w * bv.z; acc[3][3] += av.w * bv.w;
        }
        __syncthreads();
    }

    #pragma unroll
    for (int a = 0; a < 4; a++) {
        float bias = g_Beff[mo + a];
        #pragma unroll
        for (int t = 0; t < 4; t++)
            st[nn + t][mo + a] = fmaxf(acc[a][t] + bias, 0.f);
    }
    __syncthreads();

    const int n = tid >> 2, q = tid & 3;
    __align__(16) __half h8[8], l8[8];
    size_t rowb = ((size_t)b * NN + n0 + n) * 64;
    #pragma unroll
    for (int e = 0; e < 8; e++) {
        float v = st[n][q * 8 + e];
        __half h = __float2half(v);
        h8[e] = h; l8[e] = __float2half(v - __half2float(h));
    }
    *(uint4*)&g_Qt[rowb + q * 8]      = *(uint4*)h8;
    *(uint4*)&g_Qt[rowb + 32 + q * 8] = *(uint4*)l8;   // kept for layout, unused
    #pragma unroll
    for (int e = 0; e < 8; e++) {
        float v = st[n][32 + q * 8 + e];
        __half h = __float2half(v);
        h8[e] = h; l8[e] = __float2half(v - __half2float(h));
    }
    *(uint4*)&g_Kt[rowb + q * 8]      = *(uint4*)h8;
    *(uint4*)&g_Kt[rowb + 32 + q * 8] = *(uint4*)l8;
}

// ---------------- 4) V conv MMA: tile 64c x 128n, K=256 in 4 chunks ----------------
__global__ void __launch_bounds__(256) vconv_kernel()
{
    __shared__ __align__(128) __half sW[64 * 64];    // [c][k] 8KB
    __shared__ __align__(128) __half sX[128 * 64];   // [n][k] 16KB

    const int tid = threadIdx.x, wid = tid >> 5, lane = tid & 31;
    const int wm = wid >> 2, wn = wid & 3;           // 2 c-halves x 4 n-quarters
    const int n0 = blockIdx.x * 128, c0 = blockIdx.y * 64, b = blockIdx.z;

    const uint32_t sw = sm_u32(sW), sx = sm_u32(sX);
    float acc[2][4][4] = {};

    for (int kc = 0; kc < 4; kc++) {
        __syncthreads();
        #pragma unroll
        for (int l = 0; l < 2; l++) {                // sW: 512 chunks
            int idx = tid + l * 256;
            int row = idx >> 3, ch = idx & 7;
            *(uint4*)&sW[(tile_addr(sw, row, ch) - sw) >> 1] =
                *(const uint4*)&g_Wv[(size_t)(c0 + row) * CC + kc * 64 + ch * 8];
        }
        #pragma unroll
        for (int l = 0; l < 4; l++) {                // sX: 1024 chunks
            int idx = tid + l * 256;
            int row = idx >> 3, ch = idx & 7;
            *(uint4*)&sX[(tile_addr(sx, row, ch) - sx) >> 1] =
                *(const uint4*)&g_xT[((size_t)b * NN + n0 + row) * CC + kc * 64 + ch * 8];
        }
        __syncthreads();

        #pragma unroll
        for (int ks = 0; ks < 4; ks++) {
            uint32_t af[2][4], bf[4][2];
            #pragma unroll
            for (int fm = 0; fm < 2; fm++)
                ldsm_x4(af[fm], tile_addr(sw, wm * 32 + fm * 16 + (lane & 15), ks * 2 + (lane >> 4)));
            #pragma unroll
            for (int fn = 0; fn < 4; fn++) {
                int t = lane & 15;
                ldsm_x2(bf[fn], tile_addr(sx, wn * 32 + fn * 8 + (t & 7), ks * 2 + (t >> 3)));
            }
            #pragma unroll
            for (int fm = 0; fm < 2; fm++)
                #pragma unroll
                for (int fn = 0; fn < 4; fn++)
                    mma16816(acc[fm][fn], af[fm], bf[fn]);
        }
    }

    const int r = lane >> 2, cq = (lane & 3) * 2;
    #pragma unroll
    for (int fm = 0; fm < 2; fm++) {
        #pragma unroll
        for (int fn = 0; fn < 4; fn++) {
            int c = c0 + wm * 32 + fm * 16 + r;
            int n = n0 + wn * 32 + fn * 8 + cq;
            float b0 = g_Beff[64 + c], b1 = g_Beff[64 + c + 8];
            __half2 h0 = __floats2half2_rn(fmaxf(acc[fm][fn][0] + b0, 0.f),
                                           fmaxf(acc[fm][fn][1] + b0, 0.f));
            __half2 h1 = __floats2half2_rn(fmaxf(acc[fm][fn][2] + b1, 0.f),
                                           fmaxf(acc[fm][fn][3] + b1, 0.f));
            *(__half2*)&g_V[((size_t)b * CC + c) * NN + n]     = h0;
            *(__half2*)&g_V[((size_t)b * CC + c + 8) * NN + n] = h1;
        }
    }
}

// ---------------- 5) fused flash attention (S = qh.kh + qh.kl, online softmax, O=P.V^T) ----
// grid (32 i-tiles, 2 c-halves, 8 b), 256 thr. Each warp owns 16 full i-rows.
// dyn smem: Q 16KB | stage0 {K 16KB, V 32KB} | stage1 {K 16KB, V 32KB} = 114688 B
__global__ void __launch_bounds__(256, 1) flash_kernel(const float* __restrict__ x,
                                                       const float* __restrict__ gamma,
                                                       float* __restrict__ out)
{
    extern __shared__ __align__(128) unsigned char dsm[];
    const uint32_t sb = sm_u32(dsm);
    const uint32_t sQ = sb;

    const int tid = threadIdx.x, wid = tid >> 5, lane = tid & 31;
    const int i0 = blockIdx.x * 128, c0 = blockIdx.y * 128, b = blockIdx.z;

    const char* qsrc = (const char*)(g_Qt + ((size_t)b * NN + i0) * 64);
    const char* ksrc = (const char*)(g_Kt + (size_t)b * NN * 64);
    const char* vsrc = (const char*)(g_V + ((size_t)b * CC + c0) * NN);

    // Q tile: only the hi half (first 64B of each 128B row)
    #pragma unroll
    for (int l = 0; l < 2; l++) {
        int idx = tid + l * 256;          // 0..511
        int row = idx >> 2, ch = idx & 3;
        cpasync16(tile_addr(sQ, row, ch), qsrc + (size_t)row * 128 + ch * 16);
    }
    asm volatile("cp.async.commit_group;" ::: "memory");

    auto issueKV = [&](int it) {
        const uint32_t kb = sb + 16384 + (it & 1) * 49152;
        const uint32_t vb = kb + 16384;
        const char* ks = ksrc + (size_t)it * 128 * 128;   // 128 rows * 128 B
        #pragma unroll
        for (int l = 0; l < 4; l++) {
            int idx = tid + l * 256;
            int row = idx >> 3, ch = idx & 7;
            cpasync16(tile_addr(kb, row, ch), ks + (size_t)idx * 16);
        }
        const size_t jb = (size_t)it * 256;               // 128 j * 2 B
        #pragma unroll
        for (int l = 0; l < 8; l++) {
            int idx = tid + l * 256;
            int row = idx >> 4, ch = idx & 15;
            cpasync16(tile_addr256(vb, row, ch), vsrc + (size_t)row * (NN * 2) + jb + ch * 16);
        }
        asm volatile("cp.async.commit_group;" ::: "memory");
    };

    issueKV(0);
    asm volatile("cp.async.wait_group 1;" ::: "memory");
    __syncthreads();

    // Q hi A-frags (k = 0..31)
    uint32_t qA[2][4];
    #pragma unroll
    for (int ck = 0; ck < 2; ck++)
        ldsm_x4(qA[ck], tile_addr(sQ, wid * 16 + (lane & 15), ck * 2 + (lane >> 4)));

    float oacc[16][4] = {};
    float m0 = -1e30f, m1 = -1e30f, l0 = 0.f, l1 = 0.f;

    for (int it = 0; it < 32; it++) {
        __syncthreads();
        if (it + 1 < 32) {
            issueKV(it + 1);
            asm volatile("cp.async.wait_group 1;" ::: "memory");
        } else {
            asm volatile("cp.async.wait_group 0;" ::: "memory");
        }
        __syncthreads();

        const uint32_t kb = sb + 16384 + (it & 1) * 49152;
        const uint32_t vb = kb + 16384;

        // ---- S = qh.(kh + kl)  (4 MMAs per 8-j tile) ----
        float sacc[16][4];
        #pragma unroll
        for (int n = 0; n < 16; n++) {
            uint32_t Bh[4], Bl[4];
            ldsm_x4(Bh, tile_addr(kb, n * 8 + (lane & 7), (lane >> 3) & 3));
            ldsm_x4(Bl, tile_addr(kb, n * 8 + (lane & 7), 4 + ((lane >> 3) & 3)));
            mma16816z(sacc[n], qA[0], Bh);
            mma16816 (sacc[n], qA[1], Bh + 2);
            mma16816 (sacc[n], qA[0], Bl);
            mma16816 (sacc[n], qA[1], Bl + 2);
        }

        // ---- online softmax (warp-local rows) ----
        float tm0 = -1e30f, tm1 = -1e30f;
        #pragma unroll
        for (int n = 0; n < 16; n++) {
            tm0 = fmaxf(tm0, fmaxf(sacc[n][0], sacc[n][1]));
            tm1 = fmaxf(tm1, fmaxf(sacc[n][2], sacc[n][3]));
        }
        tm0 = fmaxf(tm0, __shfl_xor_sync(0xffffffffu, tm0, 1));
        tm0 = fmaxf(tm0, __shfl_xor_sync(0xffffffffu, tm0, 2));
        tm1 = fmaxf(tm1, __shfl_xor_sync(0xffffffffu, tm1, 1));
        tm1 = fmaxf(tm1, __shfl_xor_sync(0xffffffffu, tm1, 2));

        float nm0 = fmaxf(m0, tm0), nm1 = fmaxf(m1, tm1);
        float sc0 = ex2((m0 - nm0) * L2E);
        float sc1 = ex2((m1 - nm1) * L2E);
        m0 = nm0; m1 = nm1;
        const float cc0 = nm0 * L2E, cc1 = nm1 * L2E;

        float rs0 = 0.f, rs1 = 0.f;
        uint32_t pk[16][2];
        #pragma unroll
        for (int n = 0; n < 16; n++) {
            float p0 = ex2(sacc[n][0] * L2E - cc0);
            float p1 = ex2(sacc[n][1] * L2E - cc0);
            float p2 = ex2(sacc[n][2] * L2E - cc1);
            float p3 = ex2(sacc[n][3] * L2E - cc1);
            rs0 += p0 + p1; rs1 += p2 + p3;
            pk[n][0] = packh2(p0, p1);
            pk[n][1] = packh2(p2, p3);
        }
        rs0 += __shfl_xor_sync(0xffffffffu, rs0, 1);
        rs0 += __shfl_xor_sync(0xffffffffu, rs0, 2);
        rs1 += __shfl_xor_sync(0xffffffffu, rs1, 1);
        rs1 += __shfl_xor_sync(0xffffffffu, rs1, 2);
        l0 = l0 * sc0 + rs0;
        l1 = l1 * sc1 + rs1;

        #pragma unroll
        for (int n = 0; n < 16; n++) {
            oacc[n][0] *= sc0; oacc[n][1] *= sc0;
            oacc[n][2] *= sc1; oacc[n][3] *= sc1;
        }

        // ---- O += P . V^T ----
        #pragma unroll
        for (int ks = 0; ks < 8; ks++) {
            uint32_t A[4] = { pk[2 * ks][0], pk[2 * ks][1], pk[2 * ks + 1][0], pk[2 * ks + 1][1] };
            #pragma unroll
            for (int cp = 0; cp < 8; cp++) {
                uint32_t Bv[4];
                ldsm_x4(Bv, tile_addr256(vb, cp * 16 + (lane & 7) + ((lane >> 4) << 3),
                                         ks * 2 + ((lane >> 3) & 1)));
                mma16816(oacc[2 * cp],     A, Bv);
                mma16816(oacc[2 * cp + 1], A, Bv + 2);
            }
        }
    }

    // ---- epilogue: out = gamma * O / l + x ----
    const float g = gamma[0];
    const float il0 = g / l0, il1 = g / l1;
    const int r = lane >> 2, q = lane & 3;
    #pragma unroll
    for (int n = 0; n < 16; n++) {
        #pragma unroll
        for (int e = 0; e < 4; e++) {
            int c = c0 + n * 8 + q * 2 + (e & 1);
            int i = i0 + wid * 16 + r + (e >> 1) * 8;
            size_t off = ((size_t)b * CC + c) * NN + i;
            out[off] = oacc[n][e] * ((e < 2) ? il0 : il1) + x[off];
        }
    }
}

// ---------------- launch ----------------
extern "C" void kernel_launch(void* const* d_in, const int* in_sizes, int n_in,
                              void* d_out, int out_size)
{
    const float* x     = (const float*)d_in[0];
    const float* wq    = (const float*)d_in[1];
    const float* bq    = (const float*)d_in[2];
    const float* gq    = (const float*)d_in[3];
    const float* betaq = (const float*)d_in[4];
    const float* mq    = (const float*)d_in[5];
    const float* vq    = (const float*)d_in[6];
    const float* wk    = (const float*)d_in[7];
    const float* bk    = (const float*)d_in[8];
    const float* gk    = (const float*)d_in[9];
    const float* betak = (const float*)d_in[10];
    const float* mk    = (const float*)d_in[11];
    const float* vk    = (const float*)d_in[12];
    const float* wv    = (const float*)d_in[13];
    const float* bv    = (const float*)d_in[14];
    const float* gv    = (const float*)d_in[15];
    const float* betav = (const float*)d_in[16];
    const float* mv    = (const float*)d_in[17];
    const float* vv    = (const float*)d_in[18];
    const float* gamma = (const float*)d_in[19];
    float* out = (float*)d_out;

    cudaFuncSetAttribute(flash_kernel, cudaFuncAttributeMaxDynamicSharedMemorySize, 114688);

    fold_kernel<<<320, 256>>>(wq, bq, gq, betaq, mq, vq,
                              wk, bk, gk, betak, mk, vk,
                              wv, bv, gv, betav, mv, vv);

    packx_kernel<<<dim3(NN / 64, CC / 64, BB), 256>>>(x);

    qkconv_kernel<<<dim3(NN / 64, BB), 256>>>(x);

    vconv_kernel<<<dim3(NN / 128, CC / 64, BB), 256>>>();

    flash_kernel<<<dim3(NN / 128, 2, BB), 256, 114688>>>(x, gamma, out);
}

// round 7
// speedup vs baseline: 9.4412x; 1.0567x over previous
#include <cuda_runtime.h>
#include <cuda_fp16.h>
#include <cstdint>

#define BB 8
#define CC 256
#define NN 4096
#define EPSV 1e-5f
#define L2E 1.4426950408889634f

// ---------------- device-global scratch ----------------
__device__ float  g_WqkT[CC * 64];                 // [c][o] fp32 (QK conv weights)
__device__ __half g_Wv[CC * CC];                   // [c_out][c_in] fp16
__device__ float  g_Beff[320];
__device__ __half g_xT[(size_t)BB * NN * CC];      // [b][n][c] fp16
__device__ __half g_Qt[(size_t)BB * NN * 64];      // [b][n][hi32|pad32]
__device__ __half g_Kt[(size_t)BB * NN * 64];      // [b][n][hi32|pad32]
__device__ __half g_V [(size_t)BB * CC * NN];      // [b][c][n] fp16

// ---------------- helpers ----------------
__device__ __forceinline__ uint32_t sm_u32(const void* p) {
    uint32_t a;
    asm("{ .reg .u64 t; cvta.to.shared.u64 t, %1; cvt.u32.u64 %0, t; }" : "=r"(a) : "l"(p));
    return a;
}
__device__ __forceinline__ void mma16816(float* d, const uint32_t* a, const uint32_t* b) {
    asm volatile(
        "mma.sync.aligned.m16n8k16.row.col.f32.f16.f16.f32 "
        "{%0,%1,%2,%3}, {%4,%5,%6,%7}, {%8,%9}, {%0,%1,%2,%3};"
        : "+f"(d[0]), "+f"(d[1]), "+f"(d[2]), "+f"(d[3])
        : "r"(a[0]), "r"(a[1]), "r"(a[2]), "r"(a[3]), "r"(b[0]), "r"(b[1]));
}
__device__ __forceinline__ void mma16816z(float* d, const uint32_t* a, const uint32_t* b) {
    asm volatile(
        "mma.sync.aligned.m16n8k16.row.col.f32.f16.f16.f32 "
        "{%0,%1,%2,%3}, {%4,%5,%6,%7}, {%8,%9}, {%10,%11,%12,%13};"
        : "=f"(d[0]), "=f"(d[1]), "=f"(d[2]), "=f"(d[3])
        : "r"(a[0]), "r"(a[1]), "r"(a[2]), "r"(a[3]), "r"(b[0]), "r"(b[1]),
          "f"(0.f), "f"(0.f), "f"(0.f), "f"(0.f));
}
__device__ __forceinline__ void ldsm_x4(uint32_t* r, uint32_t addr) {
    asm volatile("ldmatrix.sync.aligned.m8n8.x4.shared.b16 {%0,%1,%2,%3}, [%4];"
        : "=r"(r[0]), "=r"(r[1]), "=r"(r[2]), "=r"(r[3]) : "r"(addr));
}
__device__ __forceinline__ void ldsm_x2(uint32_t* r, uint32_t addr) {
    asm volatile("ldmatrix.sync.aligned.m8n8.x2.shared.b16 {%0,%1}, [%2];"
        : "=r"(r[0]), "=r"(r[1]) : "r"(addr));
}
__device__ __forceinline__ uint32_t tile_addr(uint32_t base, int row, int ch) {
    return base + row * 128 + (((ch) ^ (row & 7)) << 4);
}
__device__ __forceinline__ uint32_t tile_addr256(uint32_t base, int row, int ch) {
    return base + row * 256 + (((((ch) & 7) ^ (row & 7)) | ((ch) & 8)) << 4);
}
__device__ __forceinline__ void cpasync16(uint32_t dst, const void* src) {
    asm volatile("cp.async.cg.shared.global [%0], [%1], 16;" :: "r"(dst), "l"(src) : "memory");
}
__device__ __forceinline__ float ex2(float v) {
    float y; asm("ex2.approx.f32 %0, %1;" : "=f"(y) : "f"(v)); return y;
}
__device__ __forceinline__ uint32_t packh2(float lo, float hi) {
    uint32_t r; asm("cvt.rn.f16x2.f32 %0, %1, %2;" : "=r"(r) : "f"(hi), "f"(lo)); return r;
}

// ---------------- 1) fold BN into conv ----------------
__global__ void fold_kernel(
    const float* __restrict__ wq, const float* __restrict__ bq,
    const float* __restrict__ gq, const float* __restrict__ betaq,
    const float* __restrict__ mq, const float* __restrict__ vq,
    const float* __restrict__ wk, const float* __restrict__ bk,
    const float* __restrict__ gk, const float* __restrict__ betak,
    const float* __restrict__ mk, const float* __restrict__ vk,
    const float* __restrict__ wv, const float* __restrict__ bv,
    const float* __restrict__ gv, const float* __restrict__ betav,
    const float* __restrict__ mv, const float* __restrict__ vv)
{
    int o = blockIdx.x, c = threadIdx.x;
    const float *w, *bb, *g, *beta, *mean, *var;
    int oo;
    if (o < 32)      { w = wq; bb = bq; g = gq; beta = betaq; mean = mq; var = vq; oo = o; }
    else if (o < 64) { w = wk; bb = bk; g = gk; beta = betak; mean = mk; var = vk; oo = o - 32; }
    else             { w = wv; bb = bv; g = gv; beta = betav; mean = mv; var = vv; oo = o - 64; }
    float scale = g[oo] * rsqrtf(var[oo] + EPSV);
    float val = w[oo * CC + c] * scale;
    if (o < 64) g_WqkT[c * 64 + o] = val;
    else        g_Wv[(o - 64) * CC + c] = __float2half(val);
    if (c == 0) g_Beff[o] = (bb[oo] - mean[oo]) * scale + beta[oo];
}

// ---------------- 2) pack x -> x^T fp16  [b][n][c] ----------------
__global__ void packx_kernel(const float* __restrict__ x)
{
    __shared__ float s[64][65];
    const int n0 = blockIdx.x * 64, c0 = blockIdx.y * 64, b = blockIdx.z;
    const int tid = threadIdx.x;
    const float* xb = x + ((size_t)b * CC + c0) * NN + n0;
    #pragma unroll
    for (int l = 0; l < 16; l++) {
        int idx = tid + l * 256, c = idx >> 6, n = idx & 63;
        s[c][n] = xb[(size_t)c * NN + n];
    }
    __syncthreads();
    __half* dst = g_xT + ((size_t)b * NN + n0) * CC + c0;
    #pragma unroll
    for (int l = 0; l < 16; l++) {
        int idx = tid + l * 256, n = idx >> 6, c = idx & 63;
        dst[(size_t)n * CC + c] = __float2half(s[c][n]);
    }
}

// ---------------- 3) QK conv (fp32 SIMT) + transposed epilogue (hi only) ----------------
__global__ void qkconv_kernel(const float* __restrict__ x)
{
    __shared__ float As[32][64];
    __shared__ float Bs[32][64];
    __shared__ float st[64][65];

    const int n0 = blockIdx.x * 64;
    const int b  = blockIdx.y;
    const int tid = threadIdx.x;
    const int mo = (tid >> 4) * 4;
    const int nn = (tid & 15) * 4;

    float acc[4][4] = {};
    const float* xb = x + (size_t)b * CC * NN;

    for (int k0 = 0; k0 < CC; k0 += 32) {
        #pragma unroll
        for (int l = 0; l < 8; l++) {
            int idx = tid + l * 256;
            int oo = idx & 63, kk = idx >> 6;
            As[kk][oo] = g_WqkT[(size_t)(k0 + kk) * 64 + oo];
            Bs[kk][oo] = xb[(size_t)(k0 + kk) * NN + n0 + oo];
        }
        __syncthreads();
        #pragma unroll
        for (int kk = 0; kk < 32; kk++) {
            float4 av = *(const float4*)&As[kk][mo];
            float4 bv = *(const float4*)&Bs[kk][nn];
            acc[0][0] += av.x * bv.x; acc[0][1] += av.x * bv.y; acc[0][2] += av.x * bv.z; acc[0][3] += av.x * bv.w;
            acc[1][0] += av.y * bv.x; acc[1][1] += av.y * bv.y; acc[1][2] += av.y * bv.z; acc[1][3] += av.y * bv.w;
            acc[2][0] += av.z * bv.x; acc[2][1] += av.z * bv.y; acc[2][2] += av.z * bv.z; acc[2][3] += av.z * bv.w;
            acc[3][0] += av.w * bv.x; acc[3][1] += av.w * bv.y; acc[3][2] += av.w * bv.z; acc[3][3] += av.w * bv.w;
        }
        __syncthreads();
    }

    #pragma unroll
    for (int a = 0; a < 4; a++) {
        float bias = g_Beff[mo + a];
        #pragma unroll
        for (int t = 0; t < 4; t++)
            st[nn + t][mo + a] = fmaxf(acc[a][t] + bias, 0.f);
    }
    __syncthreads();

    const int n = tid >> 2, q = tid & 3;
    __align__(16) __half h8[8];
    size_t rowb = ((size_t)b * NN + n0 + n) * 64;
    #pragma unroll
    for (int e = 0; e < 8; e++)
        h8[e] = __float2half(st[n][q * 8 + e]);
    *(uint4*)&g_Qt[rowb + q * 8] = *(uint4*)h8;
    #pragma unroll
    for (int e = 0; e < 8; e++)
        h8[e] = __float2half(st[n][32 + q * 8 + e]);
    *(uint4*)&g_Kt[rowb + q * 8] = *(uint4*)h8;
}

// ---------------- 4) V conv MMA: tile 128c x 128n, K=256 in 4 chunks ----------------
__global__ void __launch_bounds__(256) vconv_kernel()
{
    __shared__ __align__(128) __half sW[128 * 64];
    __shared__ __align__(128) __half sX[128 * 64];

    const int tid = threadIdx.x, wid = tid >> 5, lane = tid & 31;
    const int wm = wid >> 2, wn = wid & 3;
    const int n0 = blockIdx.x * 128, c0 = blockIdx.y * 128, b = blockIdx.z;

    const uint32_t sw = sm_u32(sW), sx = sm_u32(sX);
    float acc[4][4][4] = {};

    for (int kc = 0; kc < 4; kc++) {
        __syncthreads();
        #pragma unroll
        for (int l = 0; l < 4; l++) {
            int idx = tid + l * 256;
            int row = idx >> 3, ch = idx & 7;
            int soff = row * 64 + ((ch ^ (row & 7)) << 3);
            *(uint4*)&sW[soff] = *(const uint4*)&g_Wv[(size_t)(c0 + row) * CC + kc * 64 + ch * 8];
            *(uint4*)&sX[soff] = *(const uint4*)&g_xT[((size_t)b * NN + n0 + row) * CC + kc * 64 + ch * 8];
        }
        __syncthreads();

        #pragma unroll
        for (int ks = 0; ks < 4; ks++) {
            uint32_t af[4][4], bf[4][2];
            #pragma unroll
            for (int fm = 0; fm < 4; fm++)
                ldsm_x4(af[fm], tile_addr(sw, wm * 64 + fm * 16 + (lane & 15), ks * 2 + (lane >> 4)));
            #pragma unroll
            for (int fn = 0; fn < 4; fn++) {
                int t = lane & 15;
                ldsm_x2(bf[fn], tile_addr(sx, wn * 32 + fn * 8 + (t & 7), ks * 2 + (t >> 3)));
            }
            #pragma unroll
            for (int fm = 0; fm < 4; fm++)
                #pragma unroll
                for (int fn = 0; fn < 4; fn++)
                    mma16816(acc[fm][fn], af[fm], bf[fn]);
        }
    }

    const int r = lane >> 2, cq = (lane & 3) * 2;
    #pragma unroll
    for (int fm = 0; fm < 4; fm++) {
        #pragma unroll
        for (int fn = 0; fn < 4; fn++) {
            int c = c0 + wm * 64 + fm * 16 + r;
            int n = n0 + wn * 32 + fn * 8 + cq;
            float b0 = g_Beff[64 + c], b1 = g_Beff[64 + c + 8];
            __half2 h0 = __floats2half2_rn(fmaxf(acc[fm][fn][0] + b0, 0.f),
                                           fmaxf(acc[fm][fn][1] + b0, 0.f));
            __half2 h1 = __floats2half2_rn(fmaxf(acc[fm][fn][2] + b1, 0.f),
                                           fmaxf(acc[fm][fn][3] + b1, 0.f));
            *(__half2*)&g_V[((size_t)b * CC + c) * NN + n]     = h0;
            *(__half2*)&g_V[((size_t)b * CC + c + 8) * NN + n] = h1;
        }
    }
}

// ---------------- 5) fused flash attention (S = qh.kh, online softmax, O=P.V^T) ----
// grid (32 i-tiles, 2 c-halves, 8 b), 256 thr. Each warp owns 16 full i-rows.
// dyn smem: Q 16KB | stage0 {K 16KB, V 32KB} | stage1 {K 16KB, V 32KB} = 114688 B
__global__ void __launch_bounds__(256, 1) flash_kernel(const float* __restrict__ x,
                                                       const float* __restrict__ gamma,
                                                       float* __restrict__ out)
{
    extern __shared__ __align__(128) unsigned char dsm[];
    const uint32_t sb = sm_u32(dsm);
    const uint32_t sQ = sb;

    const int tid = threadIdx.x, wid = tid >> 5, lane = tid & 31;
    const int i0 = blockIdx.x * 128, c0 = blockIdx.y * 128, b = blockIdx.z;

    const char* qsrc = (const char*)(g_Qt + ((size_t)b * NN + i0) * 64);
    const char* ksrc = (const char*)(g_Kt + (size_t)b * NN * 64);
    const char* vsrc = (const char*)(g_V + ((size_t)b * CC + c0) * NN);

    // Q tile: hi half only (first 64B of each 128B row)
    #pragma unroll
    for (int l = 0; l < 2; l++) {
        int idx = tid + l * 256;          // 0..511
        int row = idx >> 2, ch = idx & 3;
        cpasync16(tile_addr(sQ, row, ch), qsrc + (size_t)row * 128 + ch * 16);
    }
    asm volatile("cp.async.commit_group;" ::: "memory");

    auto issueKV = [&](int it) {
        const uint32_t kb = sb + 16384 + (it & 1) * 49152;
        const uint32_t vb = kb + 16384;
        const char* ks = ksrc + (size_t)it * 128 * 128;   // 128 rows * 128 B
        // K: hi chunks only (ch 0..3)
        #pragma unroll
        for (int l = 0; l < 2; l++) {
            int idx = tid + l * 256;      // 0..511
            int row = idx >> 2, ch = idx & 3;
            cpasync16(tile_addr(kb, row, ch), ks + (size_t)row * 128 + ch * 16);
        }
        const size_t jb = (size_t)it * 256;               // 128 j * 2 B
        #pragma unroll
        for (int l = 0; l < 8; l++) {
            int idx = tid + l * 256;
            int row = idx >> 4, ch = idx & 15;
            cpasync16(tile_addr256(vb, row, ch), vsrc + (size_t)row * (NN * 2) + jb + ch * 16);
        }
        asm volatile("cp.async.commit_group;" ::: "memory");
    };

    issueKV(0);
    asm volatile("cp.async.wait_group 1;" ::: "memory");
    __syncthreads();

    // Q hi A-frags (k = 0..31)
    uint32_t qA[2][4];
    #pragma unroll
    for (int ck = 0; ck < 2; ck++)
        ldsm_x4(qA[ck], tile_addr(sQ, wid * 16 + (lane & 15), ck * 2 + (lane >> 4)));

    float oacc[16][4] = {};
    float m0 = -1e30f, m1 = -1e30f, l0 = 0.f, l1 = 0.f;

    for (int it = 0; it < 32; it++) {
        __syncthreads();
        if (it + 1 < 32) {
            issueKV(it + 1);
            asm volatile("cp.async.wait_group 1;" ::: "memory");
        } else {
            asm volatile("cp.async.wait_group 0;" ::: "memory");
        }
        __syncthreads();

        const uint32_t kb = sb + 16384 + (it & 1) * 49152;
        const uint32_t vb = kb + 16384;

        // ---- S = qh.kh  (2 MMAs per 8-j tile) ----
        float sacc[16][4];
        #pragma unroll
        for (int n = 0; n < 16; n++) {
            uint32_t Bh[4];
            ldsm_x4(Bh, tile_addr(kb, n * 8 + (lane & 7), (lane >> 3) & 3));
            mma16816z(sacc[n], qA[0], Bh);
            mma16816 (sacc[n], qA[1], Bh + 2);
        }

        // ---- online softmax (warp-local rows) ----
        float tm0 = -1e30f, tm1 = -1e30f;
        #pragma unroll
        for (int n = 0; n < 16; n++) {
            tm0 = fmaxf(tm0, fmaxf(sacc[n][0], sacc[n][1]));
            tm1 = fmaxf(tm1, fmaxf(sacc[n][2], sacc[n][3]));
        }
        tm0 = fmaxf(tm0, __shfl_xor_sync(0xffffffffu, tm0, 1));
        tm0 = fmaxf(tm0, __shfl_xor_sync(0xffffffffu, tm0, 2));
        tm1 = fmaxf(tm1, __shfl_xor_sync(0xffffffffu, tm1, 1));
        tm1 = fmaxf(tm1, __shfl_xor_sync(0xffffffffu, tm1, 2));

        float nm0 = fmaxf(m0, tm0), nm1 = fmaxf(m1, tm1);
        float sc0 = ex2((m0 - nm0) * L2E);
        float sc1 = ex2((m1 - nm1) * L2E);
        m0 = nm0; m1 = nm1;
        const float cc0 = nm0 * L2E, cc1 = nm1 * L2E;

        float rs0 = 0.f, rs1 = 0.f;
        uint32_t pk[16][2];
        #pragma unroll
        for (int n = 0; n < 16; n++) {
            float p0 = ex2(sacc[n][0] * L2E - cc0);
            float p1 = ex2(sacc[n][1] * L2E - cc0);
            float p2 = ex2(sacc[n][2] * L2E - cc1);
            float p3 = ex2(sacc[n][3] * L2E - cc1);
            rs0 += p0 + p1; rs1 += p2 + p3;
            pk[n][0] = packh2(p0, p1);
            pk[n][1] = packh2(p2, p3);
        }
        rs0 += __shfl_xor_sync(0xffffffffu, rs0, 1);
        rs0 += __shfl_xor_sync(0xffffffffu, rs0, 2);
        rs1 += __shfl_xor_sync(0xffffffffu, rs1, 1);
        rs1 += __shfl_xor_sync(0xffffffffu, rs1, 2);
        l0 = l0 * sc0 + rs0;
        l1 = l1 * sc1 + rs1;

        // skip oacc rescale when no row max changed (common after warmup)
        if (__any_sync(0xffffffffu, (sc0 != 1.f) | (sc1 != 1.f))) {
            #pragma unroll
            for (int n = 0; n < 16; n++) {
                oacc[n][0] *= sc0; oacc[n][1] *= sc0;
                oacc[n][2] *= sc1; oacc[n][3] *= sc1;
            }
        }

        // ---- O += P . V^T ----
        #pragma unroll
        for (int ks = 0; ks < 8; ks++) {
            uint32_t A[4] = { pk[2 * ks][0], pk[2 * ks][1], pk[2 * ks + 1][0], pk[2 * ks + 1][1] };
            #pragma unroll
            for (int cp = 0; cp < 8; cp++) {
                uint32_t Bv[4];
                ldsm_x4(Bv, tile_addr256(vb, cp * 16 + (lane & 7) + ((lane >> 4) << 3),
                                         ks * 2 + ((lane >> 3) & 1)));
                mma16816(oacc[2 * cp],     A, Bv);
                mma16816(oacc[2 * cp + 1], A, Bv + 2);
            }
        }
    }

    // ---- epilogue: out = gamma * O / l + x ----
    const float g = gamma[0];
    const float il0 = g / l0, il1 = g / l1;
    const int r = lane >> 2, q = lane & 3;
    #pragma unroll
    for (int n = 0; n < 16; n++) {
        #pragma unroll
        for (int e = 0; e < 4; e++) {
            int c = c0 + n * 8 + q * 2 + (e & 1);
            int i = i0 + wid * 16 + r + (e >> 1) * 8;
            size_t off = ((size_t)b * CC + c) * NN + i;
            out[off] = oacc[n][e] * ((e < 2) ? il0 : il1) + x[off];
        }
    }
}

// ---------------- launch ----------------
extern "C" void kernel_launch(void* const* d_in, const int* in_sizes, int n_in,
                              void* d_out, int out_size)
{
    const float* x     = (const float*)d_in[0];
    const float* wq    = (const float*)d_in[1];
    const float* bq    = (const float*)d_in[2];
    const float* gq    = (const float*)d_in[3];
    const float* betaq = (const float*)d_in[4];
    const float* mq    = (const float*)d_in[5];
    const float* vq    = (const float*)d_in[6];
    const float* wk    = (const float*)d_in[7];
    const float* bk    = (const float*)d_in[8];
    const float* gk    = (const float*)d_in[9];
    const float* betak = (const float*)d_in[10];
    const float* mk    = (const float*)d_in[11];
    const float* vk    = (const float*)d_in[12];
    const float* wv    = (const float*)d_in[13];
    const float* bv    = (const float*)d_in[14];
    const float* gv    = (const float*)d_in[15];
    const float* betav = (const float*)d_in[16];
    const float* mv    = (const float*)d_in[17];
    const float* vv    = (const float*)d_in[18];
    const float* gamma = (const float*)d_in[19];
    float* out = (float*)d_out;

    cudaFuncSetAttribute(flash_kernel, cudaFuncAttributeMaxDynamicSharedMemorySize, 114688);

    fold_kernel<<<320, 256>>>(wq, bq, gq, betaq, mq, vq,
                              wk, bk, gk, betak, mk, vk,
                              wv, bv, gv, betav, mv, vv);

    packx_kernel<<<dim3(NN / 64, CC / 64, BB), 256>>>(x);

    qkconv_kernel<<<dim3(NN / 64, BB), 256>>>(x);

    vconv_kernel<<<dim3(NN / 128, CC / 128, BB), 256>>>();

    flash_kernel<<<dim3(NN / 128, 2, BB), 256, 114688>>>(x, gamma, out);
}

// round 8
// speedup vs baseline: 10.0372x; 1.0631x over previous
#include <cuda_runtime.h>
#include <cuda_fp16.h>
#include <cstdint>

#define BB 8
#define CC 256
#define NN 4096
#define EPSV 1e-5f
#define L2E 1.4426950408889634f

// ---------------- device-global scratch ----------------
__device__ float  g_WqkT[CC * 64];                 // [c][o] fp32 (QK conv weights)
__device__ __half g_Wv[CC * CC];                   // [c_out][c_in] fp16
__device__ float  g_Beff[320];
__device__ __half g_xT[(size_t)BB * NN * CC];      // [b][n][c] fp16
__device__ __half g_Qt[(size_t)BB * NN * 64];      // [b][n][hi32|pad32]
__device__ __half g_Kt[(size_t)BB * NN * 64];      // [b][n][hi32|pad32]
__device__ __half g_V [(size_t)BB * CC * NN];      // [b][c][n] fp16

// ---------------- helpers ----------------
__device__ __forceinline__ uint32_t sm_u32(const void* p) {
    uint32_t a;
    asm("{ .reg .u64 t; cvta.to.shared.u64 t, %1; cvt.u32.u64 %0, t; }" : "=r"(a) : "l"(p));
    return a;
}
__device__ __forceinline__ void mma16816(float* d, const uint32_t* a, const uint32_t* b) {
    asm volatile(
        "mma.sync.aligned.m16n8k16.row.col.f32.f16.f16.f32 "
        "{%0,%1,%2,%3}, {%4,%5,%6,%7}, {%8,%9}, {%0,%1,%2,%3};"
        : "+f"(d[0]), "+f"(d[1]), "+f"(d[2]), "+f"(d[3])
        : "r"(a[0]), "r"(a[1]), "r"(a[2]), "r"(a[3]), "r"(b[0]), "r"(b[1]));
}
__device__ __forceinline__ void mma16816z(float* d, const uint32_t* a, const uint32_t* b) {
    asm volatile(
        "mma.sync.aligned.m16n8k16.row.col.f32.f16.f16.f32 "
        "{%0,%1,%2,%3}, {%4,%5,%6,%7}, {%8,%9}, {%10,%11,%12,%13};"
        : "=f"(d[0]), "=f"(d[1]), "=f"(d[2]), "=f"(d[3])
        : "r"(a[0]), "r"(a[1]), "r"(a[2]), "r"(a[3]), "r"(b[0]), "r"(b[1]),
          "f"(0.f), "f"(0.f), "f"(0.f), "f"(0.f));
}
__device__ __forceinline__ void ldsm_x4(uint32_t* r, uint32_t addr) {
    asm volatile("ldmatrix.sync.aligned.m8n8.x4.shared.b16 {%0,%1,%2,%3}, [%4];"
        : "=r"(r[0]), "=r"(r[1]), "=r"(r[2]), "=r"(r[3]) : "r"(addr));
}
__device__ __forceinline__ void ldsm_x2(uint32_t* r, uint32_t addr) {
    asm volatile("ldmatrix.sync.aligned.m8n8.x2.shared.b16 {%0,%1}, [%2];"
        : "=r"(r[0]), "=r"(r[1]) : "r"(addr));
}
__device__ __forceinline__ uint32_t tile_addr(uint32_t base, int row, int ch) {
    return base + row * 128 + (((ch) ^ (row & 7)) << 4);
}
__device__ __forceinline__ uint32_t tile_addr256(uint32_t base, int row, int ch) {
    return base + row * 256 + (((((ch) & 7) ^ (row & 7)) | ((ch) & 8)) << 4);
}
__device__ __forceinline__ void cpasync16(uint32_t dst, const void* src) {
    asm volatile("cp.async.cg.shared.global [%0], [%1], 16;" :: "r"(dst), "l"(src) : "memory");
}
__device__ __forceinline__ float ex2(float v) {
    float y; asm("ex2.approx.f32 %0, %1;" : "=f"(y) : "f"(v)); return y;
}
__device__ __forceinline__ uint32_t packh2(float lo, float hi) {
    uint32_t r; asm("cvt.rn.f16x2.f32 %0, %1, %2;" : "=r"(r) : "f"(hi), "f"(lo)); return r;
}
__device__ __forceinline__ uint32_t ex2h2(uint32_t a) {
    uint32_t r; asm("ex2.approx.f16x2 %0, %1;" : "=r"(r) : "r"(a)); return r;
}

// ---------------- 1) fold BN into conv ----------------
__global__ void fold_kernel(
    const float* __restrict__ wq, const float* __restrict__ bq,
    const float* __restrict__ gq, const float* __restrict__ betaq,
    const float* __restrict__ mq, const float* __restrict__ vq,
    const float* __restrict__ wk, const float* __restrict__ bk,
    const float* __restrict__ gk, const float* __restrict__ betak,
    const float* __restrict__ mk, const float* __restrict__ vk,
    const float* __restrict__ wv, const float* __restrict__ bv,
    const float* __restrict__ gv, const float* __restrict__ betav,
    const float* __restrict__ mv, const float* __restrict__ vv)
{
    int o = blockIdx.x, c = threadIdx.x;
    const float *w, *bb, *g, *beta, *mean, *var;
    int oo;
    if (o < 32)      { w = wq; bb = bq; g = gq; beta = betaq; mean = mq; var = vq; oo = o; }
    else if (o < 64) { w = wk; bb = bk; g = gk; beta = betak; mean = mk; var = vk; oo = o - 32; }
    else             { w = wv; bb = bv; g = gv; beta = betav; mean = mv; var = vv; oo = o - 64; }
    float scale = g[oo] * rsqrtf(var[oo] + EPSV);
    float val = w[oo * CC + c] * scale;
    if (o < 64) g_WqkT[c * 64 + o] = val;
    else        g_Wv[(o - 64) * CC + c] = __float2half(val);
    if (c == 0) g_Beff[o] = (bb[oo] - mean[oo]) * scale + beta[oo];
}

// ---------------- 2) pack x -> x^T fp16  [b][n][c] ----------------
__global__ void packx_kernel(const float* __restrict__ x)
{
    __shared__ float s[64][65];
    const int n0 = blockIdx.x * 64, c0 = blockIdx.y * 64, b = blockIdx.z;
    const int tid = threadIdx.x;
    const float* xb = x + ((size_t)b * CC + c0) * NN + n0;
    #pragma unroll
    for (int l = 0; l < 16; l++) {
        int idx = tid + l * 256, c = idx >> 6, n = idx & 63;
        s[c][n] = xb[(size_t)c * NN + n];
    }
    __syncthreads();
    __half* dst = g_xT + ((size_t)b * NN + n0) * CC + c0;
    #pragma unroll
    for (int l = 0; l < 16; l++) {
        int idx = tid + l * 256, n = idx >> 6, c = idx & 63;
        dst[(size_t)n * CC + c] = __float2half(s[c][n]);
    }
}

// ---------------- 3) QK conv (fp32 SIMT) + transposed epilogue (hi only) ----------------
__global__ void qkconv_kernel(const float* __restrict__ x)
{
    __shared__ float As[32][64];
    __shared__ float Bs[32][64];
    __shared__ float st[64][65];

    const int n0 = blockIdx.x * 64;
    const int b  = blockIdx.y;
    const int tid = threadIdx.x;
    const int mo = (tid >> 4) * 4;
    const int nn = (tid & 15) * 4;

    float acc[4][4] = {};
    const float* xb = x + (size_t)b * CC * NN;

    for (int k0 = 0; k0 < CC; k0 += 32) {
        #pragma unroll
        for (int l = 0; l < 8; l++) {
            int idx = tid + l * 256;
            int oo = idx & 63, kk = idx >> 6;
            As[kk][oo] = g_WqkT[(size_t)(k0 + kk) * 64 + oo];
            Bs[kk][oo] = xb[(size_t)(k0 + kk) * NN + n0 + oo];
        }
        __syncthreads();
        #pragma unroll
        for (int kk = 0; kk < 32; kk++) {
            float4 av = *(const float4*)&As[kk][mo];
            float4 bv = *(const float4*)&Bs[kk][nn];
            acc[0][0] += av.x * bv.x; acc[0][1] += av.x * bv.y; acc[0][2] += av.x * bv.z; acc[0][3] += av.x * bv.w;
            acc[1][0] += av.y * bv.x; acc[1][1] += av.y * bv.y; acc[1][2] += av.y * bv.z; acc[1][3] += av.y * bv.w;
            acc[2][0] += av.z * bv.x; acc[2][1] += av.z * bv.y; acc[2][2] += av.z * bv.z; acc[2][3] += av.z * bv.w;
            acc[3][0] += av.w * bv.x; acc[3][1] += av.w * bv.y; acc[3][2] += av.w * bv.z; acc[3][3] += av.w * bv.w;
        }
        __syncthreads();
    }

    #pragma unroll
    for (int a = 0; a < 4; a++) {
        float bias = g_Beff[mo + a];
        #pragma unroll
        for (int t = 0; t < 4; t++)
            st[nn + t][mo + a] = fmaxf(acc[a][t] + bias, 0.f);
    }
    __syncthreads();

    const int n = tid >> 2, q = tid & 3;
    __align__(16) __half h8[8];
    size_t rowb = ((size_t)b * NN + n0 + n) * 64;
    #pragma unroll
    for (int e = 0; e < 8; e++)
        h8[e] = __float2half(st[n][q * 8 + e]);
    *(uint4*)&g_Qt[rowb + q * 8] = *(uint4*)h8;
    #pragma unroll
    for (int e = 0; e < 8; e++)
        h8[e] = __float2half(st[n][32 + q * 8 + e]);
    *(uint4*)&g_Kt[rowb + q * 8] = *(uint4*)h8;
}

// ---------------- 4) V conv MMA: tile 128c x 128n, K=256 in 4 chunks ----------------
__global__ void __launch_bounds__(256) vconv_kernel()
{
    __shared__ __align__(128) __half sW[128 * 64];
    __shared__ __align__(128) __half sX[128 * 64];

    const int tid = threadIdx.x, wid = tid >> 5, lane = tid & 31;
    const int wm = wid >> 2, wn = wid & 3;
    const int n0 = blockIdx.x * 128, c0 = blockIdx.y * 128, b = blockIdx.z;

    const uint32_t sw = sm_u32(sW), sx = sm_u32(sX);
    float acc[4][4][4] = {};

    for (int kc = 0; kc < 4; kc++) {
        __syncthreads();
        #pragma unroll
        for (int l = 0; l < 4; l++) {
            int idx = tid + l * 256;
            int row = idx >> 3, ch = idx & 7;
            int soff = row * 64 + ((ch ^ (row & 7)) << 3);
            *(uint4*)&sW[soff] = *(const uint4*)&g_Wv[(size_t)(c0 + row) * CC + kc * 64 + ch * 8];
            *(uint4*)&sX[soff] = *(const uint4*)&g_xT[((size_t)b * NN + n0 + row) * CC + kc * 64 + ch * 8];
        }
        __syncthreads();

        #pragma unroll
        for (int ks = 0; ks < 4; ks++) {
            uint32_t af[4][4], bf[4][2];
            #pragma unroll
            for (int fm = 0; fm < 4; fm++)
                ldsm_x4(af[fm], tile_addr(sw, wm * 64 + fm * 16 + (lane & 15), ks * 2 + (lane >> 4)));
            #pragma unroll
            for (int fn = 0; fn < 4; fn++) {
                int t = lane & 15;
                ldsm_x2(bf[fn], tile_addr(sx, wn * 32 + fn * 8 + (t & 7), ks * 2 + (t >> 3)));
            }
            #pragma unroll
            for (int fm = 0; fm < 4; fm++)
                #pragma unroll
                for (int fn = 0; fn < 4; fn++)
                    mma16816(acc[fm][fn], af[fm], bf[fn]);
        }
    }

    const int r = lane >> 2, cq = (lane & 3) * 2;
    #pragma unroll
    for (int fm = 0; fm < 4; fm++) {
        #pragma unroll
        for (int fn = 0; fn < 4; fn++) {
            int c = c0 + wm * 64 + fm * 16 + r;
            int n = n0 + wn * 32 + fn * 8 + cq;
            float b0 = g_Beff[64 + c], b1 = g_Beff[64 + c + 8];
            __half2 h0 = __floats2half2_rn(fmaxf(acc[fm][fn][0] + b0, 0.f),
                                           fmaxf(acc[fm][fn][1] + b0, 0.f));
            __half2 h1 = __floats2half2_rn(fmaxf(acc[fm][fn][2] + b1, 0.f),
                                           fmaxf(acc[fm][fn][3] + b1, 0.f));
            *(__half2*)&g_V[((size_t)b * CC + c) * NN + n]     = h0;
            *(__half2*)&g_V[((size_t)b * CC + c + 8) * NN + n] = h1;
        }
    }
}

// ---------------- 5) fused flash attention (S = qh.kh, f16x2 exp, MMA row-sum) ----
// grid (32 i-tiles, 2 c-halves, 8 b), 256 thr. Each warp owns 16 full i-rows.
// dyn smem: Q 16KB | stage0 {K 16KB, V 32KB} | stage1 {K 16KB, V 32KB} = 114688 B
__global__ void __launch_bounds__(256, 1) flash_kernel(const float* __restrict__ x,
                                                       const float* __restrict__ gamma,
                                                       float* __restrict__ out)
{
    extern __shared__ __align__(128) unsigned char dsm[];
    const uint32_t sb = sm_u32(dsm);
    const uint32_t sQ = sb;

    const int tid = threadIdx.x, wid = tid >> 5, lane = tid & 31;
    const int i0 = blockIdx.x * 128, c0 = blockIdx.y * 128, b = blockIdx.z;

    const char* qsrc = (const char*)(g_Qt + ((size_t)b * NN + i0) * 64);
    const char* ksrc = (const char*)(g_Kt + (size_t)b * NN * 64);
    const char* vsrc = (const char*)(g_V + ((size_t)b * CC + c0) * NN);

    // Q tile: hi half only (first 64B of each 128B row)
    #pragma unroll
    for (int l = 0; l < 2; l++) {
        int idx = tid + l * 256;          // 0..511
        int row = idx >> 2, ch = idx & 3;
        cpasync16(tile_addr(sQ, row, ch), qsrc + (size_t)row * 128 + ch * 16);
    }
    asm volatile("cp.async.commit_group;" ::: "memory");

    auto issueKV = [&](int it) {
        const uint32_t kb = sb + 16384 + (it & 1) * 49152;
        const uint32_t vb = kb + 16384;
        const char* ks = ksrc + (size_t)it * 128 * 128;   // 128 rows * 128 B
        // K: hi chunks only (ch 0..3)
        #pragma unroll
        for (int l = 0; l < 2; l++) {
            int idx = tid + l * 256;      // 0..511
            int row = idx >> 2, ch = idx & 3;
            cpasync16(tile_addr(kb, row, ch), ks + (size_t)row * 128 + ch * 16);
        }
        const size_t jb = (size_t)it * 256;               // 128 j * 2 B
        #pragma unroll
        for (int l = 0; l < 8; l++) {
            int idx = tid + l * 256;
            int row = idx >> 4, ch = idx & 15;
            cpasync16(tile_addr256(vb, row, ch), vsrc + (size_t)row * (NN * 2) + jb + ch * 16);
        }
        asm volatile("cp.async.commit_group;" ::: "memory");
    };

    issueKV(0);
    asm volatile("cp.async.wait_group 1;" ::: "memory");
    __syncthreads();

    // Q hi A-frags (k = 0..31)
    uint32_t qA[2][4];
    #pragma unroll
    for (int ck = 0; ck < 2; ck++)
        ldsm_x4(qA[ck], tile_addr(sQ, wid * 16 + (lane & 15), ck * 2 + (lane >> 4)));

    const uint32_t bone[2] = { 0x3C003C00u, 0x3C003C00u };   // fp16 ones B-frag
    float oacc[16][4] = {};
    float lacc[4] = {};                                      // MMA row-sum accumulator
    float m0 = -1e30f, m1 = -1e30f;

    for (int it = 0; it < 32; it++) {
        __syncthreads();
        if (it + 1 < 32) {
            issueKV(it + 1);
            asm volatile("cp.async.wait_group 1;" ::: "memory");
        } else {
            asm volatile("cp.async.wait_group 0;" ::: "memory");
        }
        __syncthreads();

        const uint32_t kb = sb + 16384 + (it & 1) * 49152;
        const uint32_t vb = kb + 16384;

        // ---- S = qh.kh  (2 MMAs per 8-j tile) ----
        float sacc[16][4];
        #pragma unroll
        for (int n = 0; n < 16; n++) {
            uint32_t Bh[4];
            ldsm_x4(Bh, tile_addr(kb, n * 8 + (lane & 7), (lane >> 3) & 3));
            mma16816z(sacc[n], qA[0], Bh);
            mma16816 (sacc[n], qA[1], Bh + 2);
        }

        // ---- online softmax (warp-local rows) ----
        float tm0 = -1e30f, tm1 = -1e30f;
        #pragma unroll
        for (int n = 0; n < 16; n++) {
            tm0 = fmaxf(tm0, fmaxf(sacc[n][0], sacc[n][1]));
            tm1 = fmaxf(tm1, fmaxf(sacc[n][2], sacc[n][3]));
        }
        tm0 = fmaxf(tm0, __shfl_xor_sync(0xffffffffu, tm0, 1));
        tm0 = fmaxf(tm0, __shfl_xor_sync(0xffffffffu, tm0, 2));
        tm1 = fmaxf(tm1, __shfl_xor_sync(0xffffffffu, tm1, 1));
        tm1 = fmaxf(tm1, __shfl_xor_sync(0xffffffffu, tm1, 2));

        float nm0 = fmaxf(m0, tm0), nm1 = fmaxf(m1, tm1);
        float sc0 = ex2((m0 - nm0) * L2E);
        float sc1 = ex2((m1 - nm1) * L2E);
        m0 = nm0; m1 = nm1;
        const float cc0 = nm0 * L2E, cc1 = nm1 * L2E;

        // P = exp2(S*L2E - cc) computed in fp16x2 (arg packed, one MUFU per pair)
        uint32_t pk[16][2];
        #pragma unroll
        for (int n = 0; n < 16; n++) {
            uint32_t a0 = packh2(sacc[n][0] * L2E - cc0, sacc[n][1] * L2E - cc0);
            uint32_t a1 = packh2(sacc[n][2] * L2E - cc1, sacc[n][3] * L2E - cc1);
            pk[n][0] = ex2h2(a0);
            pk[n][1] = ex2h2(a1);
        }

        // rescale accumulators when a row max moved
        if (__any_sync(0xffffffffu, (sc0 != 1.f) | (sc1 != 1.f))) {
            #pragma unroll
            for (int n = 0; n < 16; n++) {
                oacc[n][0] *= sc0; oacc[n][1] *= sc0;
                oacc[n][2] *= sc1; oacc[n][3] *= sc1;
            }
            lacc[0] *= sc0; lacc[1] *= sc0;
            lacc[2] *= sc1; lacc[3] *= sc1;
        }

        // ---- O += P . V^T ; l += P . 1 ----
        #pragma unroll
        for (int ks = 0; ks < 8; ks++) {
            uint32_t A[4] = { pk[2 * ks][0], pk[2 * ks][1], pk[2 * ks + 1][0], pk[2 * ks + 1][1] };
            mma16816(lacc, A, bone);
            #pragma unroll
            for (int cp = 0; cp < 8; cp++) {
                uint32_t Bv[4];
                ldsm_x4(Bv, tile_addr256(vb, cp * 16 + (lane & 7) + ((lane >> 4) << 3),
                                         ks * 2 + ((lane >> 3) & 1)));
                mma16816(oacc[2 * cp],     A, Bv);
                mma16816(oacc[2 * cp + 1], A, Bv + 2);
            }
        }
    }

    // ---- epilogue: out = gamma * O / l + x ----
    const float g = gamma[0];
    const float il0 = g / lacc[0], il1 = g / lacc[2];
    const int r = lane >> 2, q = lane & 3;
    #pragma unroll
    for (int n = 0; n < 16; n++) {
        #pragma unroll
        for (int e = 0; e < 4; e++) {
            int c = c0 + n * 8 + q * 2 + (e & 1);
            int i = i0 + wid * 16 + r + (e >> 1) * 8;
            size_t off = ((size_t)b * CC + c) * NN + i;
            out[off] = oacc[n][e] * ((e < 2) ? il0 : il1) + x[off];
        }
    }
}

// ---------------- launch ----------------
extern "C" void kernel_launch(void* const* d_in, const int* in_sizes, int n_in,
                              void* d_out, int out_size)
{
    const float* x     = (const float*)d_in[0];
    const float* wq    = (const float*)d_in[1];
    const float* bq    = (const float*)d_in[2];
    const float* gq    = (const float*)d_in[3];
    const float* betaq = (const float*)d_in[4];
    const float* mq    = (const float*)d_in[5];
    const float* vq    = (const float*)d_in[6];
    const float* wk    = (const float*)d_in[7];
    const float* bk    = (const float*)d_in[8];
    const float* gk    = (const float*)d_in[9];
    const float* betak = (const float*)d_in[10];
    const float* mk    = (const float*)d_in[11];
    const float* vk    = (const float*)d_in[12];
    const float* wv    = (const float*)d_in[13];
    const float* bv    = (const float*)d_in[14];
    const float* gv    = (const float*)d_in[15];
    const float* betav = (const float*)d_in[16];
    const float* mv    = (const float*)d_in[17];
    const float* vv    = (const float*)d_in[18];
    const float* gamma = (const float*)d_in[19];
    float* out = (float*)d_out;

    cudaFuncSetAttribute(flash_kernel, cudaFuncAttributeMaxDynamicSharedMemorySize, 114688);

    fold_kernel<<<320, 256>>>(wq, bq, gq, betaq, mq, vq,
                              wk, bk, gk, betak, mk, vk,
                              wv, bv, gv, betav, mv, vv);

    packx_kernel<<<dim3(NN / 64, CC / 64, BB), 256>>>(x);

    qkconv_kernel<<<dim3(NN / 64, BB), 256>>>(x);

    vconv_kernel<<<dim3(NN / 128, CC / 128, BB), 256>>>();

    flash_kernel<<<dim3(NN / 128, 2, BB), 256, 114688>>>(x, gamma, out);
}

// round 9
// speedup vs baseline: 10.1832x; 1.0145x over previous
#include <cuda_runtime.h>
#include <cuda_fp16.h>
#include <cstdint>

#define BB 8
#define CC 256
#define NN 4096
#define EPSV 1e-5f
#define L2E 1.4426950408889634f

// ---------------- device-global scratch ----------------
__device__ float  g_WqkT[CC * 64];                 // [c][o] fp32 (QK conv weights)
__device__ __half g_Wv[CC * CC];                   // [c_out][c_in] fp16
__device__ float  g_Beff[320];
__device__ __half g_xT[(size_t)BB * NN * CC];      // [b][n][c] fp16
__device__ __half g_Qt[(size_t)BB * NN * 64];      // [b][n][hi32|pad32]
__device__ __half g_Kt[(size_t)BB * NN * 64];      // [b][n][hi32|pad32]
__device__ __half g_V [(size_t)BB * CC * NN];      // [b][c][n] fp16

// ---------------- helpers ----------------
__device__ __forceinline__ uint32_t sm_u32(const void* p) {
    uint32_t a;
    asm("{ .reg .u64 t; cvta.to.shared.u64 t, %1; cvt.u32.u64 %0, t; }" : "=r"(a) : "l"(p));
    return a;
}
__device__ __forceinline__ void mma16816(float* d, const uint32_t* a, const uint32_t* b) {
    asm volatile(
        "mma.sync.aligned.m16n8k16.row.col.f32.f16.f16.f32 "
        "{%0,%1,%2,%3}, {%4,%5,%6,%7}, {%8,%9}, {%0,%1,%2,%3};"
        : "+f"(d[0]), "+f"(d[1]), "+f"(d[2]), "+f"(d[3])
        : "r"(a[0]), "r"(a[1]), "r"(a[2]), "r"(a[3]), "r"(b[0]), "r"(b[1]));
}
__device__ __forceinline__ void mma16816z(float* d, const uint32_t* a, const uint32_t* b) {
    asm volatile(
        "mma.sync.aligned.m16n8k16.row.col.f32.f16.f16.f32 "
        "{%0,%1,%2,%3}, {%4,%5,%6,%7}, {%8,%9}, {%10,%11,%12,%13};"
        : "=f"(d[0]), "=f"(d[1]), "=f"(d[2]), "=f"(d[3])
        : "r"(a[0]), "r"(a[1]), "r"(a[2]), "r"(a[3]), "r"(b[0]), "r"(b[1]),
          "f"(0.f), "f"(0.f), "f"(0.f), "f"(0.f));
}
__device__ __forceinline__ void ldsm_x4(uint32_t* r, uint32_t addr) {
    asm volatile("ldmatrix.sync.aligned.m8n8.x4.shared.b16 {%0,%1,%2,%3}, [%4];"
        : "=r"(r[0]), "=r"(r[1]), "=r"(r[2]), "=r"(r[3]) : "r"(addr));
}
__device__ __forceinline__ void ldsm_x2(uint32_t* r, uint32_t addr) {
    asm volatile("ldmatrix.sync.aligned.m8n8.x2.shared.b16 {%0,%1}, [%2];"
        : "=r"(r[0]), "=r"(r[1]) : "r"(addr));
}
__device__ __forceinline__ uint32_t tile_addr(uint32_t base, int row, int ch) {
    return base + row * 128 + (((ch) ^ (row & 7)) << 4);
}
__device__ __forceinline__ uint32_t tile_addr256(uint32_t base, int row, int ch) {
    return base + row * 256 + (((((ch) & 7) ^ (row & 7)) | ((ch) & 8)) << 4);
}
__device__ __forceinline__ void cpasync16(uint32_t dst, const void* src) {
    asm volatile("cp.async.cg.shared.global [%0], [%1], 16;" :: "r"(dst), "l"(src) : "memory");
}
__device__ __forceinline__ float ex2(float v) {
    float y; asm("ex2.approx.f32 %0, %1;" : "=f"(y) : "f"(v)); return y;
}
__device__ __forceinline__ uint32_t packh2(float lo, float hi) {
    uint32_t r; asm("cvt.rn.f16x2.f32 %0, %1, %2;" : "=r"(r) : "f"(hi), "f"(lo)); return r;
}
__device__ __forceinline__ uint32_t ex2h2(uint32_t a) {
    uint32_t r; asm("ex2.approx.f16x2 %0, %1;" : "=r"(r) : "r"(a)); return r;
}

// ---------------- 1) fold BN into conv ----------------
__global__ void fold_kernel(
    const float* __restrict__ wq, const float* __restrict__ bq,
    const float* __restrict__ gq, const float* __restrict__ betaq,
    const float* __restrict__ mq, const float* __restrict__ vq,
    const float* __restrict__ wk, const float* __restrict__ bk,
    const float* __restrict__ gk, const float* __restrict__ betak,
    const float* __restrict__ mk, const float* __restrict__ vk,
    const float* __restrict__ wv, const float* __restrict__ bv,
    const float* __restrict__ gv, const float* __restrict__ betav,
    const float* __restrict__ mv, const float* __restrict__ vv)
{
    int o = blockIdx.x, c = threadIdx.x;
    const float *w, *bb, *g, *beta, *mean, *var;
    int oo;
    if (o < 32)      { w = wq; bb = bq; g = gq; beta = betaq; mean = mq; var = vq; oo = o; }
    else if (o < 64) { w = wk; bb = bk; g = gk; beta = betak; mean = mk; var = vk; oo = o - 32; }
    else             { w = wv; bb = bv; g = gv; beta = betav; mean = mv; var = vv; oo = o - 64; }
    float scale = g[oo] * rsqrtf(var[oo] + EPSV);
    float val = w[oo * CC + c] * scale;
    if (o < 64) g_WqkT[c * 64 + o] = val;
    else        g_Wv[(o - 64) * CC + c] = __float2half(val);
    if (c == 0) g_Beff[o] = (bb[oo] - mean[oo]) * scale + beta[oo];
}

// ---------------- 2) fused QK conv + x^T pack (x read ONCE) ----------------
// grid (NN/64, BB), 256 thr. Per k-chunk: stage x [32c x 64n] fp32, FFMA QK conv,
// and emit the staged chunk as fp16 into g_xT.
__global__ void qkconv_kernel(const float* __restrict__ x)
{
    __shared__ float As[32][64];
    __shared__ float Bs[32][68];     // pitch 68 floats: float4-aligned rows
    __shared__ float st[64][65];

    const int n0 = blockIdx.x * 64;
    const int b  = blockIdx.y;
    const int tid = threadIdx.x;
    const int mo = (tid >> 4) * 4;
    const int nn = (tid & 15) * 4;
    const int nw = tid >> 2, cw = (tid & 3) * 8;   // xT-write mapping

    float acc[4][4] = {};
    const float* xb = x + (size_t)b * CC * NN;

    for (int k0 = 0; k0 < CC; k0 += 32) {
        #pragma unroll
        for (int l = 0; l < 8; l++) {
            int idx = tid + l * 256;
            int oo = idx & 63, kk = idx >> 6;
            As[kk][oo] = g_WqkT[(size_t)(k0 + kk) * 64 + oo];
            Bs[kk][oo] = xb[(size_t)(k0 + kk) * NN + n0 + oo];
        }
        __syncthreads();
        #pragma unroll
        for (int kk = 0; kk < 32; kk++) {
            float4 av = *(const float4*)&As[kk][mo];
            float4 bv = *(const float4*)&Bs[kk][nn];
            acc[0][0] += av.x * bv.x; acc[0][1] += av.x * bv.y; acc[0][2] += av.x * bv.z; acc[0][3] += av.x * bv.w;
            acc[1][0] += av.y * bv.x; acc[1][1] += av.y * bv.y; acc[1][2] += av.y * bv.z; acc[1][3] += av.y * bv.w;
            acc[2][0] += av.z * bv.x; acc[2][1] += av.z * bv.y; acc[2][2] += av.z * bv.z; acc[2][3] += av.z * bv.w;
            acc[3][0] += av.w * bv.x; acc[3][1] += av.w * bv.y; acc[3][2] += av.w * bv.z; acc[3][3] += av.w * bv.w;
        }
        // emit staged chunk as fp16 xT (independent of FFMA results)
        {
            __align__(16) __half hx[8];
            #pragma unroll
            for (int e = 0; e < 8; e++)
                hx[e] = __float2half(Bs[cw + e][nw]);
            *(uint4*)&g_xT[((size_t)b * NN + n0 + nw) * CC + k0 + cw] = *(uint4*)hx;
        }
        __syncthreads();
    }

    #pragma unroll
    for (int a = 0; a < 4; a++) {
        float bias = g_Beff[mo + a];
        #pragma unroll
        for (int t = 0; t < 4; t++)
            st[nn + t][mo + a] = fmaxf(acc[a][t] + bias, 0.f);
    }
    __syncthreads();

    const int n = tid >> 2, q = tid & 3;
    __align__(16) __half h8[8];
    size_t rowb = ((size_t)b * NN + n0 + n) * 64;
    #pragma unroll
    for (int e = 0; e < 8; e++)
        h8[e] = __float2half(st[n][q * 8 + e]);
    *(uint4*)&g_Qt[rowb + q * 8] = *(uint4*)h8;
    #pragma unroll
    for (int e = 0; e < 8; e++)
        h8[e] = __float2half(st[n][32 + q * 8 + e]);
    *(uint4*)&g_Kt[rowb + q * 8] = *(uint4*)h8;
}

// ---------------- 3) V conv MMA: tile 128c x 128n, K=256 in 4 chunks ----------------
__global__ void __launch_bounds__(256) vconv_kernel()
{
    __shared__ __align__(128) __half sW[128 * 64];
    __shared__ __align__(128) __half sX[128 * 64];

    const int tid = threadIdx.x, wid = tid >> 5, lane = tid & 31;
    const int wm = wid >> 2, wn = wid & 3;
    const int n0 = blockIdx.x * 128, c0 = blockIdx.y * 128, b = blockIdx.z;

    const uint32_t sw = sm_u32(sW), sx = sm_u32(sX);
    float acc[4][4][4] = {};

    for (int kc = 0; kc < 4; kc++) {
        __syncthreads();
        #pragma unroll
        for (int l = 0; l < 4; l++) {
            int idx = tid + l * 256;
            int row = idx >> 3, ch = idx & 7;
            int soff = row * 64 + ((ch ^ (row & 7)) << 3);
            *(uint4*)&sW[soff] = *(const uint4*)&g_Wv[(size_t)(c0 + row) * CC + kc * 64 + ch * 8];
            *(uint4*)&sX[soff] = *(const uint4*)&g_xT[((size_t)b * NN + n0 + row) * CC + kc * 64 + ch * 8];
        }
        __syncthreads();

        #pragma unroll
        for (int ks = 0; ks < 4; ks++) {
            uint32_t af[4][4], bf[4][2];
            #pragma unroll
            for (int fm = 0; fm < 4; fm++)
                ldsm_x4(af[fm], tile_addr(sw, wm * 64 + fm * 16 + (lane & 15), ks * 2 + (lane >> 4)));
            #pragma unroll
            for (int fn = 0; fn < 4; fn++) {
                int t = lane & 15;
                ldsm_x2(bf[fn], tile_addr(sx, wn * 32 + fn * 8 + (t & 7), ks * 2 + (t >> 3)));
            }
            #pragma unroll
            for (int fm = 0; fm < 4; fm++)
                #pragma unroll
                for (int fn = 0; fn < 4; fn++)
                    mma16816(acc[fm][fn], af[fm], bf[fn]);
        }
    }

    const int r = lane >> 2, cq = (lane & 3) * 2;
    #pragma unroll
    for (int fm = 0; fm < 4; fm++) {
        #pragma unroll
        for (int fn = 0; fn < 4; fn++) {
            int c = c0 + wm * 64 + fm * 16 + r;
            int n = n0 + wn * 32 + fn * 8 + cq;
            float b0 = g_Beff[64 + c], b1 = g_Beff[64 + c + 8];
            __half2 h0 = __floats2half2_rn(fmaxf(acc[fm][fn][0] + b0, 0.f),
                                           fmaxf(acc[fm][fn][1] + b0, 0.f));
            __half2 h1 = __floats2half2_rn(fmaxf(acc[fm][fn][2] + b1, 0.f),
                                           fmaxf(acc[fm][fn][3] + b1, 0.f));
            *(__half2*)&g_V[((size_t)b * CC + c) * NN + n]     = h0;
            *(__half2*)&g_V[((size_t)b * CC + c + 8) * NN + n] = h1;
        }
    }
}

// ---------------- 4) fused flash attention (S = qh.kh, f16x2 exp, MMA row-sum) ----
// grid (32 i-tiles, 2 c-halves, 8 b), 256 thr. Each warp owns 16 full i-rows.
// dyn smem: Q 16KB | stage0 {K 16KB, V 32KB} | stage1 {K 16KB, V 32KB} = 114688 B
__global__ void __launch_bounds__(256, 1) flash_kernel(const float* __restrict__ x,
                                                       const float* __restrict__ gamma,
                                                       float* __restrict__ out)
{
    extern __shared__ __align__(128) unsigned char dsm[];
    const uint32_t sb = sm_u32(dsm);
    const uint32_t sQ = sb;

    const int tid = threadIdx.x, wid = tid >> 5, lane = tid & 31;
    const int i0 = blockIdx.x * 128, c0 = blockIdx.y * 128, b = blockIdx.z;

    const char* qsrc = (const char*)(g_Qt + ((size_t)b * NN + i0) * 64);
    const char* ksrc = (const char*)(g_Kt + (size_t)b * NN * 64);
    const char* vsrc = (const char*)(g_V + ((size_t)b * CC + c0) * NN);

    // Q tile: hi half only (first 64B of each 128B row)
    #pragma unroll
    for (int l = 0; l < 2; l++) {
        int idx = tid + l * 256;          // 0..511
        int row = idx >> 2, ch = idx & 3;
        cpasync16(tile_addr(sQ, row, ch), qsrc + (size_t)row * 128 + ch * 16);
    }
    asm volatile("cp.async.commit_group;" ::: "memory");

    auto issueKV = [&](int it) {
        const uint32_t kb = sb + 16384 + (it & 1) * 49152;
        const uint32_t vb = kb + 16384;
        const char* ks = ksrc + (size_t)it * 128 * 128;   // 128 rows * 128 B
        // K: hi chunks only (ch 0..3)
        #pragma unroll
        for (int l = 0; l < 2; l++) {
            int idx = tid + l * 256;      // 0..511
            int row = idx >> 2, ch = idx & 3;
            cpasync16(tile_addr(kb, row, ch), ks + (size_t)row * 128 + ch * 16);
        }
        const size_t jb = (size_t)it * 256;               // 128 j * 2 B
        #pragma unroll
        for (int l = 0; l < 8; l++) {
            int idx = tid + l * 256;
            int row = idx >> 4, ch = idx & 15;
            cpasync16(tile_addr256(vb, row, ch), vsrc + (size_t)row * (NN * 2) + jb + ch * 16);
        }
        asm volatile("cp.async.commit_group;" ::: "memory");
    };

    issueKV(0);
    asm volatile("cp.async.wait_group 1;" ::: "memory");
    __syncthreads();

    // Q hi A-frags (k = 0..31)
    uint32_t qA[2][4];
    #pragma unroll
    for (int ck = 0; ck < 2; ck++)
        ldsm_x4(qA[ck], tile_addr(sQ, wid * 16 + (lane & 15), ck * 2 + (lane >> 4)));

    const uint32_t bone[2] = { 0x3C003C00u, 0x3C003C00u };   // fp16 ones B-frag
    float oacc[16][4] = {};
    float lacc[4] = {};                                      // MMA row-sum accumulator
    float m0 = -1e30f, m1 = -1e30f;

    for (int it = 0; it < 32; it++) {
        __syncthreads();
        if (it + 1 < 32) {
            issueKV(it + 1);
            asm volatile("cp.async.wait_group 1;" ::: "memory");
        } else {
            asm volatile("cp.async.wait_group 0;" ::: "memory");
        }
        __syncthreads();

        const uint32_t kb = sb + 16384 + (it & 1) * 49152;
        const uint32_t vb = kb + 16384;

        // ---- S = qh.kh  (2 MMAs per 8-j tile) ----
        float sacc[16][4];
        #pragma unroll
        for (int n = 0; n < 16; n++) {
            uint32_t Bh[4];
            ldsm_x4(Bh, tile_addr(kb, n * 8 + (lane & 7), (lane >> 3) & 3));
            mma16816z(sacc[n], qA[0], Bh);
            mma16816 (sacc[n], qA[1], Bh + 2);
        }

        // ---- online softmax (warp-local rows) ----
        float tm0 = -1e30f, tm1 = -1e30f;
        #pragma unroll
        for (int n = 0; n < 16; n++) {
            tm0 = fmaxf(tm0, fmaxf(sacc[n][0], sacc[n][1]));
            tm1 = fmaxf(tm1, fmaxf(sacc[n][2], sacc[n][3]));
        }
        tm0 = fmaxf(tm0, __shfl_xor_sync(0xffffffffu, tm0, 1));
        tm0 = fmaxf(tm0, __shfl_xor_sync(0xffffffffu, tm0, 2));
        tm1 = fmaxf(tm1, __shfl_xor_sync(0xffffffffu, tm1, 1));
        tm1 = fmaxf(tm1, __shfl_xor_sync(0xffffffffu, tm1, 2));

        float nm0 = fmaxf(m0, tm0), nm1 = fmaxf(m1, tm1);
        float sc0 = ex2((m0 - nm0) * L2E);
        float sc1 = ex2((m1 - nm1) * L2E);
        m0 = nm0; m1 = nm1;
        const float cc0 = nm0 * L2E, cc1 = nm1 * L2E;

        // P = exp2(S*L2E - cc) computed in fp16x2 (arg packed, one MUFU per pair)
        uint32_t pk[16][2];
        #pragma unroll
        for (int n = 0; n < 16; n++) {
            uint32_t a0 = packh2(sacc[n][0] * L2E - cc0, sacc[n][1] * L2E - cc0);
            uint32_t a1 = packh2(sacc[n][2] * L2E - cc1, sacc[n][3] * L2E - cc1);
            pk[n][0] = ex2h2(a0);
            pk[n][1] = ex2h2(a1);
        }

        // rescale accumulators when a row max moved
        if (__any_sync(0xffffffffu, (sc0 != 1.f) | (sc1 != 1.f))) {
            #pragma unroll
            for (int n = 0; n < 16; n++) {
                oacc[n][0] *= sc0; oacc[n][1] *= sc0;
                oacc[n][2] *= sc1; oacc[n][3] *= sc1;
            }
            lacc[0] *= sc0; lacc[1] *= sc0;
            lacc[2] *= sc1; lacc[3] *= sc1;
        }

        // ---- O += P . V^T ; l += P . 1 ----
        #pragma unroll
        for (int ks = 0; ks < 8; ks++) {
            uint32_t A[4] = { pk[2 * ks][0], pk[2 * ks][1], pk[2 * ks + 1][0], pk[2 * ks + 1][1] };
            mma16816(lacc, A, bone);
            #pragma unroll
            for (int cp = 0; cp < 8; cp++) {
                uint32_t Bv[4];
                ldsm_x4(Bv, tile_addr256(vb, cp * 16 + (lane & 7) + ((lane >> 4) << 3),
                                         ks * 2 + ((lane >> 3) & 1)));
                mma16816(oacc[2 * cp],     A, Bv);
                mma16816(oacc[2 * cp + 1], A, Bv + 2);
            }
        }
    }

    // ---- epilogue: out = gamma * O / l + x ----
    const float g = gamma[0];
    const float il0 = g / lacc[0], il1 = g / lacc[2];
    const int r = lane >> 2, q = lane & 3;
    #pragma unroll
    for (int n = 0; n < 16; n++) {
        #pragma unroll
        for (int e = 0; e < 4; e++) {
            int c = c0 + n * 8 + q * 2 + (e & 1);
            int i = i0 + wid * 16 + r + (e >> 1) * 8;
            size_t off = ((size_t)b * CC + c) * NN + i;
            out[off] = oacc[n][e] * ((e < 2) ? il0 : il1) + x[off];
        }
    }
}

// ---------------- launch ----------------
extern "C" void kernel_launch(void* const* d_in, const int* in_sizes, int n_in,
                              void* d_out, int out_size)
{
    const float* x     = (const float*)d_in[0];
    const float* wq    = (const float*)d_in[1];
    const float* bq    = (const float*)d_in[2];
    const float* gq    = (const float*)d_in[3];
    const float* betaq = (const float*)d_in[4];
    const float* mq    = (const float*)d_in[5];
    const float* vq    = (const float*)d_in[6];
    const float* wk    = (const float*)d_in[7];
    const float* bk    = (const float*)d_in[8];
    const float* gk    = (const float*)d_in[9];
    const float* betak = (const float*)d_in[10];
    const float* mk    = (const float*)d_in[11];
    const float* vk    = (const float*)d_in[12];
    const float* wv    = (const float*)d_in[13];
    const float* bv    = (const float*)d_in[14];
    const float* gv    = (const float*)d_in[15];
    const float* betav = (const float*)d_in[16];
    const float* mv    = (const float*)d_in[17];
    const float* vv    = (const float*)d_in[18];
    const float* gamma = (const float*)d_in[19];
    float* out = (float*)d_out;

    cudaFuncSetAttribute(flash_kernel, cudaFuncAttributeMaxDynamicSharedMemorySize, 114688);

    fold_kernel<<<320, 256>>>(wq, bq, gq, betaq, mq, vq,
                              wk, bk, gk, betak, mk, vk,
                              wv, bv, gv, betav, mv, vv);

    qkconv_kernel<<<dim3(NN / 64, BB), 256>>>(x);

    vconv_kernel<<<dim3(NN / 128, CC / 128, BB), 256>>>();

    flash_kernel<<<dim3(NN / 128, 2, BB), 256, 114688>>>(x, gamma, out);
}

// round 10
// speedup vs baseline: 10.3307x; 1.0145x over previous
#include <cuda_runtime.h>
#include <cuda_fp16.h>
#include <cstdint>

#define BB 8
#define CC 256
#define NN 4096
#define EPSV 1e-5f
#define L2E 1.4426950408889634f

// ---------------- device-global scratch ----------------
__device__ float  g_WqkT[CC * 64];                 // [c][o] fp32 (QK conv weights)
__device__ __half g_Wv[CC * CC];                   // [c_out][c_in] fp16
__device__ float  g_Beff[320];
__device__ __half g_xT[(size_t)BB * NN * CC];      // [b][n][c] fp16
__device__ __half g_Qt[(size_t)BB * NN * 64];      // [b][n][hi32|pad32]
__device__ __half g_Kt[(size_t)BB * NN * 64];      // [b][n][hi32|pad32]
__device__ __half g_V [(size_t)BB * CC * NN];      // [b][c][n] fp16

// ---------------- helpers ----------------
__device__ __forceinline__ uint32_t sm_u32(const void* p) {
    uint32_t a;
    asm("{ .reg .u64 t; cvta.to.shared.u64 t, %1; cvt.u32.u64 %0, t; }" : "=r"(a) : "l"(p));
    return a;
}
__device__ __forceinline__ void mma16816(float* d, const uint32_t* a, const uint32_t* b) {
    asm volatile(
        "mma.sync.aligned.m16n8k16.row.col.f32.f16.f16.f32 "
        "{%0,%1,%2,%3}, {%4,%5,%6,%7}, {%8,%9}, {%0,%1,%2,%3};"
        : "+f"(d[0]), "+f"(d[1]), "+f"(d[2]), "+f"(d[3])
        : "r"(a[0]), "r"(a[1]), "r"(a[2]), "r"(a[3]), "r"(b[0]), "r"(b[1]));
}
__device__ __forceinline__ void mma16816z(float* d, const uint32_t* a, const uint32_t* b) {
    asm volatile(
        "mma.sync.aligned.m16n8k16.row.col.f32.f16.f16.f32 "
        "{%0,%1,%2,%3}, {%4,%5,%6,%7}, {%8,%9}, {%10,%11,%12,%13};"
        : "=f"(d[0]), "=f"(d[1]), "=f"(d[2]), "=f"(d[3])
        : "r"(a[0]), "r"(a[1]), "r"(a[2]), "r"(a[3]), "r"(b[0]), "r"(b[1]),
          "f"(0.f), "f"(0.f), "f"(0.f), "f"(0.f));
}
__device__ __forceinline__ void ldsm_x4(uint32_t* r, uint32_t addr) {
    asm volatile("ldmatrix.sync.aligned.m8n8.x4.shared.b16 {%0,%1,%2,%3}, [%4];"
        : "=r"(r[0]), "=r"(r[1]), "=r"(r[2]), "=r"(r[3]) : "r"(addr));
}
__device__ __forceinline__ void ldsm_x2(uint32_t* r, uint32_t addr) {
    asm volatile("ldmatrix.sync.aligned.m8n8.x2.shared.b16 {%0,%1}, [%2];"
        : "=r"(r[0]), "=r"(r[1]) : "r"(addr));
}
__device__ __forceinline__ uint32_t tile_addr(uint32_t base, int row, int ch) {
    return base + row * 128 + (((ch) ^ (row & 7)) << 4);
}
__device__ __forceinline__ uint32_t tile_addr256(uint32_t base, int row, int ch) {
    return base + row * 256 + (((((ch) & 7) ^ (row & 7)) | ((ch) & 8)) << 4);
}
__device__ __forceinline__ void cpasync16(uint32_t dst, const void* src) {
    asm volatile("cp.async.cg.shared.global [%0], [%1], 16;" :: "r"(dst), "l"(src) : "memory");
}
__device__ __forceinline__ float ex2(float v) {
    float y; asm("ex2.approx.f32 %0, %1;" : "=f"(y) : "f"(v)); return y;
}
__device__ __forceinline__ uint32_t packh2(float lo, float hi) {
    uint32_t r; asm("cvt.rn.f16x2.f32 %0, %1, %2;" : "=r"(r) : "f"(hi), "f"(lo)); return r;
}
__device__ __forceinline__ uint32_t ex2h2(uint32_t a) {
    uint32_t r; asm("ex2.approx.f16x2 %0, %1;" : "=r"(r) : "r"(a)); return r;
}

// ---------------- 1) fold BN into conv ----------------
__global__ void fold_kernel(
    const float* __restrict__ wq, const float* __restrict__ bq,
    const float* __restrict__ gq, const float* __restrict__ betaq,
    const float* __restrict__ mq, const float* __restrict__ vq,
    const float* __restrict__ wk, const float* __restrict__ bk,
    const float* __restrict__ gk, const float* __restrict__ betak,
    const float* __restrict__ mk, const float* __restrict__ vk,
    const float* __restrict__ wv, const float* __restrict__ bv,
    const float* __restrict__ gv, const float* __restrict__ betav,
    const float* __restrict__ mv, const float* __restrict__ vv)
{
    int o = blockIdx.x, c = threadIdx.x;
    const float *w, *bb, *g, *beta, *mean, *var;
    int oo;
    if (o < 32)      { w = wq; bb = bq; g = gq; beta = betaq; mean = mq; var = vq; oo = o; }
    else if (o < 64) { w = wk; bb = bk; g = gk; beta = betak; mean = mk; var = vk; oo = o - 32; }
    else             { w = wv; bb = bv; g = gv; beta = betav; mean = mv; var = vv; oo = o - 64; }
    float scale = g[oo] * rsqrtf(var[oo] + EPSV);
    float val = w[oo * CC + c] * scale;
    if (o < 64) g_WqkT[c * 64 + o] = val;
    else        g_Wv[(o - 64) * CC + c] = __float2half(val);
    if (c == 0) g_Beff[o] = (bb[oo] - mean[oo]) * scale + beta[oo];
}

// ---------------- 2) fused QK conv + x^T pack (x read ONCE) ----------------
__global__ void qkconv_kernel(const float* __restrict__ x)
{
    __shared__ float As[32][64];
    __shared__ float Bs[32][68];
    __shared__ float st[64][65];

    const int n0 = blockIdx.x * 64;
    const int b  = blockIdx.y;
    const int tid = threadIdx.x;
    const int mo = (tid >> 4) * 4;
    const int nn = (tid & 15) * 4;
    const int nw = tid >> 2, cw = (tid & 3) * 8;

    float acc[4][4] = {};
    const float* xb = x + (size_t)b * CC * NN;

    for (int k0 = 0; k0 < CC; k0 += 32) {
        #pragma unroll
        for (int l = 0; l < 8; l++) {
            int idx = tid + l * 256;
            int oo = idx & 63, kk = idx >> 6;
            As[kk][oo] = g_WqkT[(size_t)(k0 + kk) * 64 + oo];
            Bs[kk][oo] = xb[(size_t)(k0 + kk) * NN + n0 + oo];
        }
        __syncthreads();
        #pragma unroll
        for (int kk = 0; kk < 32; kk++) {
            float4 av = *(const float4*)&As[kk][mo];
            float4 bv = *(const float4*)&Bs[kk][nn];
            acc[0][0] += av.x * bv.x; acc[0][1] += av.x * bv.y; acc[0][2] += av.x * bv.z; acc[0][3] += av.x * bv.w;
            acc[1][0] += av.y * bv.x; acc[1][1] += av.y * bv.y; acc[1][2] += av.y * bv.z; acc[1][3] += av.y * bv.w;
            acc[2][0] += av.z * bv.x; acc[2][1] += av.z * bv.y; acc[2][2] += av.z * bv.z; acc[2][3] += av.z * bv.w;
            acc[3][0] += av.w * bv.x; acc[3][1] += av.w * bv.y; acc[3][2] += av.w * bv.z; acc[3][3] += av.w * bv.w;
        }
        {
            __align__(16) __half hx[8];
            #pragma unroll
            for (int e = 0; e < 8; e++)
                hx[e] = __float2half(Bs[cw + e][nw]);
            *(uint4*)&g_xT[((size_t)b * NN + n0 + nw) * CC + k0 + cw] = *(uint4*)hx;
        }
        __syncthreads();
    }

    #pragma unroll
    for (int a = 0; a < 4; a++) {
        float bias = g_Beff[mo + a];
        #pragma unroll
        for (int t = 0; t < 4; t++)
            st[nn + t][mo + a] = fmaxf(acc[a][t] + bias, 0.f);
    }
    __syncthreads();

    const int n = tid >> 2, q = tid & 3;
    __align__(16) __half h8[8];
    size_t rowb = ((size_t)b * NN + n0 + n) * 64;
    #pragma unroll
    for (int e = 0; e < 8; e++)
        h8[e] = __float2half(st[n][q * 8 + e]);
    *(uint4*)&g_Qt[rowb + q * 8] = *(uint4*)h8;
    #pragma unroll
    for (int e = 0; e < 8; e++)
        h8[e] = __float2half(st[n][32 + q * 8 + e]);
    *(uint4*)&g_Kt[rowb + q * 8] = *(uint4*)h8;
}

// ---------------- 3) V conv MMA: tile 128c x 128n, K=256 in 4 chunks ----------------
__global__ void __launch_bounds__(256) vconv_kernel()
{
    __shared__ __align__(128) __half sW[128 * 64];
    __shared__ __align__(128) __half sX[128 * 64];

    const int tid = threadIdx.x, wid = tid >> 5, lane = tid & 31;
    const int wm = wid >> 2, wn = wid & 3;
    const int n0 = blockIdx.x * 128, c0 = blockIdx.y * 128, b = blockIdx.z;

    const uint32_t sw = sm_u32(sW), sx = sm_u32(sX);
    float acc[4][4][4] = {};

    for (int kc = 0; kc < 4; kc++) {
        __syncthreads();
        #pragma unroll
        for (int l = 0; l < 4; l++) {
            int idx = tid + l * 256;
            int row = idx >> 3, ch = idx & 7;
            int soff = row * 64 + ((ch ^ (row & 7)) << 3);
            *(uint4*)&sW[soff] = *(const uint4*)&g_Wv[(size_t)(c0 + row) * CC + kc * 64 + ch * 8];
            *(uint4*)&sX[soff] = *(const uint4*)&g_xT[((size_t)b * NN + n0 + row) * CC + kc * 64 + ch * 8];
        }
        __syncthreads();

        #pragma unroll
        for (int ks = 0; ks < 4; ks++) {
            uint32_t af[4][4], bf[4][2];
            #pragma unroll
            for (int fm = 0; fm < 4; fm++)
                ldsm_x4(af[fm], tile_addr(sw, wm * 64 + fm * 16 + (lane & 15), ks * 2 + (lane >> 4)));
            #pragma unroll
            for (int fn = 0; fn < 4; fn++) {
                int t = lane & 15;
                ldsm_x2(bf[fn], tile_addr(sx, wn * 32 + fn * 8 + (t & 7), ks * 2 + (t >> 3)));
            }
            #pragma unroll
            for (int fm = 0; fm < 4; fm++)
                #pragma unroll
                for (int fn = 0; fn < 4; fn++)
                    mma16816(acc[fm][fn], af[fm], bf[fn]);
        }
    }

    const int r = lane >> 2, cq = (lane & 3) * 2;
    #pragma unroll
    for (int fm = 0; fm < 4; fm++) {
        #pragma unroll
        for (int fn = 0; fn < 4; fn++) {
            int c = c0 + wm * 64 + fm * 16 + r;
            int n = n0 + wn * 32 + fn * 8 + cq;
            float b0 = g_Beff[64 + c], b1 = g_Beff[64 + c + 8];
            __half2 h0 = __floats2half2_rn(fmaxf(acc[fm][fn][0] + b0, 0.f),
                                           fmaxf(acc[fm][fn][1] + b0, 0.f));
            __half2 h1 = __floats2half2_rn(fmaxf(acc[fm][fn][2] + b1, 0.f),
                                           fmaxf(acc[fm][fn][3] + b1, 0.f));
            *(__half2*)&g_V[((size_t)b * CC + c) * NN + n]     = h0;
            *(__half2*)&g_V[((size_t)b * CC + c + 8) * NN + n] = h1;
        }
    }
}

// ---------------- 4) flash attention, PV pipelined one iteration behind ----------------
// grid (32 i-tiles, 2 c-halves, 8 b), 256 thr. Body order per it:
//   wait+sync -> issue loads(it+1) -> rescale -> PV(it-1) -> S(it) -> softmax(it)
// smem: Q 16KB | K 2x16KB | V 3x32KB = 147456 B
__global__ void __launch_bounds__(256, 1) flash_kernel(const float* __restrict__ x,
                                                       const float* __restrict__ gamma,
                                                       float* __restrict__ out)
{
    extern __shared__ __align__(128) unsigned char dsm[];
    const uint32_t sb  = sm_u32(dsm);
    const uint32_t sQ  = sb;
    const uint32_t sK0 = sb + 16384;
    const uint32_t sV0 = sb + 49152;

    const int tid = threadIdx.x, wid = tid >> 5, lane = tid & 31;
    const int i0 = blockIdx.x * 128, c0 = blockIdx.y * 128, b = blockIdx.z;

    const char* qsrc = (const char*)(g_Qt + ((size_t)b * NN + i0) * 64);
    const char* ksrc = (const char*)(g_Kt + (size_t)b * NN * 64);
    const char* vsrc = (const char*)(g_V + ((size_t)b * CC + c0) * NN);

    auto issueK = [&](int it) {
        const uint32_t kb = sK0 + (it & 1) * 16384;
        const char* ks = ksrc + (size_t)it * 128 * 128;
        #pragma unroll
        for (int l = 0; l < 2; l++) {
            int idx = tid + l * 256;
            int row = idx >> 2, ch = idx & 3;
            cpasync16(tile_addr(kb, row, ch), ks + (size_t)row * 128 + ch * 16);
        }
    };
    auto issueV = [&](int it) {
        const uint32_t vb = sV0 + (it % 3) * 32768;
        const size_t jb = (size_t)it * 256;
        #pragma unroll
        for (int l = 0; l < 8; l++) {
            int idx = tid + l * 256;
            int row = idx >> 4, ch = idx & 15;
            cpasync16(tile_addr256(vb, row, ch), vsrc + (size_t)row * (NN * 2) + jb + ch * 16);
        }
    };

    // prologue: Q + stage 0
    #pragma unroll
    for (int l = 0; l < 2; l++) {
        int idx = tid + l * 256;
        int row = idx >> 2, ch = idx & 3;
        cpasync16(tile_addr(sQ, row, ch), qsrc + (size_t)row * 128 + ch * 16);
    }
    issueK(0); issueV(0);
    asm volatile("cp.async.commit_group;" ::: "memory");

    uint32_t qA[2][4];
    const uint32_t bone[2] = { 0x3C003C00u, 0x3C003C00u };
    float oacc[16][4] = {};
    float lacc[4] = {};
    float m0 = -1e30f, m1 = -1e30f;
    float sc0p = 1.f, sc1p = 1.f;       // sc from previous softmax
    uint32_t pkp[16][2];                // pk from previous softmax

    auto doRescale = [&]() {
        if (__any_sync(0xffffffffu, (sc0p != 1.f) | (sc1p != 1.f))) {
            #pragma unroll
            for (int n = 0; n < 16; n++) {
                oacc[n][0] *= sc0p; oacc[n][1] *= sc0p;
                oacc[n][2] *= sc1p; oacc[n][3] *= sc1p;
            }
            lacc[0] *= sc0p; lacc[1] *= sc0p;
            lacc[2] *= sc1p; lacc[3] *= sc1p;
        }
    };
    auto doPV = [&](uint32_t vb) {
        #pragma unroll
        for (int ks = 0; ks < 8; ks++) {
            uint32_t A[4] = { pkp[2 * ks][0], pkp[2 * ks][1], pkp[2 * ks + 1][0], pkp[2 * ks + 1][1] };
            mma16816(lacc, A, bone);
            #pragma unroll
            for (int cp = 0; cp < 8; cp++) {
                uint32_t Bv[4];
                ldsm_x4(Bv, tile_addr256(vb, cp * 16 + (lane & 7) + ((lane >> 4) << 3),
                                         ks * 2 + ((lane >> 3) & 1)));
                mma16816(oacc[2 * cp],     A, Bv);
                mma16816(oacc[2 * cp + 1], A, Bv + 2);
            }
        }
    };

    for (int it = 0; it < 32; it++) {
        asm volatile("cp.async.wait_group 0;" ::: "memory");
        __syncthreads();

        if (it == 0) {
            #pragma unroll
            for (int ck = 0; ck < 2; ck++)
                ldsm_x4(qA[ck], tile_addr(sQ, wid * 16 + (lane & 15), ck * 2 + (lane >> 4)));
        }

        // prefetch next stage (writes touch buffers nobody reads this body)
        if (it + 1 < 32) {
            issueK(it + 1); issueV(it + 1);
            asm volatile("cp.async.commit_group;" ::: "memory");
        }

        // PV of previous iteration (tensor work up front)
        if (it > 0) {
            doRescale();
            doPV(sV0 + ((it - 1) % 3) * 32768);
        }

        // ---- S = qh.kh for current iteration ----
        const uint32_t kb = sK0 + (it & 1) * 16384;
        float sacc[16][4];
        #pragma unroll
        for (int n = 0; n < 16; n++) {
            uint32_t Bh[4];
            ldsm_x4(Bh, tile_addr(kb, n * 8 + (lane & 7), (lane >> 3) & 3));
            mma16816z(sacc[n], qA[0], Bh);
            mma16816 (sacc[n], qA[1], Bh + 2);
        }

        // ---- online softmax ----
        float tm0 = -1e30f, tm1 = -1e30f;
        #pragma unroll
        for (int n = 0; n < 16; n++) {
            tm0 = fmaxf(tm0, fmaxf(sacc[n][0], sacc[n][1]));
            tm1 = fmaxf(tm1, fmaxf(sacc[n][2], sacc[n][3]));
        }
        tm0 = fmaxf(tm0, __shfl_xor_sync(0xffffffffu, tm0, 1));
        tm0 = fmaxf(tm0, __shfl_xor_sync(0xffffffffu, tm0, 2));
        tm1 = fmaxf(tm1, __shfl_xor_sync(0xffffffffu, tm1, 1));
        tm1 = fmaxf(tm1, __shfl_xor_sync(0xffffffffu, tm1, 2));

        float nm0 = fmaxf(m0, tm0), nm1 = fmaxf(m1, tm1);
        sc0p = ex2((m0 - nm0) * L2E);
        sc1p = ex2((m1 - nm1) * L2E);
        m0 = nm0; m1 = nm1;
        const float cc0 = nm0 * L2E, cc1 = nm1 * L2E;

        #pragma unroll
        for (int n = 0; n < 16; n++) {
            uint32_t a0 = packh2(sacc[n][0] * L2E - cc0, sacc[n][1] * L2E - cc0);
            uint32_t a1 = packh2(sacc[n][2] * L2E - cc1, sacc[n][3] * L2E - cc1);
            pkp[n][0] = ex2h2(a0);
            pkp[n][1] = ex2h2(a1);
        }
    }

    // drain: PV(31)
    doRescale();
    doPV(sV0 + (31 % 3) * 32768);

    // ---- epilogue: out = gamma * O / l + x ----
    const float g = gamma[0];
    const float il0 = g / lacc[0], il1 = g / lacc[2];
    const int r = lane >> 2, q = lane & 3;
    #pragma unroll
    for (int n = 0; n < 16; n++) {
        #pragma unroll
        for (int e = 0; e < 4; e++) {
            int c = c0 + n * 8 + q * 2 + (e & 1);
            int i = i0 + wid * 16 + r + (e >> 1) * 8;
            size_t off = ((size_t)b * CC + c) * NN + i;
            out[off] = oacc[n][e] * ((e < 2) ? il0 : il1) + x[off];
        }
    }
}

// ---------------- launch ----------------
extern "C" void kernel_launch(void* const* d_in, const int* in_sizes, int n_in,
                              void* d_out, int out_size)
{
    const float* x     = (const float*)d_in[0];
    const float* wq    = (const float*)d_in[1];
    const float* bq    = (const float*)d_in[2];
    const float* gq    = (const float*)d_in[3];
    const float* betaq = (const float*)d_in[4];
    const float* mq    = (const float*)d_in[5];
    const float* vq    = (const float*)d_in[6];
    const float* wk    = (const float*)d_in[7];
    const float* bk    = (const float*)d_in[8];
    const float* gk    = (const float*)d_in[9];
    const float* betak = (const float*)d_in[10];
    const float* mk    = (const float*)d_in[11];
    const float* vk    = (const float*)d_in[12];
    const float* wv    = (const float*)d_in[13];
    const float* bv    = (const float*)d_in[14];
    const float* gv    = (const float*)d_in[15];
    const float* betav = (const float*)d_in[16];
    const float* mv    = (const float*)d_in[17];
    const float* vv    = (const float*)d_in[18];
    const float* gamma = (const float*)d_in[19];
    float* out = (float*)d_out;

    cudaFuncSetAttribute(flash_kernel, cudaFuncAttributeMaxDynamicSharedMemorySize, 147456);

    fold_kernel<<<320, 256>>>(wq, bq, gq, betaq, mq, vq,
                              wk, bk, gk, betak, mk, vk,
                              wv, bv, gv, betav, mv, vv);

    qkconv_kernel<<<dim3(NN / 64, BB), 256>>>(x);

    vconv_kernel<<<dim3(NN / 128, CC / 128, BB), 256>>>();

    flash_kernel<<<dim3(NN / 128, 2, BB), 256, 147456>>>(x, gamma, out);
}

// round 12
// speedup vs baseline: 11.2551x; 1.0895x over previous
#include <cuda_runtime.h>
#include <cuda_fp16.h>
#include <cstdint>

#define BB 8
#define CC 256
#define NN 4096
#define EPSV 1e-5f
#define L2E 1.4426950408889634f

// ---------------- device-global scratch ----------------
__device__ float  g_WqkT[CC * 64];                 // [c][o] fp32 (QK conv weights)
__device__ __half g_Wv[CC * CC];                   // [c_out][c_in] fp16
__device__ float  g_Beff[320];
__device__ __half g_xT[(size_t)BB * NN * CC];      // [b][n][c] fp16
__device__ __half g_Qt[(size_t)BB * NN * 64];      // [b][n][hi32|pad32]
__device__ __half g_Kt[(size_t)BB * NN * 64];      // [b][n][hi32|pad32]
__device__ __half g_V [(size_t)BB * CC * NN];      // [b][c][n] fp16
__device__ float  g_Qn[(size_t)BB * NN];           // |q_i| per row
__device__ unsigned g_Kmax[BB];                    // max_j |k_j| per batch (uint-ordered)

// ---------------- helpers ----------------
__device__ __forceinline__ uint32_t sm_u32(const void* p) {
    uint32_t a;
    asm("{ .reg .u64 t; cvta.to.shared.u64 t, %1; cvt.u32.u64 %0, t; }" : "=r"(a) : "l"(p));
    return a;
}
__device__ __forceinline__ void mma16816(float* d, const uint32_t* a, const uint32_t* b) {
    asm volatile(
        "mma.sync.aligned.m16n8k16.row.col.f32.f16.f16.f32 "
        "{%0,%1,%2,%3}, {%4,%5,%6,%7}, {%8,%9}, {%0,%1,%2,%3};"
        : "+f"(d[0]), "+f"(d[1]), "+f"(d[2]), "+f"(d[3])
        : "r"(a[0]), "r"(a[1]), "r"(a[2]), "r"(a[3]), "r"(b[0]), "r"(b[1]));
}
__device__ __forceinline__ void mma16816z(float* d, const uint32_t* a, const uint32_t* b) {
    asm volatile(
        "mma.sync.aligned.m16n8k16.row.col.f32.f16.f16.f32 "
        "{%0,%1,%2,%3}, {%4,%5,%6,%7}, {%8,%9}, {%10,%11,%12,%13};"
        : "=f"(d[0]), "=f"(d[1]), "=f"(d[2]), "=f"(d[3])
        : "r"(a[0]), "r"(a[1]), "r"(a[2]), "r"(a[3]), "r"(b[0]), "r"(b[1]),
          "f"(0.f), "f"(0.f), "f"(0.f), "f"(0.f));
}
__device__ __forceinline__ void ldsm_x4(uint32_t* r, uint32_t addr) {
    asm volatile("ldmatrix.sync.aligned.m8n8.x4.shared.b16 {%0,%1,%2,%3}, [%4];"
        : "=r"(r[0]), "=r"(r[1]), "=r"(r[2]), "=r"(r[3]) : "r"(addr));
}
__device__ __forceinline__ void ldsm_x2(uint32_t* r, uint32_t addr) {
    asm volatile("ldmatrix.sync.aligned.m8n8.x2.shared.b16 {%0,%1}, [%2];"
        : "=r"(r[0]), "=r"(r[1]) : "r"(addr));
}
__device__ __forceinline__ uint32_t tile_addr(uint32_t base, int row, int ch) {
    return base + row * 128 + (((ch) ^ (row & 7)) << 4);
}
__device__ __forceinline__ uint32_t tile_addr256(uint32_t base, int row, int ch) {
    return base + row * 256 + (((((ch) & 7) ^ (row & 7)) | ((ch) & 8)) << 4);
}
__device__ __forceinline__ void cpasync16(uint32_t dst, const void* src) {
    asm volatile("cp.async.cg.shared.global [%0], [%1], 16;" :: "r"(dst), "l"(src) : "memory");
}
__device__ __forceinline__ uint32_t packh2(float lo, float hi) {
    uint32_t r; asm("cvt.rn.f16x2.f32 %0, %1, %2;" : "=r"(r) : "f"(hi), "f"(lo)); return r;
}
__device__ __forceinline__ uint32_t ex2h2(uint32_t a) {
    uint32_t r; asm("ex2.approx.f16x2 %0, %1;" : "=r"(r) : "r"(a)); return r;
}

// ---------------- 1) fold BN into conv ----------------
__global__ void fold_kernel(
    const float* __restrict__ wq, const float* __restrict__ bq,
    const float* __restrict__ gq, const float* __restrict__ betaq,
    const float* __restrict__ mq, const float* __restrict__ vq,
    const float* __restrict__ wk, const float* __restrict__ bk,
    const float* __restrict__ gk, const float* __restrict__ betak,
    const float* __restrict__ mk, const float* __restrict__ vk,
    const float* __restrict__ wv, const float* __restrict__ bv,
    const float* __restrict__ gv, const float* __restrict__ betav,
    const float* __restrict__ mv, const float* __restrict__ vv)
{
    int o = blockIdx.x, c = threadIdx.x;
    if (o == 0 && c < BB) g_Kmax[c] = 0u;
    const float *w, *bb, *g, *beta, *mean, *var;
    int oo;
    if (o < 32)      { w = wq; bb = bq; g = gq; beta = betaq; mean = mq; var = vq; oo = o; }
    else if (o < 64) { w = wk; bb = bk; g = gk; beta = betak; mean = mk; var = vk; oo = o - 32; }
    else             { w = wv; bb = bv; g = gv; beta = betav; mean = mv; var = vv; oo = o - 64; }
    float scale = g[oo] * rsqrtf(var[oo] + EPSV);
    float val = w[oo * CC + c] * scale;
    if (o < 64) g_WqkT[c * 64 + o] = val;
    else        g_Wv[(o - 64) * CC + c] = __float2half(val);
    if (c == 0) g_Beff[o] = (bb[oo] - mean[oo]) * scale + beta[oo];
}

// ---------------- 2) fused QK conv + x^T pack + row norms ----------------
__global__ void qkconv_kernel(const float* __restrict__ x)
{
    __shared__ float As[32][64];
    __shared__ float Bs[32][68];
    __shared__ float st[64][65];

    const int n0 = blockIdx.x * 64;
    const int b  = blockIdx.y;
    const int tid = threadIdx.x;
    const int mo = (tid >> 4) * 4;
    const int nn = (tid & 15) * 4;
    const int nw = tid >> 2, cw = (tid & 3) * 8;

    float acc[4][4] = {};
    const float* xb = x + (size_t)b * CC * NN;

    for (int k0 = 0; k0 < CC; k0 += 32) {
        #pragma unroll
        for (int l = 0; l < 8; l++) {
            int idx = tid + l * 256;
            int oo = idx & 63, kk = idx >> 6;
            As[kk][oo] = g_WqkT[(size_t)(k0 + kk) * 64 + oo];
            Bs[kk][oo] = xb[(size_t)(k0 + kk) * NN + n0 + oo];
        }
        __syncthreads();
        #pragma unroll
        for (int kk = 0; kk < 32; kk++) {
            float4 av = *(const float4*)&As[kk][mo];
            float4 bv = *(const float4*)&Bs[kk][nn];
            acc[0][0] += av.x * bv.x; acc[0][1] += av.x * bv.y; acc[0][2] += av.x * bv.z; acc[0][3] += av.x * bv.w;
            acc[1][0] += av.y * bv.x; acc[1][1] += av.y * bv.y; acc[1][2] += av.y * bv.z; acc[1][3] += av.y * bv.w;
            acc[2][0] += av.z * bv.x; acc[2][1] += av.z * bv.y; acc[2][2] += av.z * bv.z; acc[2][3] += av.z * bv.w;
            acc[3][0] += av.w * bv.x; acc[3][1] += av.w * bv.y; acc[3][2] += av.w * bv.z; acc[3][3] += av.w * bv.w;
        }
        {
            __align__(16) __half hx[8];
            #pragma unroll
            for (int e = 0; e < 8; e++)
                hx[e] = __float2half(Bs[cw + e][nw]);
            *(uint4*)&g_xT[((size_t)b * NN + n0 + nw) * CC + k0 + cw] = *(uint4*)hx;
        }
        __syncthreads();
    }

    #pragma unroll
    for (int a = 0; a < 4; a++) {
        float bias = g_Beff[mo + a];
        #pragma unroll
        for (int t = 0; t < 4; t++)
            st[nn + t][mo + a] = fmaxf(acc[a][t] + bias, 0.f);
    }
    __syncthreads();

    const int n = tid >> 2, q = tid & 3;
    __align__(16) __half h8[8];
    size_t rowb = ((size_t)b * NN + n0 + n) * 64;
    float sq = 0.f, sk = 0.f;
    #pragma unroll
    for (int e = 0; e < 8; e++) {
        float v = st[n][q * 8 + e];
        h8[e] = __float2half(v);
        sq += v * v;
    }
    *(uint4*)&g_Qt[rowb + q * 8] = *(uint4*)h8;
    #pragma unroll
    for (int e = 0; e < 8; e++) {
        float v = st[n][32 + q * 8 + e];
        h8[e] = __float2half(v);
        sk += v * v;
    }
    *(uint4*)&g_Kt[rowb + q * 8] = *(uint4*)h8;

    sq += __shfl_xor_sync(0xffffffffu, sq, 1);
    sq += __shfl_xor_sync(0xffffffffu, sq, 2);
    sk += __shfl_xor_sync(0xffffffffu, sk, 1);
    sk += __shfl_xor_sync(0xffffffffu, sk, 2);
    if (q == 0) {
        g_Qn[(size_t)b * NN + n0 + n] = sqrtf(sq);
        atomicMax(&g_Kmax[b], __float_as_uint(sqrtf(sk)));
    }
}

// ---------------- 3) V conv MMA: tile 128c x 128n, K=256 in 4 chunks ----------------
__global__ void __launch_bounds__(256) vconv_kernel()
{
    __shared__ __align__(128) __half sW[128 * 64];
    __shared__ __align__(128) __half sX[128 * 64];

    const int tid = threadIdx.x, wid = tid >> 5, lane = tid & 31;
    const int wm = wid >> 2, wn = wid & 3;
    const int n0 = blockIdx.x * 128, c0 = blockIdx.y * 128, b = blockIdx.z;

    const uint32_t sw = sm_u32(sW), sx = sm_u32(sX);
    float acc[4][4][4] = {};

    for (int kc = 0; kc < 4; kc++) {
        __syncthreads();
        #pragma unroll
        for (int l = 0; l < 4; l++) {
            int idx = tid + l * 256;
            int row = idx >> 3, ch = idx & 7;
            int soff = row * 64 + ((ch ^ (row & 7)) << 3);
            *(uint4*)&sW[soff] = *(const uint4*)&g_Wv[(size_t)(c0 + row) * CC + kc * 64 + ch * 8];
            *(uint4*)&sX[soff] = *(const uint4*)&g_xT[((size_t)b * NN + n0 + row) * CC + kc * 64 + ch * 8];
        }
        __syncthreads();

        #pragma unroll
        for (int ks = 0; ks < 4; ks++) {
            uint32_t af[4][4], bf[4][2];
            #pragma unroll
            for (int fm = 0; fm < 4; fm++)
                ldsm_x4(af[fm], tile_addr(sw, wm * 64 + fm * 16 + (lane & 15), ks * 2 + (lane >> 4)));
            #pragma unroll
            for (int fn = 0; fn < 4; fn++) {
                int t = lane & 15;
                ldsm_x2(bf[fn], tile_addr(sx, wn * 32 + fn * 8 + (t & 7), ks * 2 + (t >> 3)));
            }
            #pragma unroll
            for (int fm = 0; fm < 4; fm++)
                #pragma unroll
                for (int fn = 0; fn < 4; fn++)
                    mma16816(acc[fm][fn], af[fm], bf[fn]);
        }
    }

    const int r = lane >> 2, cq = (lane & 3) * 2;
    #pragma unroll
    for (int fm = 0; fm < 4; fm++) {
        #pragma unroll
        for (int fn = 0; fn < 4; fn++) {
            int c = c0 + wm * 64 + fm * 16 + r;
            int n = n0 + wn * 32 + fn * 8 + cq;
            float b0 = g_Beff[64 + c], b1 = g_Beff[64 + c + 8];
            __half2 h0 = __floats2half2_rn(fmaxf(acc[fm][fn][0] + b0, 0.f),
                                           fmaxf(acc[fm][fn][1] + b0, 0.f));
            __half2 h1 = __floats2half2_rn(fmaxf(acc[fm][fn][2] + b1, 0.f),
                                           fmaxf(acc[fm][fn][3] + b1, 0.f));
            *(__half2*)&g_V[((size_t)b * CC + c) * NN + n]     = h0;
            *(__half2*)&g_V[((size_t)b * CC + c + 8) * NN + n] = h1;
        }
    }
}

// ---------------- 4) flash attention with biased Cauchy-Schwarz shift ----------------
// P = exp2(S*L2E - M_i*L2E + 15), M_i = |q_i|*Kmax >= S (q,k >= 0): arg <= 15 so no
// overflow (2^15 < 65504); +15 bias keeps dominant entries out of fp16 underflow.
// Shift cancels in O/l. No online max, no rescale, no shuffles.
// smem: Q 16KB | K 2x16KB | V 3x32KB = 147456 B
__global__ void __launch_bounds__(256, 1) flash_kernel(const float* __restrict__ x,
                                                       const float* __restrict__ gamma,
                                                       float* __restrict__ out)
{
    extern __shared__ __align__(128) unsigned char dsm[];
    const uint32_t sb  = sm_u32(dsm);
    const uint32_t sQ  = sb;
    const uint32_t sK0 = sb + 16384;
    const uint32_t sV0 = sb + 49152;

    const int tid = threadIdx.x, wid = tid >> 5, lane = tid & 31;
    const int i0 = blockIdx.x * 128, c0 = blockIdx.y * 128, b = blockIdx.z;

    const char* qsrc = (const char*)(g_Qt + ((size_t)b * NN + i0) * 64);
    const char* ksrc = (const char*)(g_Kt + (size_t)b * NN * 64);
    const char* vsrc = (const char*)(g_V + ((size_t)b * CC + c0) * NN);

    auto issueK = [&](int it) {
        const uint32_t kb = sK0 + (it & 1) * 16384;
        const char* ks = ksrc + (size_t)it * 128 * 128;
        #pragma unroll
        for (int l = 0; l < 2; l++) {
            int idx = tid + l * 256;
            int row = idx >> 2, ch = idx & 3;
            cpasync16(tile_addr(kb, row, ch), ks + (size_t)row * 128 + ch * 16);
        }
    };
    auto issueV = [&](int it) {
        const uint32_t vb = sV0 + (it % 3) * 32768;
        const size_t jb = (size_t)it * 256;
        #pragma unroll
        for (int l = 0; l < 8; l++) {
            int idx = tid + l * 256;
            int row = idx >> 4, ch = idx & 15;
            cpasync16(tile_addr256(vb, row, ch), vsrc + (size_t)row * (NN * 2) + jb + ch * 16);
        }
    };

    // prologue: Q + stage 0
    #pragma unroll
    for (int l = 0; l < 2; l++) {
        int idx = tid + l * 256;
        int row = idx >> 2, ch = idx & 3;
        cpasync16(tile_addr(sQ, row, ch), qsrc + (size_t)row * 128 + ch * 16);
    }
    issueK(0); issueV(0);
    asm volatile("cp.async.commit_group;" ::: "memory");

    // per-lane row shifts, biased up 15 log2 units
    const float kmax = __uint_as_float(g_Kmax[b]);
    const int rrow = lane >> 2;
    const float mi0 = g_Qn[(size_t)b * NN + i0 + wid * 16 + rrow]     * kmax * L2E - 15.f;
    const float mi1 = g_Qn[(size_t)b * NN + i0 + wid * 16 + rrow + 8] * kmax * L2E - 15.f;

    uint32_t qA[2][4];
    const uint32_t bone[2] = { 0x3C003C00u, 0x3C003C00u };
    float oacc[16][4] = {};
    float lacc[4] = {};
    uint32_t pkp[16][2];

    auto doPV = [&](uint32_t vb) {
        #pragma unroll
        for (int ks = 0; ks < 8; ks++) {
            uint32_t A[4] = { pkp[2 * ks][0], pkp[2 * ks][1], pkp[2 * ks + 1][0], pkp[2 * ks + 1][1] };
            mma16816(lacc, A, bone);
            #pragma unroll
            for (int cp = 0; cp < 8; cp++) {
                uint32_t Bv[4];
                ldsm_x4(Bv, tile_addr256(vb, cp * 16 + (lane & 7) + ((lane >> 4) << 3),
                                         ks * 2 + ((lane >> 3) & 1)));
                mma16816(oacc[2 * cp],     A, Bv);
                mma16816(oacc[2 * cp + 1], A, Bv + 2);
            }
        }
    };

    for (int it = 0; it < 32; it++) {
        asm volatile("cp.async.wait_group 0;" ::: "memory");
        __syncthreads();

        if (it == 0) {
            #pragma unroll
            for (int ck = 0; ck < 2; ck++)
                ldsm_x4(qA[ck], tile_addr(sQ, wid * 16 + (lane & 15), ck * 2 + (lane >> 4)));
        }

        if (it + 1 < 32) {
            issueK(it + 1); issueV(it + 1);
            asm volatile("cp.async.commit_group;" ::: "memory");
        }

        if (it > 0)
            doPV(sV0 + ((it - 1) % 3) * 32768);

        // ---- S = qh.kh ----
        const uint32_t kb = sK0 + (it & 1) * 16384;
        float sacc[16][4];
        #pragma unroll
        for (int n = 0; n < 16; n++) {
            uint32_t Bh[4];
            ldsm_x4(Bh, tile_addr(kb, n * 8 + (lane & 7), (lane >> 3) & 3));
            mma16816z(sacc[n], qA[0], Bh);
            mma16816 (sacc[n], qA[1], Bh + 2);
        }

        // ---- P = exp2(S*L2E - mi) ----
        #pragma unroll
        for (int n = 0; n < 16; n++) {
            uint32_t a0 = packh2(fmaf(sacc[n][0], L2E, -mi0), fmaf(sacc[n][1], L2E, -mi0));
            uint32_t a1 = packh2(fmaf(sacc[n][2], L2E, -mi1), fmaf(sacc[n][3], L2E, -mi1));
            pkp[n][0] = ex2h2(a0);
            pkp[n][1] = ex2h2(a1);
        }
    }

    // drain: PV(31)
    doPV(sV0 + (31 % 3) * 32768);

    // ---- epilogue: out = gamma * O / l + x (guard degenerate rows) ----
    const float g = gamma[0];
    const float il0 = g / fmaxf(lacc[0], 1e-25f);
    const float il1 = g / fmaxf(lacc[2], 1e-25f);
    const int r = lane >> 2, q = lane & 3;
    #pragma unroll
    for (int n = 0; n < 16; n++) {
        #pragma unroll
        for (int e = 0; e < 4; e++) {
            int c = c0 + n * 8 + q * 2 + (e & 1);
            int i = i0 + wid * 16 + r + (e >> 1) * 8;
            size_t off = ((size_t)b * CC + c) * NN + i;
            out[off] = oacc[n][e] * ((e < 2) ? il0 : il1) + x[off];
        }
    }
}

// ---------------- launch ----------------
extern "C" void kernel_launch(void* const* d_in, const int* in_sizes, int n_in,
                              void* d_out, int out_size)
{
    const float* x     = (const float*)d_in[0];
    const float* wq    = (const float*)d_in[1];
    const float* bq    = (const float*)d_in[2];
    const float* gq    = (const float*)d_in[3];
    const float* betaq = (const float*)d_in[4];
    const float* mq    = (const float*)d_in[5];
    const float* vq    = (const float*)d_in[6];
    const float* wk    = (const float*)d_in[7];
    const float* bk    = (const float*)d_in[8];
    const float* gk    = (const float*)d_in[9];
    const float* betak = (const float*)d_in[10];
    const float* mk    = (const float*)d_in[11];
    const float* vk    = (const float*)d_in[12];
    const float* wv    = (const float*)d_in[13];
    const float* bv    = (const float*)d_in[14];
    const float* gv    = (const float*)d_in[15];
    const float* betav = (const float*)d_in[16];
    const float* mv    = (const float*)d_in[17];
    const float* vv    = (const float*)d_in[18];
    const float* gamma = (const float*)d_in[19];
    float* out = (float*)d_out;

    cudaFuncSetAttribute(flash_kernel, cudaFuncAttributeMaxDynamicSharedMemorySize, 147456);

    fold_kernel<<<320, 256>>>(wq, bq, gq, betaq, mq, vq,
                              wk, bk, gk, betak, mk, vk,
                              wv, bv, gv, betav, mv, vv);

    qkconv_kernel<<<dim3(NN / 64, BB), 256>>>(x);

    vconv_kernel<<<dim3(NN / 128, CC / 128, BB), 256>>>();

    flash_kernel<<<dim3(NN / 128, 2, BB), 256, 147456>>>(x, gamma, out);
}